// round 2
// baseline (speedup 1.0000x reference)
#include <cuda_runtime.h>
#include <cuda_bf16.h>
#include <math.h>

// Problem constants
#define BATCH 1024
#define TT    169
#define FDYN  36
#define FSTAT 19
#define HID   128
#define MTOT  (BATCH * TT)      // 173056, divisible by 64

// ---------------------------------------------------------------------------
// Scratch (device globals; allocation-free per harness rules)
// ---------------------------------------------------------------------------
__device__ float g_xpre[(size_t)MTOT * 1024];   // [B,T,1024]: cols 0:512 fw gates, 512:1024 bw gates (reused by both layers)
__device__ float g_cur0[(size_t)MTOT * 256];    // layer0 output concat(fw,bw)
__device__ float g_cur1[(size_t)MTOT * 256];    // layer1 output
__device__ float g_sbuf[BATCH * 16];            // static branch
__device__ float g_attb[BATCH * 256];           // attention pooled

// ---------------------------------------------------------------------------
// Static branch: s = relu(relu(x_static@w_s0+b0)@w_s1+b1)   [B,16]
// ---------------------------------------------------------------------------
__global__ __launch_bounds__(256) void static_kernel(
    const float* __restrict__ x, const float* __restrict__ w0, const float* __restrict__ b0,
    const float* __restrict__ w1, const float* __restrict__ b1, float* __restrict__ s_out)
{
    int b = blockIdx.x * blockDim.x + threadIdx.x;
    if (b >= BATCH) return;
    float xin[FSTAT];
#pragma unroll
    for (int i = 0; i < FSTAT; ++i) xin[i] = x[b * FSTAT + i];
    float h0[16];
#pragma unroll
    for (int j = 0; j < 16; ++j) {
        float a = b0[j];
#pragma unroll
        for (int i = 0; i < FSTAT; ++i) a += xin[i] * w0[i * 16 + j];
        h0[j] = fmaxf(a, 0.f);
    }
#pragma unroll
    for (int j = 0; j < 16; ++j) {
        float a = b1[j];
#pragma unroll
        for (int i = 0; i < 16; ++i) a += h0[i] * w1[i * 16 + j];
        s_out[b * 16 + j] = fmaxf(a, 0.f);
    }
}

// ---------------------------------------------------------------------------
// Input-projection GEMM: Y[M,1024] = A[M,K] @ [Wf | Wb] + [bf | bb]
// Tiles fully past seq_len are skipped (their outputs are never read).
// ---------------------------------------------------------------------------
#define GM_BK 16
__global__ __launch_bounds__(256) void xpre_gemm(
    const float* __restrict__ A, int lda, int K,
    const float* __restrict__ Wf, const float* __restrict__ Wb,
    const float* __restrict__ bf, const float* __restrict__ bb,
    const int* __restrict__ seq_len,
    float* __restrict__ Y)
{
    __shared__ float A_sm[64][17];
    __shared__ float W_sm[GM_BK][64];

    const int m0 = blockIdx.x * 64;
    const int n0 = blockIdx.y * 64;
    const int tid = threadIdx.x;

    // row-activity check (skip fully-padded tiles)
    int myact = 0;
    if (tid < 64) {
        int m = m0 + tid;
        int bb_i = m / TT;
        int t = m - bb_i * TT;
        myact = (t < seq_len[bb_i]) ? 1 : 0;
    }
    if (!__syncthreads_or(myact)) return;

    const int tx = tid & 15;         // col micro-tile
    const int ty = tid >> 4;         // row micro-tile
    float acc[4][4];
#pragma unroll
    for (int i = 0; i < 4; ++i)
#pragma unroll
        for (int j = 0; j < 4; ++j) acc[i][j] = 0.f;

    for (int k0 = 0; k0 < K; k0 += GM_BK) {
#pragma unroll
        for (int j = 0; j < 4; ++j) {
            int idx = tid + j * 256;
            int mm = idx >> 4, kk = idx & 15;
            int k = k0 + kk;
            A_sm[mm][kk] = (k < K) ? A[(size_t)(m0 + mm) * lda + k] : 0.f;
        }
#pragma unroll
        for (int j = 0; j < 4; ++j) {
            int idx = tid + j * 256;
            int nn = idx & 63, kk = idx >> 6;
            int k = k0 + kk;
            int n = n0 + nn;
            float v = 0.f;
            if (k < K) v = (n < 512) ? Wf[(size_t)k * 512 + n] : Wb[(size_t)k * 512 + (n - 512)];
            W_sm[kk][nn] = v;
        }
        __syncthreads();
#pragma unroll
        for (int kk = 0; kk < GM_BK; ++kk) {
            float4 w = *(const float4*)&W_sm[kk][tx * 4];
#pragma unroll
            for (int i = 0; i < 4; ++i) {
                float a = A_sm[ty * 4 + i][kk];
                acc[i][0] += a * w.x; acc[i][1] += a * w.y;
                acc[i][2] += a * w.z; acc[i][3] += a * w.w;
            }
        }
        __syncthreads();
    }

    const int n = n0 + tx * 4;
    float4 bias = (n < 512) ? *(const float4*)&bf[n] : *(const float4*)&bb[n - 512];
#pragma unroll
    for (int i = 0; i < 4; ++i) {
        int m = m0 + ty * 4 + i;
        float4 v = make_float4(acc[i][0] + bias.x, acc[i][1] + bias.y,
                               acc[i][2] + bias.z, acc[i][3] + bias.w);
        *(float4*)&Y[(size_t)m * 1024 + n] = v;
    }
}

// ---------------------------------------------------------------------------
// Persistent recurrent kernel. 128 blocks: blocks 0..63 forward, 64..127 backward.
// Each block owns 16 batch rows through all 169 steps.
// Phase1: gates = h @ Wh (256 threads, 4 rows x 8 cols each) -> smem
// Phase2: += Xpre, activations, c/h update, masked write (fw at t; bw at L-1-t)
// ---------------------------------------------------------------------------
__global__ __launch_bounds__(256) void rec_kernel(
    const float* __restrict__ xpre,
    const float* __restrict__ Wh_f, const float* __restrict__ Wh_b,
    const int* __restrict__ seq_len,
    float* __restrict__ outp)
{
    const int blk  = blockIdx.x;
    const int dir  = blk >> 6;             // 0 = fw, 1 = bw
    const int b0   = (blk & 63) * 16;
    const float* __restrict__ Wh = dir ? Wh_b : Wh_f;
    const int xoff = dir * 512;
    const int ooff = dir * 128;

    __shared__ float h_sm[16][128];
    __shared__ float g_sm[16][512];
    __shared__ int   L_sm[17];

    const int tid = threadIdx.x;
    if (tid < 16) L_sm[tid] = seq_len[b0 + tid];
    for (int i = tid; i < 16 * 128; i += 256) (&h_sm[0][0])[i] = 0.f;
    __syncthreads();
    if (tid == 0) {
        int m = 0;
#pragma unroll
        for (int i = 0; i < 16; ++i) m = max(m, L_sm[i]);
        L_sm[16] = m;
    }
    __syncthreads();
    const int Lmax = L_sm[16];

    // phase1 mapping
    const int c0 = (tid & 63) * 8;
    const int r0 = (tid >> 6) * 4;
    // phase2 mapping (thread owns 8 cells of (row r2, hidden h2..h2+7))
    const int r2 = tid >> 4;
    const int h2 = (tid & 15) * 8;
    const int L  = L_sm[r2];
    const size_t bR = (size_t)(b0 + r2);

    float c_reg[8];
#pragma unroll
    for (int u = 0; u < 8; ++u) c_reg[u] = 0.f;

    for (int step = 0; step < TT; ++step) {
        if (step < Lmax) {
            float acc[4][8];
#pragma unroll
            for (int r = 0; r < 4; ++r)
#pragma unroll
                for (int u = 0; u < 8; ++u) acc[r][u] = 0.f;

#pragma unroll 4
            for (int k = 0; k < HID; ++k) {
                const float4 w0 = *(const float4*)(Wh + (size_t)k * 512 + c0);
                const float4 w1 = *(const float4*)(Wh + (size_t)k * 512 + c0 + 4);
#pragma unroll
                for (int r = 0; r < 4; ++r) {
                    float hv = h_sm[r0 + r][k];
                    acc[r][0] += hv * w0.x; acc[r][1] += hv * w0.y;
                    acc[r][2] += hv * w0.z; acc[r][3] += hv * w0.w;
                    acc[r][4] += hv * w1.x; acc[r][5] += hv * w1.y;
                    acc[r][6] += hv * w1.z; acc[r][7] += hv * w1.w;
                }
            }
#pragma unroll
            for (int r = 0; r < 4; ++r) {
                *(float4*)&g_sm[r0 + r][c0]     = make_float4(acc[r][0], acc[r][1], acc[r][2], acc[r][3]);
                *(float4*)&g_sm[r0 + r][c0 + 4] = make_float4(acc[r][4], acc[r][5], acc[r][6], acc[r][7]);
            }
        }
        __syncthreads();

        const bool active = (step < L);
        float hv[8];
        int pos;
        if (active) {
            int in_idx = dir ? (L - 1 - step) : step;
            pos = in_idx;
            const float* xp = xpre + (bR * TT + in_idx) * 1024 + xoff + h2;
#pragma unroll
            for (int u = 0; u < 8; ++u) {
                float gi = xp[u]         + g_sm[r2][h2 + u];
                float gj = xp[128 + u]   + g_sm[r2][128 + h2 + u];
                float gf = xp[256 + u]   + g_sm[r2][256 + h2 + u];
                float go = xp[384 + u]   + g_sm[r2][384 + h2 + u];
                float ig = 1.f / (1.f + expf(-gi));
                float fg = 1.f / (1.f + expf(-(gf + 1.f)));   // forget_bias = 1.0
                float og = 1.f / (1.f + expf(-go));
                float jg = tanhf(gj);
                float cn = c_reg[u] * fg + ig * jg;
                c_reg[u] = cn;
                hv[u] = tanhf(cn) * og;
            }
        } else {
            pos = step;  // fw: zeros at t>=L; bw: steps [L,T) zero-fill positions [L,T)
#pragma unroll
            for (int u = 0; u < 8; ++u) hv[u] = 0.f;
        }
        float* op = outp + (bR * TT + pos) * 256 + ooff + h2;
#pragma unroll
        for (int u = 0; u < 8; ++u) op[u] = hv[u];
        if (active) {
#pragma unroll
            for (int u = 0; u < 8; ++u) h_sm[r2][h2 + u] = hv[u];
        }
        __syncthreads();
    }
}

// ---------------------------------------------------------------------------
// Attention pooling: score = softmax_t(tanh(cur@w_att+b_att)); att = sum score*cur
// One block per batch row.
// ---------------------------------------------------------------------------
__global__ __launch_bounds__(256) void att_kernel(
    const float* __restrict__ cur, const float* __restrict__ w_att,
    const float* __restrict__ b_att, float* __restrict__ att_out)
{
    const int b = blockIdx.x, tid = threadIdx.x;
    __shared__ float wv[256];
    __shared__ float e_sm[176];
    __shared__ float red[40];
    wv[tid] = w_att[tid];
    __syncthreads();

    const int warp = tid >> 5, lane = tid & 31;
    for (int t = warp; t < TT; t += 8) {
        const float* p = cur + ((size_t)b * TT + t) * 256;
        float s = 0.f;
#pragma unroll
        for (int j = 0; j < 8; ++j) s += p[lane + 32 * j] * wv[lane + 32 * j];
#pragma unroll
        for (int off = 16; off > 0; off >>= 1) s += __shfl_down_sync(0xffffffffu, s, off);
        if (lane == 0) e_sm[t] = tanhf(s + b_att[0]);
    }
    __syncthreads();

    float m = -1e30f;
    for (int t = tid; t < TT; t += 256) m = fmaxf(m, e_sm[t]);
#pragma unroll
    for (int off = 16; off > 0; off >>= 1) m = fmaxf(m, __shfl_xor_sync(0xffffffffu, m, off));
    if (lane == 0) red[warp] = m;
    __syncthreads();
    if (tid == 0) {
        float mm = red[0];
        for (int w = 1; w < 8; ++w) mm = fmaxf(mm, red[w]);
        red[32] = mm;
    }
    __syncthreads();
    const float mx = red[32];

    float ssum = 0.f;
    for (int t = tid; t < TT; t += 256) { float p = expf(e_sm[t] - mx); e_sm[t] = p; ssum += p; }
#pragma unroll
    for (int off = 16; off > 0; off >>= 1) ssum += __shfl_xor_sync(0xffffffffu, ssum, off);
    if (lane == 0) red[warp] = ssum;
    __syncthreads();
    if (tid == 0) {
        float s2 = 0.f;
        for (int w = 0; w < 8; ++w) s2 += red[w];
        red[33] = s2;
    }
    __syncthreads();
    const float inv = 1.f / red[33];

    float acc0 = 0.f, acc1 = 0.f;
    const float* base = cur + (size_t)b * TT * 256 + tid;
    for (int t = 0; t < TT - 1; t += 2) {
        acc0 += e_sm[t]     * base[(size_t)t * 256];
        acc1 += e_sm[t + 1] * base[(size_t)(t + 1) * 256];
    }
    acc0 += e_sm[TT - 1] * base[(size_t)(TT - 1) * 256];
    att_out[b * 256 + tid] = (acc0 + acc1) * inv;
}

// ---------------------------------------------------------------------------
// Classifier head: out = relu(relu([s, att]@w_c1+b_c1)@w_c2+b_c2)   [B,32]
// ---------------------------------------------------------------------------
__global__ __launch_bounds__(64) void head_kernel(
    const float* __restrict__ s, const float* __restrict__ att,
    const float* __restrict__ w1, const float* __restrict__ b1,
    const float* __restrict__ w2, const float* __restrict__ b2,
    float* __restrict__ out)
{
    const int b = blockIdx.x, tid = threadIdx.x;
    __shared__ float cat[272];
    __shared__ float h1[64];
    if (tid < 16) cat[tid] = s[b * 16 + tid];
    for (int j = tid; j < 256; j += 64) cat[16 + j] = att[b * 256 + j];
    __syncthreads();
    float a = b1[tid];
#pragma unroll 4
    for (int k = 0; k < 272; ++k) a += cat[k] * w1[k * 64 + tid];
    h1[tid] = fmaxf(a, 0.f);
    __syncthreads();
    if (tid < 32) {
        float a2 = b2[tid];
#pragma unroll
        for (int k = 0; k < 64; ++k) a2 += h1[k] * w2[k * 32 + tid];
        out[b * 32 + tid] = fmaxf(a2, 0.f);
    }
}

// ---------------------------------------------------------------------------
// Launch
// ---------------------------------------------------------------------------
extern "C" void kernel_launch(void* const* d_in, const int* in_sizes, int n_in,
                              void* d_out, int out_size)
{
    const float* x_static = (const float*)d_in[0];
    const float* x_dyn    = (const float*)d_in[1];
    const int*   seq      = (const int*)  d_in[2];
    const float* w_s0 = (const float*)d_in[3];
    const float* b_s0 = (const float*)d_in[4];
    const float* w_s1 = (const float*)d_in[5];
    const float* b_s1 = (const float*)d_in[6];
    const float* Wx_f0 = (const float*)d_in[7];
    const float* Wh_f0 = (const float*)d_in[8];
    const float* bb_f0 = (const float*)d_in[9];
    const float* Wx_b0 = (const float*)d_in[10];
    const float* Wh_b0 = (const float*)d_in[11];
    const float* bb_b0 = (const float*)d_in[12];
    const float* Wx_f1 = (const float*)d_in[13];
    const float* Wh_f1 = (const float*)d_in[14];
    const float* bb_f1 = (const float*)d_in[15];
    const float* Wx_b1 = (const float*)d_in[16];
    const float* Wh_b1 = (const float*)d_in[17];
    const float* bb_b1 = (const float*)d_in[18];
    const float* w_att = (const float*)d_in[19];
    const float* b_att = (const float*)d_in[20];
    const float* w_c1  = (const float*)d_in[21];
    const float* b_c1  = (const float*)d_in[22];
    const float* w_c2  = (const float*)d_in[23];
    const float* b_c2  = (const float*)d_in[24];
    float* out = (float*)d_out;

    float *xpre, *cur0, *cur1, *sbuf, *attb;
    cudaGetSymbolAddress((void**)&xpre, g_xpre);
    cudaGetSymbolAddress((void**)&cur0, g_cur0);
    cudaGetSymbolAddress((void**)&cur1, g_cur1);
    cudaGetSymbolAddress((void**)&sbuf, g_sbuf);
    cudaGetSymbolAddress((void**)&attb, g_attb);

    static_kernel<<<(BATCH + 255) / 256, 256>>>(x_static, w_s0, b_s0, w_s1, b_s1, sbuf);

    dim3 ggrid(MTOT / 64, 16);
    // layer 0
    xpre_gemm<<<ggrid, 256>>>(x_dyn, FDYN, FDYN, Wx_f0, Wx_b0, bb_f0, bb_b0, seq, xpre);
    rec_kernel<<<128, 256>>>(xpre, Wh_f0, Wh_b0, seq, cur0);
    // layer 1
    xpre_gemm<<<ggrid, 256>>>(cur0, 256, 256, Wx_f1, Wx_b1, bb_f1, bb_b1, seq, xpre);
    rec_kernel<<<128, 256>>>(xpre, Wh_f1, Wh_b1, seq, cur1);
    // pooling + head
    att_kernel<<<BATCH, 256>>>(cur1, w_att, b_att, attb);
    head_kernel<<<BATCH, 64>>>(sbuf, attb, w_c1, b_c1, w_c2, b_c2, out);
}

// round 5
// speedup vs baseline: 4.9757x; 4.9757x over previous
#include <cuda_runtime.h>
#include <cuda_fp16.h>
#include <cstdint>
#include <math.h>

// Problem constants
#define BATCH 1024
#define TT    169
#define FDYN  36
#define FSTAT 19
#define HID   128
#define MTOT  (BATCH * TT)

// ---------------------------------------------------------------------------
// Scratch (device globals; allocation-free per harness rules).
// Kernels reference these directly — no host-side symbol lookups needed.
// ---------------------------------------------------------------------------
__device__ __half g_xpre16[(size_t)MTOT * 1024];  // [B,T,1024] fp16 gate preacts (both layers reuse)
__device__ __half g_cur0h[(size_t)MTOT * 256];    // layer0 output concat(fw,bw), fp16
__device__ float  g_cur1[(size_t)MTOT * 256];     // layer1 output fp32 (attention input)
__device__ float  g_sbuf[BATCH * 16];
__device__ float  g_attb[BATCH * 256];
__device__ __half g_wh16[4 * 128 * 512];          // fp16 Wh: order f0, b0, f1, b1
__device__ __half g_wx0[36 * 1024];               // concat [Wx_f0 | Wx_b0]
__device__ __half g_wx1[256 * 1024];              // concat [Wx_f1 | Wx_b1]
__device__ float  g_bx0[1024];
__device__ float  g_bx1[1024];

// ---------------------------------------------------------------------------
// MMA / ldmatrix helpers
// ---------------------------------------------------------------------------
__device__ __forceinline__ unsigned smem_u32(const void* p) {
    return (unsigned)__cvta_generic_to_shared(p);
}
__device__ __forceinline__ void ldsm_x4(unsigned& r0, unsigned& r1, unsigned& r2, unsigned& r3, unsigned a) {
    asm volatile("ldmatrix.sync.aligned.m8n8.x4.shared.b16 {%0,%1,%2,%3}, [%4];"
                 : "=r"(r0), "=r"(r1), "=r"(r2), "=r"(r3) : "r"(a));
}
__device__ __forceinline__ void ldsm_x4_t(unsigned& r0, unsigned& r1, unsigned& r2, unsigned& r3, unsigned a) {
    asm volatile("ldmatrix.sync.aligned.m8n8.x4.trans.shared.b16 {%0,%1,%2,%3}, [%4];"
                 : "=r"(r0), "=r"(r1), "=r"(r2), "=r"(r3) : "r"(a));
}
__device__ __forceinline__ void mma16816(float* c, unsigned a0, unsigned a1, unsigned a2, unsigned a3,
                                         unsigned b0, unsigned b1) {
    asm volatile("mma.sync.aligned.m16n8k16.row.col.f32.f16.f16.f32 "
                 "{%0,%1,%2,%3}, {%4,%5,%6,%7}, {%8,%9}, {%0,%1,%2,%3};"
                 : "+f"(c[0]), "+f"(c[1]), "+f"(c[2]), "+f"(c[3])
                 : "r"(a0), "r"(a1), "r"(a2), "r"(a3), "r"(b0), "r"(b1));
}

// ---------------------------------------------------------------------------
// Weight conversion to fp16 (once per launch)
// ---------------------------------------------------------------------------
__global__ __launch_bounds__(256) void prep_kernel(
    const float* __restrict__ Wh_f0, const float* __restrict__ Wh_b0,
    const float* __restrict__ Wh_f1, const float* __restrict__ Wh_b1,
    const float* __restrict__ Wx_f0, const float* __restrict__ Wx_b0,
    const float* __restrict__ Wx_f1, const float* __restrict__ Wx_b1,
    const float* __restrict__ bb_f0, const float* __restrict__ bb_b0,
    const float* __restrict__ bb_f1, const float* __restrict__ bb_b1)
{
    const int N_WH = 4 * 65536;
    const int N_W0 = 36 * 1024;
    const int N_W1 = 256 * 1024;
    const int N_ALL = N_WH + N_W0 + N_W1 + 2048;
    for (int idx = blockIdx.x * 256 + threadIdx.x; idx < N_ALL; idx += gridDim.x * 256) {
        if (idx < N_WH) {
            int which = idx >> 16;
            int off = idx & 65535;
            const float* src = (which == 0) ? Wh_f0 : (which == 1) ? Wh_b0 : (which == 2) ? Wh_f1 : Wh_b1;
            g_wh16[idx] = __float2half(src[off]);
        } else if (idx < N_WH + N_W0) {
            int j = idx - N_WH;
            int k = j >> 10;
            int n = j & 1023;
            float v = (n < 512) ? Wx_f0[k * 512 + n] : Wx_b0[k * 512 + (n - 512)];
            g_wx0[j] = __float2half(v);
        } else if (idx < N_WH + N_W0 + N_W1) {
            int j = idx - N_WH - N_W0;
            int k = j >> 10;
            int n = j & 1023;
            float v = (n < 512) ? Wx_f1[k * 512 + n] : Wx_b1[k * 512 + (n - 512)];
            g_wx1[j] = __float2half(v);
        } else {
            int j = idx - N_WH - N_W0 - N_W1;
            int n = j & 1023;
            if (j < 1024) { g_bx0[n] = (n < 512) ? bb_f0[n] : bb_b0[n - 512]; }
            else          { g_bx1[n] = (n < 512) ? bb_f1[n] : bb_b1[n - 512]; }
        }
    }
}

// ---------------------------------------------------------------------------
// Static branch -> g_sbuf
// ---------------------------------------------------------------------------
__global__ __launch_bounds__(256) void static_kernel(
    const float* __restrict__ x, const float* __restrict__ w0, const float* __restrict__ b0,
    const float* __restrict__ w1, const float* __restrict__ b1)
{
    int b = blockIdx.x * blockDim.x + threadIdx.x;
    if (b >= BATCH) return;
    float xin[FSTAT];
#pragma unroll
    for (int i = 0; i < FSTAT; ++i) xin[i] = x[b * FSTAT + i];
    float h0[16];
#pragma unroll
    for (int j = 0; j < 16; ++j) {
        float a = b0[j];
#pragma unroll
        for (int i = 0; i < FSTAT; ++i) a += xin[i] * w0[i * 16 + j];
        h0[j] = fmaxf(a, 0.f);
    }
#pragma unroll
    for (int j = 0; j < 16; ++j) {
        float a = b1[j];
#pragma unroll
        for (int i = 0; i < 16; ++i) a += h0[i] * w1[i * 16 + j];
        g_sbuf[b * 16 + j] = fmaxf(a, 0.f);
    }
}

// ---------------------------------------------------------------------------
// Input-projection GEMM via mma -> g_xpre16.
// layer==0: A = x_dyn (float, K=36). layer==1: A = g_cur0h (half, K=256).
// BM=64, BN=128, BK=32. 8 warps: wy(0..3) x 16 rows, wx(0..1) x 64 cols.
// ---------------------------------------------------------------------------
__global__ __launch_bounds__(256) void xpre_gemm_mma(
    const float* __restrict__ Afloat, int K, int layer,
    const int* __restrict__ seq_len)
{
    __shared__ __half A_sm[64 * 40];
    __shared__ __half B_sm[32 * 136];

    const int m0 = blockIdx.x * 64;
    const int nb = blockIdx.y * 128;
    const int tid = threadIdx.x;

    int act = 0;
    if (tid < 64) {
        int m = m0 + tid;
        int bi = m / TT;
        int t = m - bi * TT;
        act = (t < seq_len[bi]) ? 1 : 0;
    }
    if (!__syncthreads_or(act)) return;

    const __half* Bw = (layer == 0) ? g_wx0 : g_wx1;
    const float* bias = (layer == 0) ? g_bx0 : g_bx1;

    const int warp = tid >> 5;
    const int lane = tid & 31;
    const int wy = warp >> 1;
    const int wx = warp & 1;

    float c[8][4];
#pragma unroll
    for (int i = 0; i < 8; ++i) {
#pragma unroll
        for (int j = 0; j < 4; ++j) c[i][j] = 0.f;
    }

    for (int k0 = 0; k0 < K; k0 += 32) {
#pragma unroll
        for (int j = 0; j < 8; ++j) {
            int i = tid + j * 256;
            int row = i >> 5;
            int col = i & 31;
            int k = k0 + col;
            __half hv = __float2half(0.f);
            if (k < K) {
                if (layer == 0) hv = __float2half(Afloat[(size_t)(m0 + row) * K + k]);
                else            hv = g_cur0h[(size_t)(m0 + row) * 256 + k];
            }
            A_sm[row * 40 + col] = hv;
        }
#pragma unroll
        for (int j = 0; j < 2; ++j) {
            int i = tid + j * 256;
            int row = i >> 4;
            int c8 = i & 15;
            int k = k0 + row;
            uint4 v = make_uint4(0u, 0u, 0u, 0u);
            if (k < K) v = *(const uint4*)&Bw[(size_t)k * 1024 + nb + c8 * 8];
            *(uint4*)&B_sm[row * 136 + c8 * 8] = v;
        }
        __syncthreads();

#pragma unroll
        for (int kk = 0; kk < 2; ++kk) {
            unsigned a0, a1, a2, a3;
            unsigned aaddr = smem_u32(&A_sm[(wy * 16 + (lane & 15)) * 40 + kk * 16 + (lane >> 4) * 8]);
            ldsm_x4(a0, a1, a2, a3, aaddr);
#pragma unroll
            for (int np = 0; np < 4; ++np) {
                unsigned q0, q1, q2, q3;
                unsigned baddr = smem_u32(&B_sm[(kk * 16 + (lane & 15)) * 136 + wx * 64 + np * 16 + (lane >> 4) * 8]);
                ldsm_x4_t(q0, q1, q2, q3, baddr);
                mma16816(c[np * 2],     a0, a1, a2, a3, q0, q1);
                mma16816(c[np * 2 + 1], a0, a1, a2, a3, q2, q3);
            }
        }
        __syncthreads();
    }

    const int r = lane >> 2;
    const int cb = (lane & 3) * 2;
#pragma unroll
    for (int nt = 0; nt < 8; ++nt) {
        int gn = nb + wx * 64 + nt * 8 + cb;
        float bx = bias[gn];
        float by = bias[gn + 1];
        int m1 = m0 + wy * 16 + r;
        int m2 = m1 + 8;
        __half2 lo = __floats2half2_rn(c[nt][0] + bx, c[nt][1] + by);
        __half2 hi = __floats2half2_rn(c[nt][2] + bx, c[nt][3] + by);
        *(__half2*)&g_xpre16[(size_t)m1 * 1024 + gn] = lo;
        *(__half2*)&g_xpre16[(size_t)m2 * 1024 + gn] = hi;
    }
}

// ---------------------------------------------------------------------------
// Persistent recurrent kernel, SMEM-resident fp16 Wh, mma phase1.
// 128 blocks: 0..63 fw, 64..127 bw; 16 batch rows/block; 169 steps.
// Dyn smem: WH[128][520] h | HS[16][136] h | GS[16][516] f | LS[17] i
// ---------------------------------------------------------------------------
#define WH_STRIDE 520
#define HS_STRIDE 136
#define GS_STRIDE 516
#define SM_HS_OFF 133120
#define SM_GS_OFF 137472
#define SM_LS_OFF 170496
#define REC_SMEM  170624

__global__ __launch_bounds__(256) void rec_mma(const int* __restrict__ seq_len, int layer)
{
    extern __shared__ char smraw[];
    __half* WH = (__half*)(smraw);
    __half* HS = (__half*)(smraw + SM_HS_OFF);
    float*  GS = (float*)(smraw + SM_GS_OFF);
    int*    LS = (int*)(smraw + SM_LS_OFF);

    const int blk = blockIdx.x;
    const int dir = blk >> 6;
    const int b0 = (blk & 63) * 16;
    const int xoff = dir * 512;
    const int ooff = dir * 128;
    const int tid = threadIdx.x;

    const __half* wg = g_wh16 + (size_t)(layer * 2 + dir) * 65536;
#pragma unroll 8
    for (int i = tid; i < 8192; i += 256) {
        int r = i >> 6;
        int c8 = i & 63;
        *(uint4*)&WH[r * WH_STRIDE + c8 * 8] = ((const uint4*)wg)[i];
    }
    for (int i = tid; i < (16 * HS_STRIDE) / 2; i += 256) ((unsigned*)HS)[i] = 0u;
    if (tid < 16) LS[tid] = seq_len[b0 + tid];
    __syncthreads();
    if (tid == 0) {
        int m = 0;
#pragma unroll
        for (int i = 0; i < 16; ++i) m = max(m, LS[i]);
        LS[16] = m;
    }
    __syncthreads();
    const int Lmax = LS[16];

    const int warp = tid >> 5;
    const int lane = tid & 31;
    const int n_base = warp * 64;
    const int r2 = tid >> 4;
    const int h2 = (tid & 15) * 8;
    const int L = LS[r2];
    const size_t bR = (size_t)(b0 + r2);

    float c_reg[8];
#pragma unroll
    for (int u = 0; u < 8; ++u) c_reg[u] = 0.f;

    const int arow = lane & 15;
    const int acol8 = (lane >> 4) * 8;

    for (int step = 0; step < TT; ++step) {
        if (step < Lmax) {
            float c[8][4];
#pragma unroll
            for (int i = 0; i < 8; ++i) {
#pragma unroll
                for (int j = 0; j < 4; ++j) c[i][j] = 0.f;
            }
#pragma unroll
            for (int kk = 0; kk < 8; ++kk) {
                unsigned a0, a1, a2, a3;
                unsigned aaddr = smem_u32(&HS[arow * HS_STRIDE + kk * 16 + acol8]);
                ldsm_x4(a0, a1, a2, a3, aaddr);
#pragma unroll
                for (int np = 0; np < 4; ++np) {
                    unsigned q0, q1, q2, q3;
                    unsigned baddr = smem_u32(&WH[(kk * 16 + arow) * WH_STRIDE + n_base + np * 16 + acol8]);
                    ldsm_x4_t(q0, q1, q2, q3, baddr);
                    mma16816(c[np * 2],     a0, a1, a2, a3, q0, q1);
                    mma16816(c[np * 2 + 1], a0, a1, a2, a3, q2, q3);
                }
            }
            const int rr = lane >> 2;
            const int cbase = (lane & 3) * 2;
#pragma unroll
            for (int nt = 0; nt < 8; ++nt) {
                int n = n_base + nt * 8 + cbase;
                *(float2*)&GS[rr * GS_STRIDE + n]       = make_float2(c[nt][0], c[nt][1]);
                *(float2*)&GS[(rr + 8) * GS_STRIDE + n] = make_float2(c[nt][2], c[nt][3]);
            }
        }
        __syncthreads();

        const bool active = (step < L);
        float hv[8];
        int pos;
        if (active) {
            int in_idx = dir ? (L - 1 - step) : step;
            pos = in_idx;
            const __half* xp = g_xpre16 + (bR * TT + in_idx) * 1024 + xoff + h2;
            uint4 vi = *(const uint4*)(xp);
            uint4 vj = *(const uint4*)(xp + 128);
            uint4 vf = *(const uint4*)(xp + 256);
            uint4 vo = *(const uint4*)(xp + 384);
            const __half* pi = (const __half*)&vi;
            const __half* pj = (const __half*)&vj;
            const __half* pf = (const __half*)&vf;
            const __half* po = (const __half*)&vo;
            const float* gsr = &GS[r2 * GS_STRIDE];
#pragma unroll
            for (int u = 0; u < 8; ++u) {
                float gi = __half2float(pi[u]) + gsr[h2 + u];
                float gj = __half2float(pj[u]) + gsr[128 + h2 + u];
                float gf = __half2float(pf[u]) + gsr[256 + h2 + u];
                float go = __half2float(po[u]) + gsr[384 + h2 + u];
                float ig = 1.f / (1.f + expf(-gi));
                float fg = 1.f / (1.f + expf(-(gf + 1.f)));
                float og = 1.f / (1.f + expf(-go));
                float jg = tanhf(gj);
                float cn = c_reg[u] * fg + ig * jg;
                c_reg[u] = cn;
                hv[u] = tanhf(cn) * og;
            }
        } else {
            pos = step;
#pragma unroll
            for (int u = 0; u < 8; ++u) hv[u] = 0.f;
        }

        if (layer == 0) {
            __half hb[8];
#pragma unroll
            for (int u = 0; u < 8; ++u) hb[u] = __float2half(hv[u]);
            *(uint4*)&g_cur0h[(bR * TT + pos) * 256 + ooff + h2] = *(uint4*)hb;
        } else {
            float* op = &g_cur1[(bR * TT + pos) * 256 + ooff + h2];
            *(float4*)(op)     = make_float4(hv[0], hv[1], hv[2], hv[3]);
            *(float4*)(op + 4) = make_float4(hv[4], hv[5], hv[6], hv[7]);
        }
        if (active) {
            __half hb2[8];
#pragma unroll
            for (int u = 0; u < 8; ++u) hb2[u] = __float2half(hv[u]);
            *(uint4*)&HS[r2 * HS_STRIDE + h2] = *(uint4*)hb2;
        }
        __syncthreads();
    }
}

// ---------------------------------------------------------------------------
// Attention pooling: g_cur1 -> g_attb
// ---------------------------------------------------------------------------
__global__ __launch_bounds__(256) void att_kernel(
    const float* __restrict__ w_att, const float* __restrict__ b_att)
{
    const int b = blockIdx.x;
    const int tid = threadIdx.x;
    __shared__ float wv[256];
    __shared__ float e_sm[176];
    __shared__ float red[40];
    wv[tid] = w_att[tid];
    __syncthreads();

    const int warp = tid >> 5;
    const int lane = tid & 31;
    for (int t = warp; t < TT; t += 8) {
        const float* p = &g_cur1[((size_t)b * TT + t) * 256];
        float s = 0.f;
#pragma unroll
        for (int j = 0; j < 8; ++j) s += p[lane + 32 * j] * wv[lane + 32 * j];
#pragma unroll
        for (int off = 16; off > 0; off >>= 1) s += __shfl_down_sync(0xffffffffu, s, off);
        if (lane == 0) e_sm[t] = tanhf(s + b_att[0]);
    }
    __syncthreads();

    float m = -1e30f;
    for (int t = tid; t < TT; t += 256) m = fmaxf(m, e_sm[t]);
#pragma unroll
    for (int off = 16; off > 0; off >>= 1) m = fmaxf(m, __shfl_xor_sync(0xffffffffu, m, off));
    if (lane == 0) red[warp] = m;
    __syncthreads();
    if (tid == 0) {
        float mm = red[0];
        for (int w = 1; w < 8; ++w) mm = fmaxf(mm, red[w]);
        red[32] = mm;
    }
    __syncthreads();
    const float mx = red[32];

    float ssum = 0.f;
    for (int t = tid; t < TT; t += 256) {
        float p = expf(e_sm[t] - mx);
        e_sm[t] = p;
        ssum += p;
    }
#pragma unroll
    for (int off = 16; off > 0; off >>= 1) ssum += __shfl_xor_sync(0xffffffffu, ssum, off);
    if (lane == 0) red[warp] = ssum;
    __syncthreads();
    if (tid == 0) {
        float s2 = 0.f;
        for (int w = 0; w < 8; ++w) s2 += red[w];
        red[33] = s2;
    }
    __syncthreads();
    const float inv = 1.f / red[33];

    float acc0 = 0.f, acc1 = 0.f;
    const float* base = &g_cur1[(size_t)b * TT * 256 + tid];
    for (int t = 0; t < TT - 1; t += 2) {
        acc0 += e_sm[t]     * base[(size_t)t * 256];
        acc1 += e_sm[t + 1] * base[(size_t)(t + 1) * 256];
    }
    acc0 += e_sm[TT - 1] * base[(size_t)(TT - 1) * 256];
    g_attb[b * 256 + tid] = (acc0 + acc1) * inv;
}

// ---------------------------------------------------------------------------
// Classifier head: [g_sbuf, g_attb] -> out
// ---------------------------------------------------------------------------
__global__ __launch_bounds__(64) void head_kernel(
    const float* __restrict__ w1, const float* __restrict__ b1,
    const float* __restrict__ w2, const float* __restrict__ b2,
    float* __restrict__ out)
{
    const int b = blockIdx.x;
    const int tid = threadIdx.x;
    __shared__ float cat[272];
    __shared__ float h1[64];
    if (tid < 16) cat[tid] = g_sbuf[b * 16 + tid];
    for (int j = tid; j < 256; j += 64) cat[16 + j] = g_attb[b * 256 + j];
    __syncthreads();
    float a = b1[tid];
#pragma unroll 4
    for (int k = 0; k < 272; ++k) a += cat[k] * w1[k * 64 + tid];
    h1[tid] = fmaxf(a, 0.f);
    __syncthreads();
    if (tid < 32) {
        float a2 = b2[tid];
#pragma unroll
        for (int k = 0; k < 64; ++k) a2 += h1[k] * w2[k * 32 + tid];
        out[b * 32 + tid] = fmaxf(a2, 0.f);
    }
}

// ---------------------------------------------------------------------------
// Launch
// ---------------------------------------------------------------------------
extern "C" void kernel_launch(void* const* d_in, const int* in_sizes, int n_in,
                              void* d_out, int out_size)
{
    const float* x_static = (const float*)d_in[0];
    const float* x_dyn    = (const float*)d_in[1];
    const int*   seq      = (const int*)  d_in[2];
    const float* w_s0  = (const float*)d_in[3];
    const float* b_s0  = (const float*)d_in[4];
    const float* w_s1  = (const float*)d_in[5];
    const float* b_s1  = (const float*)d_in[6];
    const float* Wx_f0 = (const float*)d_in[7];
    const float* Wh_f0 = (const float*)d_in[8];
    const float* bb_f0 = (const float*)d_in[9];
    const float* Wx_b0 = (const float*)d_in[10];
    const float* Wh_b0 = (const float*)d_in[11];
    const float* bb_b0 = (const float*)d_in[12];
    const float* Wx_f1 = (const float*)d_in[13];
    const float* Wh_f1 = (const float*)d_in[14];
    const float* bb_f1 = (const float*)d_in[15];
    const float* Wx_b1 = (const float*)d_in[16];
    const float* Wh_b1 = (const float*)d_in[17];
    const float* bb_b1 = (const float*)d_in[18];
    const float* w_att = (const float*)d_in[19];
    const float* b_att = (const float*)d_in[20];
    const float* w_c1  = (const float*)d_in[21];
    const float* b_c1  = (const float*)d_in[22];
    const float* w_c2  = (const float*)d_in[23];
    const float* b_c2  = (const float*)d_in[24];
    float* out = (float*)d_out;

    cudaFuncSetAttribute(rec_mma, cudaFuncAttributeMaxDynamicSharedMemorySize, REC_SMEM);

    prep_kernel<<<256, 256>>>(Wh_f0, Wh_b0, Wh_f1, Wh_b1,
                              Wx_f0, Wx_b0, Wx_f1, Wx_b1,
                              bb_f0, bb_b0, bb_f1, bb_b1);
    static_kernel<<<(BATCH + 255) / 256, 256>>>(x_static, w_s0, b_s0, w_s1, b_s1);

    dim3 ggrid(MTOT / 64, 8);
    xpre_gemm_mma<<<ggrid, 256>>>(x_dyn, FDYN, 0, seq);
    rec_mma<<<128, 256, REC_SMEM>>>(seq, 0);
    xpre_gemm_mma<<<ggrid, 256>>>(nullptr, 256, 1, seq);
    rec_mma<<<128, 256, REC_SMEM>>>(seq, 1);
    att_kernel<<<BATCH, 256>>>(w_att, b_att);
    head_kernel<<<BATCH, 64>>>(w_c1, b_c1, w_c2, b_c2, out);
}

// round 7
// speedup vs baseline: 4.9974x; 1.0044x over previous
#include <cuda_runtime.h>
#include <cuda_fp16.h>
#include <cstdint>
#include <math.h>

// Problem constants
#define BATCH 1024
#define TT    169
#define FDYN  36
#define FSTAT 19
#define HID   128
#define MTOT  (BATCH * TT)

// ---------------------------------------------------------------------------
// Scratch (device globals; allocation-free per harness rules).
// Kernels reference these directly — no host-side symbol lookups needed.
// ---------------------------------------------------------------------------
__device__ __half g_xpre16[(size_t)MTOT * 1024];  // [B,T,1024] fp16 gate preacts (both layers reuse)
__device__ __half g_cur0h[(size_t)MTOT * 256];    // layer0 output concat(fw,bw), fp16
__device__ float  g_cur1[(size_t)MTOT * 256];     // layer1 output fp32 (attention input)
__device__ float  g_sbuf[BATCH * 16];
__device__ float  g_attb[BATCH * 256];
__device__ __half g_wh16[4 * 128 * 512];          // fp16 Wh: order f0, b0, f1, b1
__device__ __half g_wx0[36 * 1024];               // concat [Wx_f0 | Wx_b0]
__device__ __half g_wx1[256 * 1024];              // concat [Wx_f1 | Wx_b1]
__device__ float  g_bx0[1024];
__device__ float  g_bx1[1024];

// ---------------------------------------------------------------------------
// MMA / ldmatrix helpers
// ---------------------------------------------------------------------------
__device__ __forceinline__ unsigned smem_u32(const void* p) {
    return (unsigned)__cvta_generic_to_shared(p);
}
__device__ __forceinline__ void ldsm_x4(unsigned& r0, unsigned& r1, unsigned& r2, unsigned& r3, unsigned a) {
    asm volatile("ldmatrix.sync.aligned.m8n8.x4.shared.b16 {%0,%1,%2,%3}, [%4];"
                 : "=r"(r0), "=r"(r1), "=r"(r2), "=r"(r3) : "r"(a));
}
__device__ __forceinline__ void ldsm_x4_t(unsigned& r0, unsigned& r1, unsigned& r2, unsigned& r3, unsigned a) {
    asm volatile("ldmatrix.sync.aligned.m8n8.x4.trans.shared.b16 {%0,%1,%2,%3}, [%4];"
                 : "=r"(r0), "=r"(r1), "=r"(r2), "=r"(r3) : "r"(a));
}
__device__ __forceinline__ void mma16816(float* c, unsigned a0, unsigned a1, unsigned a2, unsigned a3,
                                         unsigned b0, unsigned b1) {
    asm volatile("mma.sync.aligned.m16n8k16.row.col.f32.f16.f16.f32 "
                 "{%0,%1,%2,%3}, {%4,%5,%6,%7}, {%8,%9}, {%0,%1,%2,%3};"
                 : "+f"(c[0]), "+f"(c[1]), "+f"(c[2]), "+f"(c[3])
                 : "r"(a0), "r"(a1), "r"(a2), "r"(a3), "r"(b0), "r"(b1));
}

// ---------------------------------------------------------------------------
// Weight conversion to fp16 (once per launch)
// ---------------------------------------------------------------------------
__global__ __launch_bounds__(256) void prep_kernel(
    const float* __restrict__ Wh_f0, const float* __restrict__ Wh_b0,
    const float* __restrict__ Wh_f1, const float* __restrict__ Wh_b1,
    const float* __restrict__ Wx_f0, const float* __restrict__ Wx_b0,
    const float* __restrict__ Wx_f1, const float* __restrict__ Wx_b1,
    const float* __restrict__ bb_f0, const float* __restrict__ bb_b0,
    const float* __restrict__ bb_f1, const float* __restrict__ bb_b1)
{
    const int N_WH = 4 * 65536;
    const int N_W0 = 36 * 1024;
    const int N_W1 = 256 * 1024;
    const int N_ALL = N_WH + N_W0 + N_W1 + 2048;
    for (int idx = blockIdx.x * 256 + threadIdx.x; idx < N_ALL; idx += gridDim.x * 256) {
        if (idx < N_WH) {
            int which = idx >> 16;
            int off = idx & 65535;
            const float* src = (which == 0) ? Wh_f0 : (which == 1) ? Wh_b0 : (which == 2) ? Wh_f1 : Wh_b1;
            g_wh16[idx] = __float2half(src[off]);
        } else if (idx < N_WH + N_W0) {
            int j = idx - N_WH;
            int k = j >> 10;
            int n = j & 1023;
            float v = (n < 512) ? Wx_f0[k * 512 + n] : Wx_b0[k * 512 + (n - 512)];
            g_wx0[j] = __float2half(v);
        } else if (idx < N_WH + N_W0 + N_W1) {
            int j = idx - N_WH - N_W0;
            int k = j >> 10;
            int n = j & 1023;
            float v = (n < 512) ? Wx_f1[k * 512 + n] : Wx_b1[k * 512 + (n - 512)];
            g_wx1[j] = __float2half(v);
        } else {
            int j = idx - N_WH - N_W0 - N_W1;
            int n = j & 1023;
            if (j < 1024) { g_bx0[n] = (n < 512) ? bb_f0[n] : bb_b0[n - 512]; }
            else          { g_bx1[n] = (n < 512) ? bb_f1[n] : bb_b1[n - 512]; }
        }
    }
}

// ---------------------------------------------------------------------------
// Static branch -> g_sbuf
// ---------------------------------------------------------------------------
__global__ __launch_bounds__(256) void static_kernel(
    const float* __restrict__ x, const float* __restrict__ w0, const float* __restrict__ b0,
    const float* __restrict__ w1, const float* __restrict__ b1)
{
    int b = blockIdx.x * blockDim.x + threadIdx.x;
    if (b >= BATCH) return;
    float xin[FSTAT];
#pragma unroll
    for (int i = 0; i < FSTAT; ++i) xin[i] = x[b * FSTAT + i];
    float h0[16];
#pragma unroll
    for (int j = 0; j < 16; ++j) {
        float a = b0[j];
#pragma unroll
        for (int i = 0; i < FSTAT; ++i) a += xin[i] * w0[i * 16 + j];
        h0[j] = fmaxf(a, 0.f);
    }
#pragma unroll
    for (int j = 0; j < 16; ++j) {
        float a = b1[j];
#pragma unroll
        for (int i = 0; i < 16; ++i) a += h0[i] * w1[i * 16 + j];
        g_sbuf[b * 16 + j] = fmaxf(a, 0.f);
    }
}

// ---------------------------------------------------------------------------
// Input-projection GEMM via mma -> g_xpre16.
// layer==0: A = x_dyn (float, K=36). layer==1: A = g_cur0h (half, K=256).
// BM=64, BN=128, BK=32. 8 warps: wy(0..3) x 16 rows, wx(0..1) x 64 cols.
// ---------------------------------------------------------------------------
__global__ __launch_bounds__(256) void xpre_gemm_mma(
    const float* __restrict__ Afloat, int K, int layer,
    const int* __restrict__ seq_len)
{
    __shared__ __half A_sm[64 * 40];
    __shared__ __half B_sm[32 * 136];

    const int m0 = blockIdx.x * 64;
    const int nb = blockIdx.y * 128;
    const int tid = threadIdx.x;

    int act = 0;
    if (tid < 64) {
        int m = m0 + tid;
        int bi = m / TT;
        int t = m - bi * TT;
        act = (t < seq_len[bi]) ? 1 : 0;
    }
    if (!__syncthreads_or(act)) return;

    const __half* Bw = (layer == 0) ? g_wx0 : g_wx1;
    const float* bias = (layer == 0) ? g_bx0 : g_bx1;

    const int warp = tid >> 5;
    const int lane = tid & 31;
    const int wy = warp >> 1;
    const int wx = warp & 1;

    float c[8][4];
#pragma unroll
    for (int i = 0; i < 8; ++i) {
#pragma unroll
        for (int j = 0; j < 4; ++j) c[i][j] = 0.f;
    }

    for (int k0 = 0; k0 < K; k0 += 32) {
#pragma unroll
        for (int j = 0; j < 8; ++j) {
            int i = tid + j * 256;
            int row = i >> 5;
            int col = i & 31;
            int k = k0 + col;
            __half hv = __float2half(0.f);
            if (k < K) {
                if (layer == 0) hv = __float2half(Afloat[(size_t)(m0 + row) * K + k]);
                else            hv = g_cur0h[(size_t)(m0 + row) * 256 + k];
            }
            A_sm[row * 40 + col] = hv;
        }
#pragma unroll
        for (int j = 0; j < 2; ++j) {
            int i = tid + j * 256;
            int row = i >> 4;
            int c8 = i & 15;
            int k = k0 + row;
            uint4 v = make_uint4(0u, 0u, 0u, 0u);
            if (k < K) v = *(const uint4*)&Bw[(size_t)k * 1024 + nb + c8 * 8];
            *(uint4*)&B_sm[row * 136 + c8 * 8] = v;
        }
        __syncthreads();

#pragma unroll
        for (int kk = 0; kk < 2; ++kk) {
            unsigned a0, a1, a2, a3;
            unsigned aaddr = smem_u32(&A_sm[(wy * 16 + (lane & 15)) * 40 + kk * 16 + (lane >> 4) * 8]);
            ldsm_x4(a0, a1, a2, a3, aaddr);
#pragma unroll
            for (int np = 0; np < 4; ++np) {
                unsigned q0, q1, q2, q3;
                unsigned baddr = smem_u32(&B_sm[(kk * 16 + (lane & 15)) * 136 + wx * 64 + np * 16 + (lane >> 4) * 8]);
                ldsm_x4_t(q0, q1, q2, q3, baddr);
                mma16816(c[np * 2],     a0, a1, a2, a3, q0, q1);
                mma16816(c[np * 2 + 1], a0, a1, a2, a3, q2, q3);
            }
        }
        __syncthreads();
    }

    const int r = lane >> 2;
    const int cb = (lane & 3) * 2;
#pragma unroll
    for (int nt = 0; nt < 8; ++nt) {
        int gn = nb + wx * 64 + nt * 8 + cb;
        float bx = bias[gn];
        float by = bias[gn + 1];
        int m1 = m0 + wy * 16 + r;
        int m2 = m1 + 8;
        __half2 lo = __floats2half2_rn(c[nt][0] + bx, c[nt][1] + by);
        __half2 hi = __floats2half2_rn(c[nt][2] + bx, c[nt][3] + by);
        *(__half2*)&g_xpre16[(size_t)m1 * 1024 + gn] = lo;
        *(__half2*)&g_xpre16[(size_t)m2 * 1024 + gn] = hi;
    }
}

// ---------------------------------------------------------------------------
// Persistent recurrent kernel, SMEM-resident fp16 Wh, mma phase1.
// 128 blocks: 0..63 fw, 64..127 bw; 16 batch rows/block; 169 steps.
// Dyn smem: WH[128][520] h | HS[16][136] h | GS[16][516] f | LS[17] i
// ---------------------------------------------------------------------------
#define WH_STRIDE 520
#define HS_STRIDE 136
#define GS_STRIDE 516
#define SM_HS_OFF 133120
#define SM_GS_OFF 137472
#define SM_LS_OFF 170496
#define REC_SMEM  170624

__global__ __launch_bounds__(256) void rec_mma(const int* __restrict__ seq_len, int layer)
{
    extern __shared__ char smraw[];
    __half* WH = (__half*)(smraw);
    __half* HS = (__half*)(smraw + SM_HS_OFF);
    float*  GS = (float*)(smraw + SM_GS_OFF);
    int*    LS = (int*)(smraw + SM_LS_OFF);

    const int blk = blockIdx.x;
    const int dir = blk >> 6;
    const int b0 = (blk & 63) * 16;
    const int xoff = dir * 512;
    const int ooff = dir * 128;
    const int tid = threadIdx.x;

    const __half* wg = g_wh16 + (size_t)(layer * 2 + dir) * 65536;
#pragma unroll 8
    for (int i = tid; i < 8192; i += 256) {
        int r = i >> 6;
        int c8 = i & 63;
        *(uint4*)&WH[r * WH_STRIDE + c8 * 8] = ((const uint4*)wg)[i];
    }
    for (int i = tid; i < (16 * HS_STRIDE) / 2; i += 256) ((unsigned*)HS)[i] = 0u;
    if (tid < 16) LS[tid] = seq_len[b0 + tid];
    __syncthreads();
    if (tid == 0) {
        int m = 0;
#pragma unroll
        for (int i = 0; i < 16; ++i) m = max(m, LS[i]);
        LS[16] = m;
    }
    __syncthreads();
    const int Lmax = LS[16];

    const int warp = tid >> 5;
    const int lane = tid & 31;
    const int n_base = warp * 64;
    const int r2 = tid >> 4;
    const int h2 = (tid & 15) * 8;
    const int L = LS[r2];
    const size_t bR = (size_t)(b0 + r2);

    float c_reg[8];
#pragma unroll
    for (int u = 0; u < 8; ++u) c_reg[u] = 0.f;

    const int arow = lane & 15;
    const int acol8 = (lane >> 4) * 8;

    for (int step = 0; step < TT; ++step) {
        if (step < Lmax) {
            float c[8][4];
#pragma unroll
            for (int i = 0; i < 8; ++i) {
#pragma unroll
                for (int j = 0; j < 4; ++j) c[i][j] = 0.f;
            }
#pragma unroll
            for (int kk = 0; kk < 8; ++kk) {
                unsigned a0, a1, a2, a3;
                unsigned aaddr = smem_u32(&HS[arow * HS_STRIDE + kk * 16 + acol8]);
                ldsm_x4(a0, a1, a2, a3, aaddr);
#pragma unroll
                for (int np = 0; np < 4; ++np) {
                    unsigned q0, q1, q2, q3;
                    unsigned baddr = smem_u32(&WH[(kk * 16 + arow) * WH_STRIDE + n_base + np * 16 + acol8]);
                    ldsm_x4_t(q0, q1, q2, q3, baddr);
                    mma16816(c[np * 2],     a0, a1, a2, a3, q0, q1);
                    mma16816(c[np * 2 + 1], a0, a1, a2, a3, q2, q3);
                }
            }
            const int rr = lane >> 2;
            const int cbase = (lane & 3) * 2;
#pragma unroll
            for (int nt = 0; nt < 8; ++nt) {
                int n = n_base + nt * 8 + cbase;
                *(float2*)&GS[rr * GS_STRIDE + n]       = make_float2(c[nt][0], c[nt][1]);
                *(float2*)&GS[(rr + 8) * GS_STRIDE + n] = make_float2(c[nt][2], c[nt][3]);
            }
        }
        __syncthreads();

        const bool active = (step < L);
        float hv[8];
        int pos;
        if (active) {
            int in_idx = dir ? (L - 1 - step) : step;
            pos = in_idx;
            const __half* xp = g_xpre16 + (bR * TT + in_idx) * 1024 + xoff + h2;
            uint4 vi = *(const uint4*)(xp);
            uint4 vj = *(const uint4*)(xp + 128);
            uint4 vf = *(const uint4*)(xp + 256);
            uint4 vo = *(const uint4*)(xp + 384);
            const __half* pi = (const __half*)&vi;
            const __half* pj = (const __half*)&vj;
            const __half* pf = (const __half*)&vf;
            const __half* po = (const __half*)&vo;
            const float* gsr = &GS[r2 * GS_STRIDE];
#pragma unroll
            for (int u = 0; u < 8; ++u) {
                float gi = __half2float(pi[u]) + gsr[h2 + u];
                float gj = __half2float(pj[u]) + gsr[128 + h2 + u];
                float gf = __half2float(pf[u]) + gsr[256 + h2 + u];
                float go = __half2float(po[u]) + gsr[384 + h2 + u];
                float ig = 1.f / (1.f + expf(-gi));
                float fg = 1.f / (1.f + expf(-(gf + 1.f)));
                float og = 1.f / (1.f + expf(-go));
                float jg = tanhf(gj);
                float cn = c_reg[u] * fg + ig * jg;
                c_reg[u] = cn;
                hv[u] = tanhf(cn) * og;
            }
        } else {
            pos = step;
#pragma unroll
            for (int u = 0; u < 8; ++u) hv[u] = 0.f;
        }

        if (layer == 0) {
            __half hb[8];
#pragma unroll
            for (int u = 0; u < 8; ++u) hb[u] = __float2half(hv[u]);
            *(uint4*)&g_cur0h[(bR * TT + pos) * 256 + ooff + h2] = *(uint4*)hb;
        } else {
            float* op = &g_cur1[(bR * TT + pos) * 256 + ooff + h2];
            *(float4*)(op)     = make_float4(hv[0], hv[1], hv[2], hv[3]);
            *(float4*)(op + 4) = make_float4(hv[4], hv[5], hv[6], hv[7]);
        }
        if (active) {
            __half hb2[8];
#pragma unroll
            for (int u = 0; u < 8; ++u) hb2[u] = __float2half(hv[u]);
            *(uint4*)&HS[r2 * HS_STRIDE + h2] = *(uint4*)hb2;
        }
        __syncthreads();
    }
}

// ---------------------------------------------------------------------------
// Attention pooling: g_cur1 -> g_attb
// ---------------------------------------------------------------------------
__global__ __launch_bounds__(256) void att_kernel(
    const float* __restrict__ w_att, const float* __restrict__ b_att)
{
    const int b = blockIdx.x;
    const int tid = threadIdx.x;
    __shared__ float wv[256];
    __shared__ float e_sm[176];
    __shared__ float red[40];
    wv[tid] = w_att[tid];
    __syncthreads();

    const int warp = tid >> 5;
    const int lane = tid & 31;
    for (int t = warp; t < TT; t += 8) {
        const float* p = &g_cur1[((size_t)b * TT + t) * 256];
        float s = 0.f;
#pragma unroll
        for (int j = 0; j < 8; ++j) s += p[lane + 32 * j] * wv[lane + 32 * j];
#pragma unroll
        for (int off = 16; off > 0; off >>= 1) s += __shfl_down_sync(0xffffffffu, s, off);
        if (lane == 0) e_sm[t] = tanhf(s + b_att[0]);
    }
    __syncthreads();

    float m = -1e30f;
    for (int t = tid; t < TT; t += 256) m = fmaxf(m, e_sm[t]);
#pragma unroll
    for (int off = 16; off > 0; off >>= 1) m = fmaxf(m, __shfl_xor_sync(0xffffffffu, m, off));
    if (lane == 0) red[warp] = m;
    __syncthreads();
    if (tid == 0) {
        float mm = red[0];
        for (int w = 1; w < 8; ++w) mm = fmaxf(mm, red[w]);
        red[32] = mm;
    }
    __syncthreads();
    const float mx = red[32];

    float ssum = 0.f;
    for (int t = tid; t < TT; t += 256) {
        float p = expf(e_sm[t] - mx);
        e_sm[t] = p;
        ssum += p;
    }
#pragma unroll
    for (int off = 16; off > 0; off >>= 1) ssum += __shfl_xor_sync(0xffffffffu, ssum, off);
    if (lane == 0) red[warp] = ssum;
    __syncthreads();
    if (tid == 0) {
        float s2 = 0.f;
        for (int w = 0; w < 8; ++w) s2 += red[w];
        red[33] = s2;
    }
    __syncthreads();
    const float inv = 1.f / red[33];

    float acc0 = 0.f, acc1 = 0.f;
    const float* base = &g_cur1[(size_t)b * TT * 256 + tid];
    for (int t = 0; t < TT - 1; t += 2) {
        acc0 += e_sm[t]     * base[(size_t)t * 256];
        acc1 += e_sm[t + 1] * base[(size_t)(t + 1) * 256];
    }
    acc0 += e_sm[TT - 1] * base[(size_t)(TT - 1) * 256];
    g_attb[b * 256 + tid] = (acc0 + acc1) * inv;
}

// ---------------------------------------------------------------------------
// Classifier head: [g_sbuf, g_attb] -> out
// ---------------------------------------------------------------------------
__global__ __launch_bounds__(64) void head_kernel(
    const float* __restrict__ w1, const float* __restrict__ b1,
    const float* __restrict__ w2, const float* __restrict__ b2,
    float* __restrict__ out)
{
    const int b = blockIdx.x;
    const int tid = threadIdx.x;
    __shared__ float cat[272];
    __shared__ float h1[64];
    if (tid < 16) cat[tid] = g_sbuf[b * 16 + tid];
    for (int j = tid; j < 256; j += 64) cat[16 + j] = g_attb[b * 256 + j];
    __syncthreads();
    float a = b1[tid];
#pragma unroll 4
    for (int k = 0; k < 272; ++k) a += cat[k] * w1[k * 64 + tid];
    h1[tid] = fmaxf(a, 0.f);
    __syncthreads();
    if (tid < 32) {
        float a2 = b2[tid];
#pragma unroll
        for (int k = 0; k < 64; ++k) a2 += h1[k] * w2[k * 32 + tid];
        out[b * 32 + tid] = fmaxf(a2, 0.f);
    }
}

// ---------------------------------------------------------------------------
// Launch
// ---------------------------------------------------------------------------
extern "C" void kernel_launch(void* const* d_in, const int* in_sizes, int n_in,
                              void* d_out, int out_size)
{
    const float* x_static = (const float*)d_in[0];
    const float* x_dyn    = (const float*)d_in[1];
    const int*   seq      = (const int*)  d_in[2];
    const float* w_s0  = (const float*)d_in[3];
    const float* b_s0  = (const float*)d_in[4];
    const float* w_s1  = (const float*)d_in[5];
    const float* b_s1  = (const float*)d_in[6];
    const float* Wx_f0 = (const float*)d_in[7];
    const float* Wh_f0 = (const float*)d_in[8];
    const float* bb_f0 = (const float*)d_in[9];
    const float* Wx_b0 = (const float*)d_in[10];
    const float* Wh_b0 = (const float*)d_in[11];
    const float* bb_b0 = (const float*)d_in[12];
    const float* Wx_f1 = (const float*)d_in[13];
    const float* Wh_f1 = (const float*)d_in[14];
    const float* bb_f1 = (const float*)d_in[15];
    const float* Wx_b1 = (const float*)d_in[16];
    const float* Wh_b1 = (const float*)d_in[17];
    const float* bb_b1 = (const float*)d_in[18];
    const float* w_att = (const float*)d_in[19];
    const float* b_att = (const float*)d_in[20];
    const float* w_c1  = (const float*)d_in[21];
    const float* b_c1  = (const float*)d_in[22];
    const float* w_c2  = (const float*)d_in[23];
    const float* b_c2  = (const float*)d_in[24];
    float* out = (float*)d_out;

    cudaFuncSetAttribute(rec_mma, cudaFuncAttributeMaxDynamicSharedMemorySize, REC_SMEM);

    prep_kernel<<<256, 256>>>(Wh_f0, Wh_b0, Wh_f1, Wh_b1,
                              Wx_f0, Wx_b0, Wx_f1, Wx_b1,
                              bb_f0, bb_b0, bb_f1, bb_b1);
    static_kernel<<<(BATCH + 255) / 256, 256>>>(x_static, w_s0, b_s0, w_s1, b_s1);

    dim3 ggrid(MTOT / 64, 8);
    xpre_gemm_mma<<<ggrid, 256>>>(x_dyn, FDYN, 0, seq);
    rec_mma<<<128, 256, REC_SMEM>>>(seq, 0);
    xpre_gemm_mma<<<ggrid, 256>>>(nullptr, 256, 1, seq);
    rec_mma<<<128, 256, REC_SMEM>>>(seq, 1);
    att_kernel<<<BATCH, 256>>>(w_att, b_att);
    head_kernel<<<BATCH, 64>>>(w_c1, b_c1, w_c2, b_c2, out);
}

// round 8
// speedup vs baseline: 8.0964x; 1.6201x over previous
#include <cuda_runtime.h>
#include <cuda_fp16.h>
#include <cstdint>
#include <math.h>

// Problem constants
#define BATCH 1024
#define TT    169
#define FDYN  36
#define FSTAT 19
#define HID   128
#define MTOT  (BATCH * TT)

// ---------------------------------------------------------------------------
// Scratch (device globals)
// ---------------------------------------------------------------------------
__device__ __half g_xpre16[(size_t)MTOT * 1024];
__device__ __half g_cur0h[(size_t)MTOT * 256];
__device__ float  g_cur1[(size_t)MTOT * 256];
__device__ float  g_sbuf[BATCH * 16];
__device__ float  g_attb[BATCH * 256];
__device__ __half g_wh16[4 * 128 * 512];
__device__ __half g_wx0[36 * 1024];
__device__ __half g_wx1[256 * 1024];
__device__ float  g_bx0[1024];
__device__ float  g_bx1[1024];

// ---------------------------------------------------------------------------
// MMA / ldmatrix / fast-math helpers
// ---------------------------------------------------------------------------
__device__ __forceinline__ unsigned smem_u32(const void* p) {
    return (unsigned)__cvta_generic_to_shared(p);
}
__device__ __forceinline__ void ldsm_x4(unsigned& r0, unsigned& r1, unsigned& r2, unsigned& r3, unsigned a) {
    asm volatile("ldmatrix.sync.aligned.m8n8.x4.shared.b16 {%0,%1,%2,%3}, [%4];"
                 : "=r"(r0), "=r"(r1), "=r"(r2), "=r"(r3) : "r"(a));
}
__device__ __forceinline__ void ldsm_x4_t(unsigned& r0, unsigned& r1, unsigned& r2, unsigned& r3, unsigned a) {
    asm volatile("ldmatrix.sync.aligned.m8n8.x4.trans.shared.b16 {%0,%1,%2,%3}, [%4];"
                 : "=r"(r0), "=r"(r1), "=r"(r2), "=r"(r3) : "r"(a));
}
__device__ __forceinline__ void mma16816(float* c, unsigned a0, unsigned a1, unsigned a2, unsigned a3,
                                         unsigned b0, unsigned b1) {
    asm volatile("mma.sync.aligned.m16n8k16.row.col.f32.f16.f16.f32 "
                 "{%0,%1,%2,%3}, {%4,%5,%6,%7}, {%8,%9}, {%0,%1,%2,%3};"
                 : "+f"(c[0]), "+f"(c[1]), "+f"(c[2]), "+f"(c[3])
                 : "r"(a0), "r"(a1), "r"(a2), "r"(a3), "r"(b0), "r"(b1));
}
__device__ __forceinline__ float fast_ex2(float x) {
    float r; asm("ex2.approx.f32 %0, %1;" : "=f"(r) : "f"(x)); return r;
}
__device__ __forceinline__ float fast_rcp(float x) {
    float r; asm("rcp.approx.f32 %0, %1;" : "=f"(r) : "f"(x)); return r;
}
__device__ __forceinline__ float sigmoid_fast(float x) {
    // 1/(1+e^-x) = rcp(1 + 2^(-x*log2e))
    return fast_rcp(1.f + fast_ex2(-1.44269504f * x));
}
__device__ __forceinline__ float tanh_fast(float x) {
    // tanh(x) = 1 - 2/(1+e^{2x});  e^{2x} = 2^(2x*log2e)
    float e = fast_ex2(2.88539008f * x);
    return 1.f - 2.f * fast_rcp(1.f + e);
}

// ---------------------------------------------------------------------------
// Weight conversion to fp16 (once per launch)
// ---------------------------------------------------------------------------
__global__ __launch_bounds__(256) void prep_kernel(
    const float* __restrict__ Wh_f0, const float* __restrict__ Wh_b0,
    const float* __restrict__ Wh_f1, const float* __restrict__ Wh_b1,
    const float* __restrict__ Wx_f0, const float* __restrict__ Wx_b0,
    const float* __restrict__ Wx_f1, const float* __restrict__ Wx_b1,
    const float* __restrict__ bb_f0, const float* __restrict__ bb_b0,
    const float* __restrict__ bb_f1, const float* __restrict__ bb_b1)
{
    const int N_WH = 4 * 65536;
    const int N_W0 = 36 * 1024;
    const int N_W1 = 256 * 1024;
    const int N_ALL = N_WH + N_W0 + N_W1 + 2048;
    for (int idx = blockIdx.x * 256 + threadIdx.x; idx < N_ALL; idx += gridDim.x * 256) {
        if (idx < N_WH) {
            int which = idx >> 16;
            int off = idx & 65535;
            const float* src = (which == 0) ? Wh_f0 : (which == 1) ? Wh_b0 : (which == 2) ? Wh_f1 : Wh_b1;
            g_wh16[idx] = __float2half(src[off]);
        } else if (idx < N_WH + N_W0) {
            int j = idx - N_WH;
            int k = j >> 10;
            int n = j & 1023;
            float v = (n < 512) ? Wx_f0[k * 512 + n] : Wx_b0[k * 512 + (n - 512)];
            g_wx0[j] = __float2half(v);
        } else if (idx < N_WH + N_W0 + N_W1) {
            int j = idx - N_WH - N_W0;
            int k = j >> 10;
            int n = j & 1023;
            float v = (n < 512) ? Wx_f1[k * 512 + n] : Wx_b1[k * 512 + (n - 512)];
            g_wx1[j] = __float2half(v);
        } else {
            int j = idx - N_WH - N_W0 - N_W1;
            int n = j & 1023;
            if (j < 1024) { g_bx0[n] = (n < 512) ? bb_f0[n] : bb_b0[n - 512]; }
            else          { g_bx1[n] = (n < 512) ? bb_f1[n] : bb_b1[n - 512]; }
        }
    }
}

// ---------------------------------------------------------------------------
// Static branch -> g_sbuf
// ---------------------------------------------------------------------------
__global__ __launch_bounds__(256) void static_kernel(
    const float* __restrict__ x, const float* __restrict__ w0, const float* __restrict__ b0,
    const float* __restrict__ w1, const float* __restrict__ b1)
{
    int b = blockIdx.x * blockDim.x + threadIdx.x;
    if (b >= BATCH) return;
    float xin[FSTAT];
#pragma unroll
    for (int i = 0; i < FSTAT; ++i) xin[i] = x[b * FSTAT + i];
    float h0[16];
#pragma unroll
    for (int j = 0; j < 16; ++j) {
        float a = b0[j];
#pragma unroll
        for (int i = 0; i < FSTAT; ++i) a += xin[i] * w0[i * 16 + j];
        h0[j] = fmaxf(a, 0.f);
    }
#pragma unroll
    for (int j = 0; j < 16; ++j) {
        float a = b1[j];
#pragma unroll
        for (int i = 0; i < 16; ++i) a += h0[i] * w1[i * 16 + j];
        g_sbuf[b * 16 + j] = fmaxf(a, 0.f);
    }
}

// ---------------------------------------------------------------------------
// Input-projection GEMM via mma -> g_xpre16.
// layer==0: A = x_dyn (float, K=36). layer==1: A = g_cur0h (half, K=256).
// ---------------------------------------------------------------------------
__global__ __launch_bounds__(256) void xpre_gemm_mma(
    const float* __restrict__ Afloat, int K, int layer,
    const int* __restrict__ seq_len)
{
    __shared__ __half A_sm[64 * 40];
    __shared__ __half B_sm[32 * 136];

    const int m0 = blockIdx.x * 64;
    const int nb = blockIdx.y * 128;
    const int tid = threadIdx.x;

    int act = 0;
    if (tid < 64) {
        int m = m0 + tid;
        int bi = m / TT;
        int t = m - bi * TT;
        act = (t < seq_len[bi]) ? 1 : 0;
    }
    if (!__syncthreads_or(act)) return;

    const __half* Bw = (layer == 0) ? g_wx0 : g_wx1;
    const float* bias = (layer == 0) ? g_bx0 : g_bx1;

    const int warp = tid >> 5;
    const int lane = tid & 31;
    const int wy = warp >> 1;
    const int wx = warp & 1;

    float c[8][4];
#pragma unroll
    for (int i = 0; i < 8; ++i) {
#pragma unroll
        for (int j = 0; j < 4; ++j) c[i][j] = 0.f;
    }

    for (int k0 = 0; k0 < K; k0 += 32) {
        if (layer == 1) {
            // vectorized A load: 64 rows x 32 halves, each thread one uint4 (8 halves)
            int row = tid >> 2;
            int colc = (tid & 3) * 8;
            uint4 v = *(const uint4*)&g_cur0h[(size_t)(m0 + row) * 256 + k0 + colc];
            *(uint4*)&A_sm[row * 40 + colc] = v;
        } else {
#pragma unroll
            for (int j = 0; j < 8; ++j) {
                int i = tid + j * 256;
                int row = i >> 5;
                int col = i & 31;
                int k = k0 + col;
                __half hv = __float2half(0.f);
                if (k < K) hv = __float2half(Afloat[(size_t)(m0 + row) * K + k]);
                A_sm[row * 40 + col] = hv;
            }
        }
#pragma unroll
        for (int j = 0; j < 2; ++j) {
            int i = tid + j * 256;
            int row = i >> 4;
            int c8 = i & 15;
            int k = k0 + row;
            uint4 v = make_uint4(0u, 0u, 0u, 0u);
            if (k < K) v = *(const uint4*)&Bw[(size_t)k * 1024 + nb + c8 * 8];
            *(uint4*)&B_sm[row * 136 + c8 * 8] = v;
        }
        __syncthreads();

#pragma unroll
        for (int kk = 0; kk < 2; ++kk) {
            unsigned a0, a1, a2, a3;
            unsigned aaddr = smem_u32(&A_sm[(wy * 16 + (lane & 15)) * 40 + kk * 16 + (lane >> 4) * 8]);
            ldsm_x4(a0, a1, a2, a3, aaddr);
#pragma unroll
            for (int np = 0; np < 4; ++np) {
                unsigned q0, q1, q2, q3;
                unsigned baddr = smem_u32(&B_sm[(kk * 16 + (lane & 15)) * 136 + wx * 64 + np * 16 + (lane >> 4) * 8]);
                ldsm_x4_t(q0, q1, q2, q3, baddr);
                mma16816(c[np * 2],     a0, a1, a2, a3, q0, q1);
                mma16816(c[np * 2 + 1], a0, a1, a2, a3, q2, q3);
            }
        }
        __syncthreads();
    }

    const int r = lane >> 2;
    const int cb = (lane & 3) * 2;
#pragma unroll
    for (int nt = 0; nt < 8; ++nt) {
        int gn = nb + wx * 64 + nt * 8 + cb;
        float bx = bias[gn];
        float by = bias[gn + 1];
        int m1 = m0 + wy * 16 + r;
        int m2 = m1 + 8;
        __half2 lo = __floats2half2_rn(c[nt][0] + bx, c[nt][1] + by);
        __half2 hi = __floats2half2_rn(c[nt][2] + bx, c[nt][3] + by);
        *(__half2*)&g_xpre16[(size_t)m1 * 1024 + gn] = lo;
        *(__half2*)&g_xpre16[(size_t)m2 * 1024 + gn] = hi;
    }
}

// ---------------------------------------------------------------------------
// Persistent recurrent kernel v2.
// 512 threads (16 warps), 128 blocks (0..63 fw, 64..127 bw), 16 batch rows.
// Wh held in per-thread register fragments (loaded once via ldmatrix).
// Per step: phase1 = 8 ldsm(A) + 32 HMMA per warp -> GS; phase2 = cell update
// with ex2/rcp-based activations; xpre prefetched before phase1.
// Dyn smem: WH[128][520]h (init staging) | HS[16][136]h | GS[16][520]f | LS
// ---------------------------------------------------------------------------
#define WH_STRIDE 520
#define HS_STRIDE 136
#define GS_STRIDE 520
#define SM_HS_OFF 133120
#define SM_GS_OFF 137472
#define SM_LS_OFF 170752
#define REC_SMEM  170880

__global__ __launch_bounds__(512) void rec_mma(const int* __restrict__ seq_len, int layer)
{
    extern __shared__ char smraw[];
    __half* WH = (__half*)(smraw);
    __half* HS = (__half*)(smraw + SM_HS_OFF);
    float*  GS = (float*)(smraw + SM_GS_OFF);
    int*    LS = (int*)(smraw + SM_LS_OFF);

    const int blk = blockIdx.x;
    const int dir = blk >> 6;
    const int b0 = (blk & 63) * 16;
    const int xoff = dir * 512;
    const int ooff = dir * 128;
    const int tid = threadIdx.x;

    // stage Wh into smem once
    const __half* wg = g_wh16 + (size_t)(layer * 2 + dir) * 65536;
#pragma unroll 4
    for (int i = tid; i < 8192; i += 512) {
        int r = i >> 6;
        int c8 = i & 63;
        *(uint4*)&WH[r * WH_STRIDE + c8 * 8] = ((const uint4*)wg)[i];
    }
    for (int i = tid; i < (16 * HS_STRIDE) / 2; i += 512) ((unsigned*)HS)[i] = 0u;
    if (tid < 16) LS[tid] = seq_len[b0 + tid];
    __syncthreads();
    if (tid == 0) {
        int m = 0;
#pragma unroll
        for (int i = 0; i < 16; ++i) m = max(m, LS[i]);
        LS[16] = m;
    }
    __syncthreads();
    const int Lmax = LS[16];

    const int warp = tid >> 5;
    const int lane = tid & 31;
    const int n_base = warp * 32;          // warp owns 32 N-cols
    const int arow = lane & 15;
    const int acol8 = (lane >> 4) * 8;

    // load Wh B-fragments into registers (once)
    unsigned bfr[8][8];
#pragma unroll
    for (int kk = 0; kk < 8; ++kk) {
#pragma unroll
        for (int nt2 = 0; nt2 < 2; ++nt2) {
            unsigned baddr = smem_u32(&WH[(kk * 16 + arow) * WH_STRIDE + n_base + nt2 * 16 + acol8]);
            ldsm_x4_t(bfr[kk][nt2 * 4 + 0], bfr[kk][nt2 * 4 + 1],
                      bfr[kk][nt2 * 4 + 2], bfr[kk][nt2 * 4 + 3], baddr);
        }
    }

    // phase2 mapping: warp == batch row, lane*4 == hidden slice
    const int r2 = warp;
    const int h2 = lane * 4;
    const int L = LS[r2];
    const size_t bR = (size_t)(b0 + r2);

    float c_reg[4] = {0.f, 0.f, 0.f, 0.f};

    for (int step = 0; step < TT; ++step) {
        // prefetch xpre for this step (consumed in phase2, after the MMA block)
        const bool active = (step < L);
        const int in_idx = active ? (dir ? (L - 1 - step) : step) : 0;
        uint2 vi, vj, vf, vo;
        if (active) {
            const __half* xp = g_xpre16 + (bR * TT + in_idx) * 1024 + xoff + h2;
            vi = *(const uint2*)(xp);
            vj = *(const uint2*)(xp + 128);
            vf = *(const uint2*)(xp + 256);
            vo = *(const uint2*)(xp + 384);
        }

        if (step < Lmax) {
            float c[4][4];
#pragma unroll
            for (int i = 0; i < 4; ++i) {
#pragma unroll
                for (int j = 0; j < 4; ++j) c[i][j] = 0.f;
            }
#pragma unroll
            for (int kk = 0; kk < 8; ++kk) {
                unsigned a0, a1, a2, a3;
                unsigned aaddr = smem_u32(&HS[arow * HS_STRIDE + kk * 16 + acol8]);
                ldsm_x4(a0, a1, a2, a3, aaddr);
                mma16816(c[0], a0, a1, a2, a3, bfr[kk][0], bfr[kk][1]);
                mma16816(c[1], a0, a1, a2, a3, bfr[kk][2], bfr[kk][3]);
                mma16816(c[2], a0, a1, a2, a3, bfr[kk][4], bfr[kk][5]);
                mma16816(c[3], a0, a1, a2, a3, bfr[kk][6], bfr[kk][7]);
            }
            const int rr = lane >> 2;
            const int cb = (lane & 3) * 2;
#pragma unroll
            for (int nt = 0; nt < 4; ++nt) {
                int n = n_base + nt * 8 + cb;
                *(float2*)&GS[rr * GS_STRIDE + n]       = make_float2(c[nt][0], c[nt][1]);
                *(float2*)&GS[(rr + 8) * GS_STRIDE + n] = make_float2(c[nt][2], c[nt][3]);
            }
        }
        __syncthreads();

        float hv[4];
        int pos;
        if (active) {
            pos = in_idx;
            const __half* pi = (const __half*)&vi;
            const __half* pj = (const __half*)&vj;
            const __half* pf = (const __half*)&vf;
            const __half* po = (const __half*)&vo;
            const float* gsr = &GS[r2 * GS_STRIDE];
#pragma unroll
            for (int u = 0; u < 4; ++u) {
                float gi = __half2float(pi[u]) + gsr[h2 + u];
                float gj = __half2float(pj[u]) + gsr[128 + h2 + u];
                float gf = __half2float(pf[u]) + gsr[256 + h2 + u];
                float go = __half2float(po[u]) + gsr[384 + h2 + u];
                float ig = sigmoid_fast(gi);
                float fg = sigmoid_fast(gf + 1.f);
                float og = sigmoid_fast(go);
                float jg = tanh_fast(gj);
                float cn = c_reg[u] * fg + ig * jg;
                c_reg[u] = cn;
                hv[u] = tanh_fast(cn) * og;
            }
        } else {
            pos = step;
#pragma unroll
            for (int u = 0; u < 4; ++u) hv[u] = 0.f;
        }

        if (layer == 0) {
            __half hb[4];
#pragma unroll
            for (int u = 0; u < 4; ++u) hb[u] = __float2half(hv[u]);
            *(uint2*)&g_cur0h[(bR * TT + pos) * 256 + ooff + h2] = *(uint2*)hb;
        } else {
            *(float4*)&g_cur1[(bR * TT + pos) * 256 + ooff + h2] =
                make_float4(hv[0], hv[1], hv[2], hv[3]);
        }
        if (active) {
            __half hb2[4];
#pragma unroll
            for (int u = 0; u < 4; ++u) hb2[u] = __float2half(hv[u]);
            *(uint2*)&HS[r2 * HS_STRIDE + h2] = *(uint2*)hb2;
        }
        __syncthreads();
    }
}

// ---------------------------------------------------------------------------
// Attention pooling: g_cur1 -> g_attb
// ---------------------------------------------------------------------------
__global__ __launch_bounds__(256) void att_kernel(
    const float* __restrict__ w_att, const float* __restrict__ b_att)
{
    const int b = blockIdx.x;
    const int tid = threadIdx.x;
    __shared__ float wv[256];
    __shared__ float e_sm[176];
    __shared__ float red[40];
    wv[tid] = w_att[tid];
    __syncthreads();

    const int warp = tid >> 5;
    const int lane = tid & 31;
    for (int t = warp; t < TT; t += 8) {
        const float* p = &g_cur1[((size_t)b * TT + t) * 256];
        float s = 0.f;
#pragma unroll
        for (int j = 0; j < 8; ++j) s += p[lane + 32 * j] * wv[lane + 32 * j];
#pragma unroll
        for (int off = 16; off > 0; off >>= 1) s += __shfl_down_sync(0xffffffffu, s, off);
        if (lane == 0) e_sm[t] = tanhf(s + b_att[0]);
    }
    __syncthreads();

    float m = -1e30f;
    for (int t = tid; t < TT; t += 256) m = fmaxf(m, e_sm[t]);
#pragma unroll
    for (int off = 16; off > 0; off >>= 1) m = fmaxf(m, __shfl_xor_sync(0xffffffffu, m, off));
    if (lane == 0) red[warp] = m;
    __syncthreads();
    if (tid == 0) {
        float mm = red[0];
        for (int w = 1; w < 8; ++w) mm = fmaxf(mm, red[w]);
        red[32] = mm;
    }
    __syncthreads();
    const float mx = red[32];

    float ssum = 0.f;
    for (int t = tid; t < TT; t += 256) {
        float p = expf(e_sm[t] - mx);
        e_sm[t] = p;
        ssum += p;
    }
#pragma unroll
    for (int off = 16; off > 0; off >>= 1) ssum += __shfl_xor_sync(0xffffffffu, ssum, off);
    if (lane == 0) red[warp] = ssum;
    __syncthreads();
    if (tid == 0) {
        float s2 = 0.f;
        for (int w = 0; w < 8; ++w) s2 += red[w];
        red[33] = s2;
    }
    __syncthreads();
    const float inv = 1.f / red[33];

    float acc0 = 0.f, acc1 = 0.f;
    const float* base = &g_cur1[(size_t)b * TT * 256 + tid];
    for (int t = 0; t < TT - 1; t += 2) {
        acc0 += e_sm[t]     * base[(size_t)t * 256];
        acc1 += e_sm[t + 1] * base[(size_t)(t + 1) * 256];
    }
    acc0 += e_sm[TT - 1] * base[(size_t)(TT - 1) * 256];
    g_attb[b * 256 + tid] = (acc0 + acc1) * inv;
}

// ---------------------------------------------------------------------------
// Classifier head: [g_sbuf, g_attb] -> out
// ---------------------------------------------------------------------------
__global__ __launch_bounds__(64) void head_kernel(
    const float* __restrict__ w1, const float* __restrict__ b1,
    const float* __restrict__ w2, const float* __restrict__ b2,
    float* __restrict__ out)
{
    const int b = blockIdx.x;
    const int tid = threadIdx.x;
    __shared__ float cat[272];
    __shared__ float h1[64];
    if (tid < 16) cat[tid] = g_sbuf[b * 16 + tid];
    for (int j = tid; j < 256; j += 64) cat[16 + j] = g_attb[b * 256 + j];
    __syncthreads();
    float a = b1[tid];
#pragma unroll 4
    for (int k = 0; k < 272; ++k) a += cat[k] * w1[k * 64 + tid];
    h1[tid] = fmaxf(a, 0.f);
    __syncthreads();
    if (tid < 32) {
        float a2 = b2[tid];
#pragma unroll
        for (int k = 0; k < 64; ++k) a2 += h1[k] * w2[k * 32 + tid];
        out[b * 32 + tid] = fmaxf(a2, 0.f);
    }
}

// ---------------------------------------------------------------------------
// Launch
// ---------------------------------------------------------------------------
extern "C" void kernel_launch(void* const* d_in, const int* in_sizes, int n_in,
                              void* d_out, int out_size)
{
    const float* x_static = (const float*)d_in[0];
    const float* x_dyn    = (const float*)d_in[1];
    const int*   seq      = (const int*)  d_in[2];
    const float* w_s0  = (const float*)d_in[3];
    const float* b_s0  = (const float*)d_in[4];
    const float* w_s1  = (const float*)d_in[5];
    const float* b_s1  = (const float*)d_in[6];
    const float* Wx_f0 = (const float*)d_in[7];
    const float* Wh_f0 = (const float*)d_in[8];
    const float* bb_f0 = (const float*)d_in[9];
    const float* Wx_b0 = (const float*)d_in[10];
    const float* Wh_b0 = (const float*)d_in[11];
    const float* bb_b0 = (const float*)d_in[12];
    const float* Wx_f1 = (const float*)d_in[13];
    const float* Wh_f1 = (const float*)d_in[14];
    const float* bb_f1 = (const float*)d_in[15];
    const float* Wx_b1 = (const float*)d_in[16];
    const float* Wh_b1 = (const float*)d_in[17];
    const float* bb_b1 = (const float*)d_in[18];
    const float* w_att = (const float*)d_in[19];
    const float* b_att = (const float*)d_in[20];
    const float* w_c1  = (const float*)d_in[21];
    const float* b_c1  = (const float*)d_in[22];
    const float* w_c2  = (const float*)d_in[23];
    const float* b_c2  = (const float*)d_in[24];
    float* out = (float*)d_out;

    cudaFuncSetAttribute(rec_mma, cudaFuncAttributeMaxDynamicSharedMemorySize, REC_SMEM);

    prep_kernel<<<256, 256>>>(Wh_f0, Wh_b0, Wh_f1, Wh_b1,
                              Wx_f0, Wx_b0, Wx_f1, Wx_b1,
                              bb_f0, bb_b0, bb_f1, bb_b1);
    static_kernel<<<(BATCH + 255) / 256, 256>>>(x_static, w_s0, b_s0, w_s1, b_s1);

    dim3 ggrid(MTOT / 64, 8);
    xpre_gemm_mma<<<ggrid, 256>>>(x_dyn, FDYN, 0, seq);
    rec_mma<<<128, 512, REC_SMEM>>>(seq, 0);
    xpre_gemm_mma<<<ggrid, 256>>>(nullptr, 256, 1, seq);
    rec_mma<<<128, 512, REC_SMEM>>>(seq, 1);
    att_kernel<<<BATCH, 256>>>(w_att, b_att);
    head_kernel<<<BATCH, 64>>>(w_c1, b_c1, w_c2, b_c2, out);
}

// round 9
// speedup vs baseline: 8.1088x; 1.0015x over previous
#include <cuda_runtime.h>
#include <cuda_fp16.h>
#include <cstdint>
#include <math.h>

// Problem constants
#define BATCH 1024
#define TT    169
#define FDYN  36
#define FSTAT 19
#define HID   128
#define MTOT  (BATCH * TT)

// ---------------------------------------------------------------------------
// Scratch (device globals)
// ---------------------------------------------------------------------------
__device__ __half g_xpre16[(size_t)MTOT * 1024];
__device__ __half g_cur0h[(size_t)MTOT * 256];
__device__ float  g_cur1[(size_t)MTOT * 256];
__device__ float  g_sbuf[BATCH * 16];
__device__ float  g_attb[BATCH * 256];
__device__ __half g_wh16[4 * 128 * 512];
__device__ __half g_wx0[36 * 1024];
__device__ __half g_wx1[256 * 1024];
__device__ float  g_bx0[1024];
__device__ float  g_bx1[1024];

// ---------------------------------------------------------------------------
// MMA / ldmatrix / fast-math helpers
// ---------------------------------------------------------------------------
__device__ __forceinline__ unsigned smem_u32(const void* p) {
    return (unsigned)__cvta_generic_to_shared(p);
}
__device__ __forceinline__ void ldsm_x4(unsigned& r0, unsigned& r1, unsigned& r2, unsigned& r3, unsigned a) {
    asm volatile("ldmatrix.sync.aligned.m8n8.x4.shared.b16 {%0,%1,%2,%3}, [%4];"
                 : "=r"(r0), "=r"(r1), "=r"(r2), "=r"(r3) : "r"(a));
}
__device__ __forceinline__ void ldsm_x4_t(unsigned& r0, unsigned& r1, unsigned& r2, unsigned& r3, unsigned a) {
    asm volatile("ldmatrix.sync.aligned.m8n8.x4.trans.shared.b16 {%0,%1,%2,%3}, [%4];"
                 : "=r"(r0), "=r"(r1), "=r"(r2), "=r"(r3) : "r"(a));
}
__device__ __forceinline__ void mma16816(float* c, unsigned a0, unsigned a1, unsigned a2, unsigned a3,
                                         unsigned b0, unsigned b1) {
    asm volatile("mma.sync.aligned.m16n8k16.row.col.f32.f16.f16.f32 "
                 "{%0,%1,%2,%3}, {%4,%5,%6,%7}, {%8,%9}, {%0,%1,%2,%3};"
                 : "+f"(c[0]), "+f"(c[1]), "+f"(c[2]), "+f"(c[3])
                 : "r"(a0), "r"(a1), "r"(a2), "r"(a3), "r"(b0), "r"(b1));
}
__device__ __forceinline__ float fast_ex2(float x) {
    float r; asm("ex2.approx.f32 %0, %1;" : "=f"(r) : "f"(x)); return r;
}
__device__ __forceinline__ float fast_rcp(float x) {
    float r; asm("rcp.approx.f32 %0, %1;" : "=f"(r) : "f"(x)); return r;
}
__device__ __forceinline__ float sigmoid_fast(float x) {
    // 1/(1+e^-x) = rcp(1 + 2^(-x*log2e))
    return fast_rcp(1.f + fast_ex2(-1.44269504f * x));
}
__device__ __forceinline__ float tanh_fast(float x) {
    // tanh(x) = 1 - 2/(1+e^{2x});  e^{2x} = 2^(2x*log2e)
    float e = fast_ex2(2.88539008f * x);
    return 1.f - 2.f * fast_rcp(1.f + e);
}

// ---------------------------------------------------------------------------
// Weight conversion to fp16 (once per launch)
// ---------------------------------------------------------------------------
__global__ __launch_bounds__(256) void prep_kernel(
    const float* __restrict__ Wh_f0, const float* __restrict__ Wh_b0,
    const float* __restrict__ Wh_f1, const float* __restrict__ Wh_b1,
    const float* __restrict__ Wx_f0, const float* __restrict__ Wx_b0,
    const float* __restrict__ Wx_f1, const float* __restrict__ Wx_b1,
    const float* __restrict__ bb_f0, const float* __restrict__ bb_b0,
    const float* __restrict__ bb_f1, const float* __restrict__ bb_b1)
{
    const int N_WH = 4 * 65536;
    const int N_W0 = 36 * 1024;
    const int N_W1 = 256 * 1024;
    const int N_ALL = N_WH + N_W0 + N_W1 + 2048;
    for (int idx = blockIdx.x * 256 + threadIdx.x; idx < N_ALL; idx += gridDim.x * 256) {
        if (idx < N_WH) {
            int which = idx >> 16;
            int off = idx & 65535;
            const float* src = (which == 0) ? Wh_f0 : (which == 1) ? Wh_b0 : (which == 2) ? Wh_f1 : Wh_b1;
            g_wh16[idx] = __float2half(src[off]);
        } else if (idx < N_WH + N_W0) {
            int j = idx - N_WH;
            int k = j >> 10;
            int n = j & 1023;
            float v = (n < 512) ? Wx_f0[k * 512 + n] : Wx_b0[k * 512 + (n - 512)];
            g_wx0[j] = __float2half(v);
        } else if (idx < N_WH + N_W0 + N_W1) {
            int j = idx - N_WH - N_W0;
            int k = j >> 10;
            int n = j & 1023;
            float v = (n < 512) ? Wx_f1[k * 512 + n] : Wx_b1[k * 512 + (n - 512)];
            g_wx1[j] = __float2half(v);
        } else {
            int j = idx - N_WH - N_W0 - N_W1;
            int n = j & 1023;
            if (j < 1024) { g_bx0[n] = (n < 512) ? bb_f0[n] : bb_b0[n - 512]; }
            else          { g_bx1[n] = (n < 512) ? bb_f1[n] : bb_b1[n - 512]; }
        }
    }
}

// ---------------------------------------------------------------------------
// Static branch -> g_sbuf
// ---------------------------------------------------------------------------
__global__ __launch_bounds__(256) void static_kernel(
    const float* __restrict__ x, const float* __restrict__ w0, const float* __restrict__ b0,
    const float* __restrict__ w1, const float* __restrict__ b1)
{
    int b = blockIdx.x * blockDim.x + threadIdx.x;
    if (b >= BATCH) return;
    float xin[FSTAT];
#pragma unroll
    for (int i = 0; i < FSTAT; ++i) xin[i] = x[b * FSTAT + i];
    float h0[16];
#pragma unroll
    for (int j = 0; j < 16; ++j) {
        float a = b0[j];
#pragma unroll
        for (int i = 0; i < FSTAT; ++i) a += xin[i] * w0[i * 16 + j];
        h0[j] = fmaxf(a, 0.f);
    }
#pragma unroll
    for (int j = 0; j < 16; ++j) {
        float a = b1[j];
#pragma unroll
        for (int i = 0; i < 16; ++i) a += h0[i] * w1[i * 16 + j];
        g_sbuf[b * 16 + j] = fmaxf(a, 0.f);
    }
}

// ---------------------------------------------------------------------------
// Input-projection GEMM via mma -> g_xpre16.
// layer==0: A = x_dyn (float, K=36). layer==1: A = g_cur0h (half, K=256).
// ---------------------------------------------------------------------------
__global__ __launch_bounds__(256) void xpre_gemm_mma(
    const float* __restrict__ Afloat, int K, int layer,
    const int* __restrict__ seq_len)
{
    __shared__ __half A_sm[64 * 40];
    __shared__ __half B_sm[32 * 136];

    const int m0 = blockIdx.x * 64;
    const int nb = blockIdx.y * 128;
    const int tid = threadIdx.x;

    int act = 0;
    if (tid < 64) {
        int m = m0 + tid;
        int bi = m / TT;
        int t = m - bi * TT;
        act = (t < seq_len[bi]) ? 1 : 0;
    }
    if (!__syncthreads_or(act)) return;

    const __half* Bw = (layer == 0) ? g_wx0 : g_wx1;
    const float* bias = (layer == 0) ? g_bx0 : g_bx1;

    const int warp = tid >> 5;
    const int lane = tid & 31;
    const int wy = warp >> 1;
    const int wx = warp & 1;

    float c[8][4];
#pragma unroll
    for (int i = 0; i < 8; ++i) {
#pragma unroll
        for (int j = 0; j < 4; ++j) c[i][j] = 0.f;
    }

    for (int k0 = 0; k0 < K; k0 += 32) {
        if (layer == 1) {
            // vectorized A load: 64 rows x 32 halves, each thread one uint4 (8 halves)
            int row = tid >> 2;
            int colc = (tid & 3) * 8;
            uint4 v = *(const uint4*)&g_cur0h[(size_t)(m0 + row) * 256 + k0 + colc];
            *(uint4*)&A_sm[row * 40 + colc] = v;
        } else {
#pragma unroll
            for (int j = 0; j < 8; ++j) {
                int i = tid + j * 256;
                int row = i >> 5;
                int col = i & 31;
                int k = k0 + col;
                __half hv = __float2half(0.f);
                if (k < K) hv = __float2half(Afloat[(size_t)(m0 + row) * K + k]);
                A_sm[row * 40 + col] = hv;
            }
        }
#pragma unroll
        for (int j = 0; j < 2; ++j) {
            int i = tid + j * 256;
            int row = i >> 4;
            int c8 = i & 15;
            int k = k0 + row;
            uint4 v = make_uint4(0u, 0u, 0u, 0u);
            if (k < K) v = *(const uint4*)&Bw[(size_t)k * 1024 + nb + c8 * 8];
            *(uint4*)&B_sm[row * 136 + c8 * 8] = v;
        }
        __syncthreads();

#pragma unroll
        for (int kk = 0; kk < 2; ++kk) {
            unsigned a0, a1, a2, a3;
            unsigned aaddr = smem_u32(&A_sm[(wy * 16 + (lane & 15)) * 40 + kk * 16 + (lane >> 4) * 8]);
            ldsm_x4(a0, a1, a2, a3, aaddr);
#pragma unroll
            for (int np = 0; np < 4; ++np) {
                unsigned q0, q1, q2, q3;
                unsigned baddr = smem_u32(&B_sm[(kk * 16 + (lane & 15)) * 136 + wx * 64 + np * 16 + (lane >> 4) * 8]);
                ldsm_x4_t(q0, q1, q2, q3, baddr);
                mma16816(c[np * 2],     a0, a1, a2, a3, q0, q1);
                mma16816(c[np * 2 + 1], a0, a1, a2, a3, q2, q3);
            }
        }
        __syncthreads();
    }

    const int r = lane >> 2;
    const int cb = (lane & 3) * 2;
#pragma unroll
    for (int nt = 0; nt < 8; ++nt) {
        int gn = nb + wx * 64 + nt * 8 + cb;
        float bx = bias[gn];
        float by = bias[gn + 1];
        int m1 = m0 + wy * 16 + r;
        int m2 = m1 + 8;
        __half2 lo = __floats2half2_rn(c[nt][0] + bx, c[nt][1] + by);
        __half2 hi = __floats2half2_rn(c[nt][2] + bx, c[nt][3] + by);
        *(__half2*)&g_xpre16[(size_t)m1 * 1024 + gn] = lo;
        *(__half2*)&g_xpre16[(size_t)m2 * 1024 + gn] = hi;
    }
}

// ---------------------------------------------------------------------------
// Persistent recurrent kernel v2.
// 512 threads (16 warps), 128 blocks (0..63 fw, 64..127 bw), 16 batch rows.
// Wh held in per-thread register fragments (loaded once via ldmatrix).
// Per step: phase1 = 8 ldsm(A) + 32 HMMA per warp -> GS; phase2 = cell update
// with ex2/rcp-based activations; xpre prefetched before phase1.
// Dyn smem: WH[128][520]h (init staging) | HS[16][136]h | GS[16][520]f | LS
// ---------------------------------------------------------------------------
#define WH_STRIDE 520
#define HS_STRIDE 136
#define GS_STRIDE 520
#define SM_HS_OFF 133120
#define SM_GS_OFF 137472
#define SM_LS_OFF 170752
#define REC_SMEM  170880

__global__ __launch_bounds__(512) void rec_mma(const int* __restrict__ seq_len, int layer)
{
    extern __shared__ char smraw[];
    __half* WH = (__half*)(smraw);
    __half* HS = (__half*)(smraw + SM_HS_OFF);
    float*  GS = (float*)(smraw + SM_GS_OFF);
    int*    LS = (int*)(smraw + SM_LS_OFF);

    const int blk = blockIdx.x;
    const int dir = blk >> 6;
    const int b0 = (blk & 63) * 16;
    const int xoff = dir * 512;
    const int ooff = dir * 128;
    const int tid = threadIdx.x;

    // stage Wh into smem once
    const __half* wg = g_wh16 + (size_t)(layer * 2 + dir) * 65536;
#pragma unroll 4
    for (int i = tid; i < 8192; i += 512) {
        int r = i >> 6;
        int c8 = i & 63;
        *(uint4*)&WH[r * WH_STRIDE + c8 * 8] = ((const uint4*)wg)[i];
    }
    for (int i = tid; i < (16 * HS_STRIDE) / 2; i += 512) ((unsigned*)HS)[i] = 0u;
    if (tid < 16) LS[tid] = seq_len[b0 + tid];
    __syncthreads();
    if (tid == 0) {
        int m = 0;
#pragma unroll
        for (int i = 0; i < 16; ++i) m = max(m, LS[i]);
        LS[16] = m;
    }
    __syncthreads();
    const int Lmax = LS[16];

    const int warp = tid >> 5;
    const int lane = tid & 31;
    const int n_base = warp * 32;          // warp owns 32 N-cols
    const int arow = lane & 15;
    const int acol8 = (lane >> 4) * 8;

    // load Wh B-fragments into registers (once)
    unsigned bfr[8][8];
#pragma unroll
    for (int kk = 0; kk < 8; ++kk) {
#pragma unroll
        for (int nt2 = 0; nt2 < 2; ++nt2) {
            unsigned baddr = smem_u32(&WH[(kk * 16 + arow) * WH_STRIDE + n_base + nt2 * 16 + acol8]);
            ldsm_x4_t(bfr[kk][nt2 * 4 + 0], bfr[kk][nt2 * 4 + 1],
                      bfr[kk][nt2 * 4 + 2], bfr[kk][nt2 * 4 + 3], baddr);
        }
    }

    // phase2 mapping: warp == batch row, lane*4 == hidden slice
    const int r2 = warp;
    const int h2 = lane * 4;
    const int L = LS[r2];
    const size_t bR = (size_t)(b0 + r2);

    float c_reg[4] = {0.f, 0.f, 0.f, 0.f};

    for (int step = 0; step < TT; ++step) {
        // prefetch xpre for this step (consumed in phase2, after the MMA block)
        const bool active = (step < L);
        const int in_idx = active ? (dir ? (L - 1 - step) : step) : 0;
        uint2 vi, vj, vf, vo;
        if (active) {
            const __half* xp = g_xpre16 + (bR * TT + in_idx) * 1024 + xoff + h2;
            vi = *(const uint2*)(xp);
            vj = *(const uint2*)(xp + 128);
            vf = *(const uint2*)(xp + 256);
            vo = *(const uint2*)(xp + 384);
        }

        if (step < Lmax) {
            float c[4][4];
#pragma unroll
            for (int i = 0; i < 4; ++i) {
#pragma unroll
                for (int j = 0; j < 4; ++j) c[i][j] = 0.f;
            }
#pragma unroll
            for (int kk = 0; kk < 8; ++kk) {
                unsigned a0, a1, a2, a3;
                unsigned aaddr = smem_u32(&HS[arow * HS_STRIDE + kk * 16 + acol8]);
                ldsm_x4(a0, a1, a2, a3, aaddr);
                mma16816(c[0], a0, a1, a2, a3, bfr[kk][0], bfr[kk][1]);
                mma16816(c[1], a0, a1, a2, a3, bfr[kk][2], bfr[kk][3]);
                mma16816(c[2], a0, a1, a2, a3, bfr[kk][4], bfr[kk][5]);
                mma16816(c[3], a0, a1, a2, a3, bfr[kk][6], bfr[kk][7]);
            }
            const int rr = lane >> 2;
            const int cb = (lane & 3) * 2;
#pragma unroll
            for (int nt = 0; nt < 4; ++nt) {
                int n = n_base + nt * 8 + cb;
                *(float2*)&GS[rr * GS_STRIDE + n]       = make_float2(c[nt][0], c[nt][1]);
                *(float2*)&GS[(rr + 8) * GS_STRIDE + n] = make_float2(c[nt][2], c[nt][3]);
            }
        }
        __syncthreads();

        float hv[4];
        int pos;
        if (active) {
            pos = in_idx;
            const __half* pi = (const __half*)&vi;
            const __half* pj = (const __half*)&vj;
            const __half* pf = (const __half*)&vf;
            const __half* po = (const __half*)&vo;
            const float* gsr = &GS[r2 * GS_STRIDE];
#pragma unroll
            for (int u = 0; u < 4; ++u) {
                float gi = __half2float(pi[u]) + gsr[h2 + u];
                float gj = __half2float(pj[u]) + gsr[128 + h2 + u];
                float gf = __half2float(pf[u]) + gsr[256 + h2 + u];
                float go = __half2float(po[u]) + gsr[384 + h2 + u];
                float ig = sigmoid_fast(gi);
                float fg = sigmoid_fast(gf + 1.f);
                float og = sigmoid_fast(go);
                float jg = tanh_fast(gj);
                float cn = c_reg[u] * fg + ig * jg;
                c_reg[u] = cn;
                hv[u] = tanh_fast(cn) * og;
            }
        } else {
            pos = step;
#pragma unroll
            for (int u = 0; u < 4; ++u) hv[u] = 0.f;
        }

        if (layer == 0) {
            __half hb[4];
#pragma unroll
            for (int u = 0; u < 4; ++u) hb[u] = __float2half(hv[u]);
            *(uint2*)&g_cur0h[(bR * TT + pos) * 256 + ooff + h2] = *(uint2*)hb;
        } else {
            *(float4*)&g_cur1[(bR * TT + pos) * 256 + ooff + h2] =
                make_float4(hv[0], hv[1], hv[2], hv[3]);
        }
        if (active) {
            __half hb2[4];
#pragma unroll
            for (int u = 0; u < 4; ++u) hb2[u] = __float2half(hv[u]);
            *(uint2*)&HS[r2 * HS_STRIDE + h2] = *(uint2*)hb2;
        }
        __syncthreads();
    }
}

// ---------------------------------------------------------------------------
// Attention pooling: g_cur1 -> g_attb
// ---------------------------------------------------------------------------
__global__ __launch_bounds__(256) void att_kernel(
    const float* __restrict__ w_att, const float* __restrict__ b_att)
{
    const int b = blockIdx.x;
    const int tid = threadIdx.x;
    __shared__ float wv[256];
    __shared__ float e_sm[176];
    __shared__ float red[40];
    wv[tid] = w_att[tid];
    __syncthreads();

    const int warp = tid >> 5;
    const int lane = tid & 31;
    for (int t = warp; t < TT; t += 8) {
        const float* p = &g_cur1[((size_t)b * TT + t) * 256];
        float s = 0.f;
#pragma unroll
        for (int j = 0; j < 8; ++j) s += p[lane + 32 * j] * wv[lane + 32 * j];
#pragma unroll
        for (int off = 16; off > 0; off >>= 1) s += __shfl_down_sync(0xffffffffu, s, off);
        if (lane == 0) e_sm[t] = tanhf(s + b_att[0]);
    }
    __syncthreads();

    float m = -1e30f;
    for (int t = tid; t < TT; t += 256) m = fmaxf(m, e_sm[t]);
#pragma unroll
    for (int off = 16; off > 0; off >>= 1) m = fmaxf(m, __shfl_xor_sync(0xffffffffu, m, off));
    if (lane == 0) red[warp] = m;
    __syncthreads();
    if (tid == 0) {
        float mm = red[0];
        for (int w = 1; w < 8; ++w) mm = fmaxf(mm, red[w]);
        red[32] = mm;
    }
    __syncthreads();
    const float mx = red[32];

    float ssum = 0.f;
    for (int t = tid; t < TT; t += 256) {
        float p = expf(e_sm[t] - mx);
        e_sm[t] = p;
        ssum += p;
    }
#pragma unroll
    for (int off = 16; off > 0; off >>= 1) ssum += __shfl_xor_sync(0xffffffffu, ssum, off);
    if (lane == 0) red[warp] = ssum;
    __syncthreads();
    if (tid == 0) {
        float s2 = 0.f;
        for (int w = 0; w < 8; ++w) s2 += red[w];
        red[33] = s2;
    }
    __syncthreads();
    const float inv = 1.f / red[33];

    float acc0 = 0.f, acc1 = 0.f;
    const float* base = &g_cur1[(size_t)b * TT * 256 + tid];
    for (int t = 0; t < TT - 1; t += 2) {
        acc0 += e_sm[t]     * base[(size_t)t * 256];
        acc1 += e_sm[t + 1] * base[(size_t)(t + 1) * 256];
    }
    acc0 += e_sm[TT - 1] * base[(size_t)(TT - 1) * 256];
    g_attb[b * 256 + tid] = (acc0 + acc1) * inv;
}

// ---------------------------------------------------------------------------
// Classifier head: [g_sbuf, g_attb] -> out
// ---------------------------------------------------------------------------
__global__ __launch_bounds__(64) void head_kernel(
    const float* __restrict__ w1, const float* __restrict__ b1,
    const float* __restrict__ w2, const float* __restrict__ b2,
    float* __restrict__ out)
{
    const int b = blockIdx.x;
    const int tid = threadIdx.x;
    __shared__ float cat[272];
    __shared__ float h1[64];
    if (tid < 16) cat[tid] = g_sbuf[b * 16 + tid];
    for (int j = tid; j < 256; j += 64) cat[16 + j] = g_attb[b * 256 + j];
    __syncthreads();
    float a = b1[tid];
#pragma unroll 4
    for (int k = 0; k < 272; ++k) a += cat[k] * w1[k * 64 + tid];
    h1[tid] = fmaxf(a, 0.f);
    __syncthreads();
    if (tid < 32) {
        float a2 = b2[tid];
#pragma unroll
        for (int k = 0; k < 64; ++k) a2 += h1[k] * w2[k * 32 + tid];
        out[b * 32 + tid] = fmaxf(a2, 0.f);
    }
}

// ---------------------------------------------------------------------------
// Launch
// ---------------------------------------------------------------------------
extern "C" void kernel_launch(void* const* d_in, const int* in_sizes, int n_in,
                              void* d_out, int out_size)
{
    const float* x_static = (const float*)d_in[0];
    const float* x_dyn    = (const float*)d_in[1];
    const int*   seq      = (const int*)  d_in[2];
    const float* w_s0  = (const float*)d_in[3];
    const float* b_s0  = (const float*)d_in[4];
    const float* w_s1  = (const float*)d_in[5];
    const float* b_s1  = (const float*)d_in[6];
    const float* Wx_f0 = (const float*)d_in[7];
    const float* Wh_f0 = (const float*)d_in[8];
    const float* bb_f0 = (const float*)d_in[9];
    const float* Wx_b0 = (const float*)d_in[10];
    const float* Wh_b0 = (const float*)d_in[11];
    const float* bb_b0 = (const float*)d_in[12];
    const float* Wx_f1 = (const float*)d_in[13];
    const float* Wh_f1 = (const float*)d_in[14];
    const float* bb_f1 = (const float*)d_in[15];
    const float* Wx_b1 = (const float*)d_in[16];
    const float* Wh_b1 = (const float*)d_in[17];
    const float* bb_b1 = (const float*)d_in[18];
    const float* w_att = (const float*)d_in[19];
    const float* b_att = (const float*)d_in[20];
    const float* w_c1  = (const float*)d_in[21];
    const float* b_c1  = (const float*)d_in[22];
    const float* w_c2  = (const float*)d_in[23];
    const float* b_c2  = (const float*)d_in[24];
    float* out = (float*)d_out;

    cudaFuncSetAttribute(rec_mma, cudaFuncAttributeMaxDynamicSharedMemorySize, REC_SMEM);

    prep_kernel<<<256, 256>>>(Wh_f0, Wh_b0, Wh_f1, Wh_b1,
                              Wx_f0, Wx_b0, Wx_f1, Wx_b1,
                              bb_f0, bb_b0, bb_f1, bb_b1);
    static_kernel<<<(BATCH + 255) / 256, 256>>>(x_static, w_s0, b_s0, w_s1, b_s1);

    dim3 ggrid(MTOT / 64, 8);
    xpre_gemm_mma<<<ggrid, 256>>>(x_dyn, FDYN, 0, seq);
    rec_mma<<<128, 512, REC_SMEM>>>(seq, 0);
    xpre_gemm_mma<<<ggrid, 256>>>(nullptr, 256, 1, seq);
    rec_mma<<<128, 512, REC_SMEM>>>(seq, 1);
    att_kernel<<<BATCH, 256>>>(w_att, b_att);
    head_kernel<<<BATCH, 64>>>(w_c1, b_c1, w_c2, b_c2, out);
}

// round 10
// speedup vs baseline: 8.1199x; 1.0014x over previous
#include <cuda_runtime.h>
#include <cuda_fp16.h>
#include <cstdint>
#include <math.h>

// Problem constants
#define BATCH 1024
#define TT    169
#define FDYN  36
#define FSTAT 19
#define HID   128
#define MTOT  (BATCH * TT)

// ---------------------------------------------------------------------------
// Scratch (device globals)
// ---------------------------------------------------------------------------
__device__ __half g_xpre16[(size_t)MTOT * 1024];
__device__ __half g_cur0h[(size_t)MTOT * 256];
__device__ float  g_cur1[(size_t)MTOT * 256];
__device__ float  g_sbuf[BATCH * 16];
__device__ float  g_attb[BATCH * 256];
__device__ __half g_wh16[4 * 128 * 512];
__device__ __half g_wx0[36 * 1024];
__device__ __half g_wx1[256 * 1024];
__device__ float  g_bx0[1024];
__device__ float  g_bx1[1024];

// ---------------------------------------------------------------------------
// MMA / ldmatrix / fast-math helpers
// ---------------------------------------------------------------------------
__device__ __forceinline__ unsigned smem_u32(const void* p) {
    return (unsigned)__cvta_generic_to_shared(p);
}
__device__ __forceinline__ void ldsm_x4(unsigned& r0, unsigned& r1, unsigned& r2, unsigned& r3, unsigned a) {
    asm volatile("ldmatrix.sync.aligned.m8n8.x4.shared.b16 {%0,%1,%2,%3}, [%4];"
                 : "=r"(r0), "=r"(r1), "=r"(r2), "=r"(r3) : "r"(a));
}
__device__ __forceinline__ void ldsm_x4_t(unsigned& r0, unsigned& r1, unsigned& r2, unsigned& r3, unsigned a) {
    asm volatile("ldmatrix.sync.aligned.m8n8.x4.trans.shared.b16 {%0,%1,%2,%3}, [%4];"
                 : "=r"(r0), "=r"(r1), "=r"(r2), "=r"(r3) : "r"(a));
}
__device__ __forceinline__ void mma16816(float* c, unsigned a0, unsigned a1, unsigned a2, unsigned a3,
                                         unsigned b0, unsigned b1) {
    asm volatile("mma.sync.aligned.m16n8k16.row.col.f32.f16.f16.f32 "
                 "{%0,%1,%2,%3}, {%4,%5,%6,%7}, {%8,%9}, {%0,%1,%2,%3};"
                 : "+f"(c[0]), "+f"(c[1]), "+f"(c[2]), "+f"(c[3])
                 : "r"(a0), "r"(a1), "r"(a2), "r"(a3), "r"(b0), "r"(b1));
}
__device__ __forceinline__ float fast_ex2(float x) {
    float r; asm("ex2.approx.f32 %0, %1;" : "=f"(r) : "f"(x)); return r;
}
__device__ __forceinline__ float fast_rcp(float x) {
    float r; asm("rcp.approx.f32 %0, %1;" : "=f"(r) : "f"(x)); return r;
}
__device__ __forceinline__ float sigmoid_fast(float x) {
    // 1/(1+e^-x) = rcp(1 + 2^(-x*log2e))
    return fast_rcp(1.f + fast_ex2(-1.44269504f * x));
}
__device__ __forceinline__ float tanh_fast(float x) {
    // tanh(x) = 1 - 2/(1+e^{2x});  e^{2x} = 2^(2x*log2e)
    float e = fast_ex2(2.88539008f * x);
    return 1.f - 2.f * fast_rcp(1.f + e);
}

// ---------------------------------------------------------------------------
// Weight conversion to fp16 (once per launch)
// ---------------------------------------------------------------------------
__global__ __launch_bounds__(256) void prep_kernel(
    const float* __restrict__ Wh_f0, const float* __restrict__ Wh_b0,
    const float* __restrict__ Wh_f1, const float* __restrict__ Wh_b1,
    const float* __restrict__ Wx_f0, const float* __restrict__ Wx_b0,
    const float* __restrict__ Wx_f1, const float* __restrict__ Wx_b1,
    const float* __restrict__ bb_f0, const float* __restrict__ bb_b0,
    const float* __restrict__ bb_f1, const float* __restrict__ bb_b1)
{
    const int N_WH = 4 * 65536;
    const int N_W0 = 36 * 1024;
    const int N_W1 = 256 * 1024;
    const int N_ALL = N_WH + N_W0 + N_W1 + 2048;
    for (int idx = blockIdx.x * 256 + threadIdx.x; idx < N_ALL; idx += gridDim.x * 256) {
        if (idx < N_WH) {
            int which = idx >> 16;
            int off = idx & 65535;
            const float* src = (which == 0) ? Wh_f0 : (which == 1) ? Wh_b0 : (which == 2) ? Wh_f1 : Wh_b1;
            g_wh16[idx] = __float2half(src[off]);
        } else if (idx < N_WH + N_W0) {
            int j = idx - N_WH;
            int k = j >> 10;
            int n = j & 1023;
            float v = (n < 512) ? Wx_f0[k * 512 + n] : Wx_b0[k * 512 + (n - 512)];
            g_wx0[j] = __float2half(v);
        } else if (idx < N_WH + N_W0 + N_W1) {
            int j = idx - N_WH - N_W0;
            int k = j >> 10;
            int n = j & 1023;
            float v = (n < 512) ? Wx_f1[k * 512 + n] : Wx_b1[k * 512 + (n - 512)];
            g_wx1[j] = __float2half(v);
        } else {
            int j = idx - N_WH - N_W0 - N_W1;
            int n = j & 1023;
            if (j < 1024) { g_bx0[n] = (n < 512) ? bb_f0[n] : bb_b0[n - 512]; }
            else          { g_bx1[n] = (n < 512) ? bb_f1[n] : bb_b1[n - 512]; }
        }
    }
}

// ---------------------------------------------------------------------------
// Static branch -> g_sbuf
// ---------------------------------------------------------------------------
__global__ __launch_bounds__(256) void static_kernel(
    const float* __restrict__ x, const float* __restrict__ w0, const float* __restrict__ b0,
    const float* __restrict__ w1, const float* __restrict__ b1)
{
    int b = blockIdx.x * blockDim.x + threadIdx.x;
    if (b >= BATCH) return;
    float xin[FSTAT];
#pragma unroll
    for (int i = 0; i < FSTAT; ++i) xin[i] = x[b * FSTAT + i];
    float h0[16];
#pragma unroll
    for (int j = 0; j < 16; ++j) {
        float a = b0[j];
#pragma unroll
        for (int i = 0; i < FSTAT; ++i) a += xin[i] * w0[i * 16 + j];
        h0[j] = fmaxf(a, 0.f);
    }
#pragma unroll
    for (int j = 0; j < 16; ++j) {
        float a = b1[j];
#pragma unroll
        for (int i = 0; i < 16; ++i) a += h0[i] * w1[i * 16 + j];
        g_sbuf[b * 16 + j] = fmaxf(a, 0.f);
    }
}

// ---------------------------------------------------------------------------
// Input-projection GEMM via mma -> g_xpre16.
// layer==0: A = x_dyn (float, K=36). layer==1: A = g_cur0h (half, K=256).
// ---------------------------------------------------------------------------
__global__ __launch_bounds__(256) void xpre_gemm_mma(
    const float* __restrict__ Afloat, int K, int layer,
    const int* __restrict__ seq_len)
{
    __shared__ __half A_sm[64 * 40];
    __shared__ __half B_sm[32 * 136];

    const int m0 = blockIdx.x * 64;
    const int nb = blockIdx.y * 128;
    const int tid = threadIdx.x;

    int act = 0;
    if (tid < 64) {
        int m = m0 + tid;
        int bi = m / TT;
        int t = m - bi * TT;
        act = (t < seq_len[bi]) ? 1 : 0;
    }
    if (!__syncthreads_or(act)) return;

    const __half* Bw = (layer == 0) ? g_wx0 : g_wx1;
    const float* bias = (layer == 0) ? g_bx0 : g_bx1;

    const int warp = tid >> 5;
    const int lane = tid & 31;
    const int wy = warp >> 1;
    const int wx = warp & 1;

    float c[8][4];
#pragma unroll
    for (int i = 0; i < 8; ++i) {
#pragma unroll
        for (int j = 0; j < 4; ++j) c[i][j] = 0.f;
    }

    for (int k0 = 0; k0 < K; k0 += 32) {
        if (layer == 1) {
            // vectorized A load: 64 rows x 32 halves, each thread one uint4 (8 halves)
            int row = tid >> 2;
            int colc = (tid & 3) * 8;
            uint4 v = *(const uint4*)&g_cur0h[(size_t)(m0 + row) * 256 + k0 + colc];
            *(uint4*)&A_sm[row * 40 + colc] = v;
        } else {
#pragma unroll
            for (int j = 0; j < 8; ++j) {
                int i = tid + j * 256;
                int row = i >> 5;
                int col = i & 31;
                int k = k0 + col;
                __half hv = __float2half(0.f);
                if (k < K) hv = __float2half(Afloat[(size_t)(m0 + row) * K + k]);
                A_sm[row * 40 + col] = hv;
            }
        }
#pragma unroll
        for (int j = 0; j < 2; ++j) {
            int i = tid + j * 256;
            int row = i >> 4;
            int c8 = i & 15;
            int k = k0 + row;
            uint4 v = make_uint4(0u, 0u, 0u, 0u);
            if (k < K) v = *(const uint4*)&Bw[(size_t)k * 1024 + nb + c8 * 8];
            *(uint4*)&B_sm[row * 136 + c8 * 8] = v;
        }
        __syncthreads();

#pragma unroll
        for (int kk = 0; kk < 2; ++kk) {
            unsigned a0, a1, a2, a3;
            unsigned aaddr = smem_u32(&A_sm[(wy * 16 + (lane & 15)) * 40 + kk * 16 + (lane >> 4) * 8]);
            ldsm_x4(a0, a1, a2, a3, aaddr);
#pragma unroll
            for (int np = 0; np < 4; ++np) {
                unsigned q0, q1, q2, q3;
                unsigned baddr = smem_u32(&B_sm[(kk * 16 + (lane & 15)) * 136 + wx * 64 + np * 16 + (lane >> 4) * 8]);
                ldsm_x4_t(q0, q1, q2, q3, baddr);
                mma16816(c[np * 2],     a0, a1, a2, a3, q0, q1);
                mma16816(c[np * 2 + 1], a0, a1, a2, a3, q2, q3);
            }
        }
        __syncthreads();
    }

    const int r = lane >> 2;
    const int cb = (lane & 3) * 2;
#pragma unroll
    for (int nt = 0; nt < 8; ++nt) {
        int gn = nb + wx * 64 + nt * 8 + cb;
        float bx = bias[gn];
        float by = bias[gn + 1];
        int m1 = m0 + wy * 16 + r;
        int m2 = m1 + 8;
        __half2 lo = __floats2half2_rn(c[nt][0] + bx, c[nt][1] + by);
        __half2 hi = __floats2half2_rn(c[nt][2] + bx, c[nt][3] + by);
        *(__half2*)&g_xpre16[(size_t)m1 * 1024 + gn] = lo;
        *(__half2*)&g_xpre16[(size_t)m2 * 1024 + gn] = hi;
    }
}

// ---------------------------------------------------------------------------
// Persistent recurrent kernel v2.
// 512 threads (16 warps), 128 blocks (0..63 fw, 64..127 bw), 16 batch rows.
// Wh held in per-thread register fragments (loaded once via ldmatrix).
// Per step: phase1 = 8 ldsm(A) + 32 HMMA per warp -> GS; phase2 = cell update
// with ex2/rcp-based activations; xpre prefetched before phase1.
// Dyn smem: WH[128][520]h (init staging) | HS[16][136]h | GS[16][520]f | LS
// ---------------------------------------------------------------------------
#define WH_STRIDE 520
#define HS_STRIDE 136
#define GS_STRIDE 520
#define SM_HS_OFF 133120
#define SM_GS_OFF 137472
#define SM_LS_OFF 170752
#define REC_SMEM  170880

__global__ __launch_bounds__(512) void rec_mma(const int* __restrict__ seq_len, int layer)
{
    extern __shared__ char smraw[];
    __half* WH = (__half*)(smraw);
    __half* HS = (__half*)(smraw + SM_HS_OFF);
    float*  GS = (float*)(smraw + SM_GS_OFF);
    int*    LS = (int*)(smraw + SM_LS_OFF);

    const int blk = blockIdx.x;
    const int dir = blk >> 6;
    const int b0 = (blk & 63) * 16;
    const int xoff = dir * 512;
    const int ooff = dir * 128;
    const int tid = threadIdx.x;

    // stage Wh into smem once
    const __half* wg = g_wh16 + (size_t)(layer * 2 + dir) * 65536;
#pragma unroll 4
    for (int i = tid; i < 8192; i += 512) {
        int r = i >> 6;
        int c8 = i & 63;
        *(uint4*)&WH[r * WH_STRIDE + c8 * 8] = ((const uint4*)wg)[i];
    }
    for (int i = tid; i < (16 * HS_STRIDE) / 2; i += 512) ((unsigned*)HS)[i] = 0u;
    if (tid < 16) LS[tid] = seq_len[b0 + tid];
    __syncthreads();
    if (tid == 0) {
        int m = 0;
#pragma unroll
        for (int i = 0; i < 16; ++i) m = max(m, LS[i]);
        LS[16] = m;
    }
    __syncthreads();
    const int Lmax = LS[16];

    const int warp = tid >> 5;
    const int lane = tid & 31;
    const int n_base = warp * 32;          // warp owns 32 N-cols
    const int arow = lane & 15;
    const int acol8 = (lane >> 4) * 8;

    // load Wh B-fragments into registers (once)
    unsigned bfr[8][8];
#pragma unroll
    for (int kk = 0; kk < 8; ++kk) {
#pragma unroll
        for (int nt2 = 0; nt2 < 2; ++nt2) {
            unsigned baddr = smem_u32(&WH[(kk * 16 + arow) * WH_STRIDE + n_base + nt2 * 16 + acol8]);
            ldsm_x4_t(bfr[kk][nt2 * 4 + 0], bfr[kk][nt2 * 4 + 1],
                      bfr[kk][nt2 * 4 + 2], bfr[kk][nt2 * 4 + 3], baddr);
        }
    }

    // phase2 mapping: warp == batch row, lane*4 == hidden slice
    const int r2 = warp;
    const int h2 = lane * 4;
    const int L = LS[r2];
    const size_t bR = (size_t)(b0 + r2);

    float c_reg[4] = {0.f, 0.f, 0.f, 0.f};

    for (int step = 0; step < TT; ++step) {
        // prefetch xpre for this step (consumed in phase2, after the MMA block)
        const bool active = (step < L);
        const int in_idx = active ? (dir ? (L - 1 - step) : step) : 0;
        uint2 vi, vj, vf, vo;
        if (active) {
            const __half* xp = g_xpre16 + (bR * TT + in_idx) * 1024 + xoff + h2;
            vi = *(const uint2*)(xp);
            vj = *(const uint2*)(xp + 128);
            vf = *(const uint2*)(xp + 256);
            vo = *(const uint2*)(xp + 384);
        }

        if (step < Lmax) {
            float c[4][4];
#pragma unroll
            for (int i = 0; i < 4; ++i) {
#pragma unroll
                for (int j = 0; j < 4; ++j) c[i][j] = 0.f;
            }
#pragma unroll
            for (int kk = 0; kk < 8; ++kk) {
                unsigned a0, a1, a2, a3;
                unsigned aaddr = smem_u32(&HS[arow * HS_STRIDE + kk * 16 + acol8]);
                ldsm_x4(a0, a1, a2, a3, aaddr);
                mma16816(c[0], a0, a1, a2, a3, bfr[kk][0], bfr[kk][1]);
                mma16816(c[1], a0, a1, a2, a3, bfr[kk][2], bfr[kk][3]);
                mma16816(c[2], a0, a1, a2, a3, bfr[kk][4], bfr[kk][5]);
                mma16816(c[3], a0, a1, a2, a3, bfr[kk][6], bfr[kk][7]);
            }
            const int rr = lane >> 2;
            const int cb = (lane & 3) * 2;
#pragma unroll
            for (int nt = 0; nt < 4; ++nt) {
                int n = n_base + nt * 8 + cb;
                *(float2*)&GS[rr * GS_STRIDE + n]       = make_float2(c[nt][0], c[nt][1]);
                *(float2*)&GS[(rr + 8) * GS_STRIDE + n] = make_float2(c[nt][2], c[nt][3]);
            }
        }
        __syncthreads();

        float hv[4];
        int pos;
        if (active) {
            pos = in_idx;
            const __half* pi = (const __half*)&vi;
            const __half* pj = (const __half*)&vj;
            const __half* pf = (const __half*)&vf;
            const __half* po = (const __half*)&vo;
            const float* gsr = &GS[r2 * GS_STRIDE];
#pragma unroll
            for (int u = 0; u < 4; ++u) {
                float gi = __half2float(pi[u]) + gsr[h2 + u];
                float gj = __half2float(pj[u]) + gsr[128 + h2 + u];
                float gf = __half2float(pf[u]) + gsr[256 + h2 + u];
                float go = __half2float(po[u]) + gsr[384 + h2 + u];
                float ig = sigmoid_fast(gi);
                float fg = sigmoid_fast(gf + 1.f);
                float og = sigmoid_fast(go);
                float jg = tanh_fast(gj);
                float cn = c_reg[u] * fg + ig * jg;
                c_reg[u] = cn;
                hv[u] = tanh_fast(cn) * og;
            }
        } else {
            pos = step;
#pragma unroll
            for (int u = 0; u < 4; ++u) hv[u] = 0.f;
        }

        if (layer == 0) {
            __half hb[4];
#pragma unroll
            for (int u = 0; u < 4; ++u) hb[u] = __float2half(hv[u]);
            *(uint2*)&g_cur0h[(bR * TT + pos) * 256 + ooff + h2] = *(uint2*)hb;
        } else {
            *(float4*)&g_cur1[(bR * TT + pos) * 256 + ooff + h2] =
                make_float4(hv[0], hv[1], hv[2], hv[3]);
        }
        if (active) {
            __half hb2[4];
#pragma unroll
            for (int u = 0; u < 4; ++u) hb2[u] = __float2half(hv[u]);
            *(uint2*)&HS[r2 * HS_STRIDE + h2] = *(uint2*)hb2;
        }
        __syncthreads();
    }
}

// ---------------------------------------------------------------------------
// Attention pooling: g_cur1 -> g_attb
// ---------------------------------------------------------------------------
__global__ __launch_bounds__(256) void att_kernel(
    const float* __restrict__ w_att, const float* __restrict__ b_att)
{
    const int b = blockIdx.x;
    const int tid = threadIdx.x;
    __shared__ float wv[256];
    __shared__ float e_sm[176];
    __shared__ float red[40];
    wv[tid] = w_att[tid];
    __syncthreads();

    const int warp = tid >> 5;
    const int lane = tid & 31;
    for (int t = warp; t < TT; t += 8) {
        const float* p = &g_cur1[((size_t)b * TT + t) * 256];
        float s = 0.f;
#pragma unroll
        for (int j = 0; j < 8; ++j) s += p[lane + 32 * j] * wv[lane + 32 * j];
#pragma unroll
        for (int off = 16; off > 0; off >>= 1) s += __shfl_down_sync(0xffffffffu, s, off);
        if (lane == 0) e_sm[t] = tanhf(s + b_att[0]);
    }
    __syncthreads();

    float m = -1e30f;
    for (int t = tid; t < TT; t += 256) m = fmaxf(m, e_sm[t]);
#pragma unroll
    for (int off = 16; off > 0; off >>= 1) m = fmaxf(m, __shfl_xor_sync(0xffffffffu, m, off));
    if (lane == 0) red[warp] = m;
    __syncthreads();
    if (tid == 0) {
        float mm = red[0];
        for (int w = 1; w < 8; ++w) mm = fmaxf(mm, red[w]);
        red[32] = mm;
    }
    __syncthreads();
    const float mx = red[32];

    float ssum = 0.f;
    for (int t = tid; t < TT; t += 256) {
        float p = expf(e_sm[t] - mx);
        e_sm[t] = p;
        ssum += p;
    }
#pragma unroll
    for (int off = 16; off > 0; off >>= 1) ssum += __shfl_xor_sync(0xffffffffu, ssum, off);
    if (lane == 0) red[warp] = ssum;
    __syncthreads();
    if (tid == 0) {
        float s2 = 0.f;
        for (int w = 0; w < 8; ++w) s2 += red[w];
        red[33] = s2;
    }
    __syncthreads();
    const float inv = 1.f / red[33];

    float acc0 = 0.f, acc1 = 0.f;
    const float* base = &g_cur1[(size_t)b * TT * 256 + tid];
    for (int t = 0; t < TT - 1; t += 2) {
        acc0 += e_sm[t]     * base[(size_t)t * 256];
        acc1 += e_sm[t + 1] * base[(size_t)(t + 1) * 256];
    }
    acc0 += e_sm[TT - 1] * base[(size_t)(TT - 1) * 256];
    g_attb[b * 256 + tid] = (acc0 + acc1) * inv;
}

// ---------------------------------------------------------------------------
// Classifier head: [g_sbuf, g_attb] -> out
// ---------------------------------------------------------------------------
__global__ __launch_bounds__(64) void head_kernel(
    const float* __restrict__ w1, const float* __restrict__ b1,
    const float* __restrict__ w2, const float* __restrict__ b2,
    float* __restrict__ out)
{
    const int b = blockIdx.x;
    const int tid = threadIdx.x;
    __shared__ float cat[272];
    __shared__ float h1[64];
    if (tid < 16) cat[tid] = g_sbuf[b * 16 + tid];
    for (int j = tid; j < 256; j += 64) cat[16 + j] = g_attb[b * 256 + j];
    __syncthreads();
    float a = b1[tid];
#pragma unroll 4
    for (int k = 0; k < 272; ++k) a += cat[k] * w1[k * 64 + tid];
    h1[tid] = fmaxf(a, 0.f);
    __syncthreads();
    if (tid < 32) {
        float a2 = b2[tid];
#pragma unroll
        for (int k = 0; k < 64; ++k) a2 += h1[k] * w2[k * 32 + tid];
        out[b * 32 + tid] = fmaxf(a2, 0.f);
    }
}

// ---------------------------------------------------------------------------
// Launch
// ---------------------------------------------------------------------------
extern "C" void kernel_launch(void* const* d_in, const int* in_sizes, int n_in,
                              void* d_out, int out_size)
{
    const float* x_static = (const float*)d_in[0];
    const float* x_dyn    = (const float*)d_in[1];
    const int*   seq      = (const int*)  d_in[2];
    const float* w_s0  = (const float*)d_in[3];
    const float* b_s0  = (const float*)d_in[4];
    const float* w_s1  = (const float*)d_in[5];
    const float* b_s1  = (const float*)d_in[6];
    const float* Wx_f0 = (const float*)d_in[7];
    const float* Wh_f0 = (const float*)d_in[8];
    const float* bb_f0 = (const float*)d_in[9];
    const float* Wx_b0 = (const float*)d_in[10];
    const float* Wh_b0 = (const float*)d_in[11];
    const float* bb_b0 = (const float*)d_in[12];
    const float* Wx_f1 = (const float*)d_in[13];
    const float* Wh_f1 = (const float*)d_in[14];
    const float* bb_f1 = (const float*)d_in[15];
    const float* Wx_b1 = (const float*)d_in[16];
    const float* Wh_b1 = (const float*)d_in[17];
    const float* bb_b1 = (const float*)d_in[18];
    const float* w_att = (const float*)d_in[19];
    const float* b_att = (const float*)d_in[20];
    const float* w_c1  = (const float*)d_in[21];
    const float* b_c1  = (const float*)d_in[22];
    const float* w_c2  = (const float*)d_in[23];
    const float* b_c2  = (const float*)d_in[24];
    float* out = (float*)d_out;

    cudaFuncSetAttribute(rec_mma, cudaFuncAttributeMaxDynamicSharedMemorySize, REC_SMEM);

    prep_kernel<<<256, 256>>>(Wh_f0, Wh_b0, Wh_f1, Wh_b1,
                              Wx_f0, Wx_b0, Wx_f1, Wx_b1,
                              bb_f0, bb_b0, bb_f1, bb_b1);
    static_kernel<<<(BATCH + 255) / 256, 256>>>(x_static, w_s0, b_s0, w_s1, b_s1);

    dim3 ggrid(MTOT / 64, 8);
    xpre_gemm_mma<<<ggrid, 256>>>(x_dyn, FDYN, 0, seq);
    rec_mma<<<128, 512, REC_SMEM>>>(seq, 0);
    xpre_gemm_mma<<<ggrid, 256>>>(nullptr, 256, 1, seq);
    rec_mma<<<128, 512, REC_SMEM>>>(seq, 1);
    att_kernel<<<BATCH, 256>>>(w_att, b_att);
    head_kernel<<<BATCH, 64>>>(w_c1, b_c1, w_c2, b_c2, out);
}

// round 11
// speedup vs baseline: 8.4083x; 1.0355x over previous
#include <cuda_runtime.h>
#include <cuda_fp16.h>
#include <cstdint>
#include <math.h>

// Problem constants
#define BATCH 1024
#define TT    169
#define FDYN  36
#define FSTAT 19
#define HID   128
#define MTOT  (BATCH * TT)

// ---------------------------------------------------------------------------
// Scratch (device globals)
// ---------------------------------------------------------------------------
__device__ __half g_xpre16[(size_t)MTOT * 1024];
__device__ __half g_cur0h[(size_t)MTOT * 256];
__device__ __half g_cur1h[(size_t)MTOT * 256];
__device__ float  g_sbuf[BATCH * 16];
__device__ float  g_attb[BATCH * 256];
__device__ __half g_wh16[4 * 128 * 512];
__device__ __half g_wx0[36 * 1024];
__device__ __half g_wx1[256 * 1024];
__device__ float  g_bx0[1024];
__device__ float  g_bx1[1024];

// ---------------------------------------------------------------------------
// MMA / ldmatrix / fast-math helpers
// ---------------------------------------------------------------------------
__device__ __forceinline__ unsigned smem_u32(const void* p) {
    return (unsigned)__cvta_generic_to_shared(p);
}
__device__ __forceinline__ void ldsm_x4(unsigned& r0, unsigned& r1, unsigned& r2, unsigned& r3, unsigned a) {
    asm volatile("ldmatrix.sync.aligned.m8n8.x4.shared.b16 {%0,%1,%2,%3}, [%4];"
                 : "=r"(r0), "=r"(r1), "=r"(r2), "=r"(r3) : "r"(a));
}
__device__ __forceinline__ void ldsm_x4_t(unsigned& r0, unsigned& r1, unsigned& r2, unsigned& r3, unsigned a) {
    asm volatile("ldmatrix.sync.aligned.m8n8.x4.trans.shared.b16 {%0,%1,%2,%3}, [%4];"
                 : "=r"(r0), "=r"(r1), "=r"(r2), "=r"(r3) : "r"(a));
}
__device__ __forceinline__ void mma16816(float* c, unsigned a0, unsigned a1, unsigned a2, unsigned a3,
                                         unsigned b0, unsigned b1) {
    asm volatile("mma.sync.aligned.m16n8k16.row.col.f32.f16.f16.f32 "
                 "{%0,%1,%2,%3}, {%4,%5,%6,%7}, {%8,%9}, {%0,%1,%2,%3};"
                 : "+f"(c[0]), "+f"(c[1]), "+f"(c[2]), "+f"(c[3])
                 : "r"(a0), "r"(a1), "r"(a2), "r"(a3), "r"(b0), "r"(b1));
}
__device__ __forceinline__ float tanh_apx(float x) {
    float r; asm("tanh.approx.f32 %0, %1;" : "=f"(r) : "f"(x)); return r;
}
__device__ __forceinline__ float sig_apx(float x) {
    return fmaf(tanh_apx(0.5f * x), 0.5f, 0.5f);
}

// ---------------------------------------------------------------------------
// Weight conversion to fp16 (once per launch)
// ---------------------------------------------------------------------------
__global__ __launch_bounds__(256) void prep_kernel(
    const float* __restrict__ Wh_f0, const float* __restrict__ Wh_b0,
    const float* __restrict__ Wh_f1, const float* __restrict__ Wh_b1,
    const float* __restrict__ Wx_f0, const float* __restrict__ Wx_b0,
    const float* __restrict__ Wx_f1, const float* __restrict__ Wx_b1,
    const float* __restrict__ bb_f0, const float* __restrict__ bb_b0,
    const float* __restrict__ bb_f1, const float* __restrict__ bb_b1)
{
    const int N_WH = 4 * 65536;
    const int N_W0 = 36 * 1024;
    const int N_W1 = 256 * 1024;
    const int N_ALL = N_WH + N_W0 + N_W1 + 2048;
    for (int idx = blockIdx.x * 256 + threadIdx.x; idx < N_ALL; idx += gridDim.x * 256) {
        if (idx < N_WH) {
            int which = idx >> 16;
            int off = idx & 65535;
            const float* src = (which == 0) ? Wh_f0 : (which == 1) ? Wh_b0 : (which == 2) ? Wh_f1 : Wh_b1;
            g_wh16[idx] = __float2half(src[off]);
        } else if (idx < N_WH + N_W0) {
            int j = idx - N_WH;
            int k = j >> 10;
            int n = j & 1023;
            float v = (n < 512) ? Wx_f0[k * 512 + n] : Wx_b0[k * 512 + (n - 512)];
            g_wx0[j] = __float2half(v);
        } else if (idx < N_WH + N_W0 + N_W1) {
            int j = idx - N_WH - N_W0;
            int k = j >> 10;
            int n = j & 1023;
            float v = (n < 512) ? Wx_f1[k * 512 + n] : Wx_b1[k * 512 + (n - 512)];
            g_wx1[j] = __float2half(v);
        } else {
            int j = idx - N_WH - N_W0 - N_W1;
            int n = j & 1023;
            if (j < 1024) { g_bx0[n] = (n < 512) ? bb_f0[n] : bb_b0[n - 512]; }
            else          { g_bx1[n] = (n < 512) ? bb_f1[n] : bb_b1[n - 512]; }
        }
    }
}

// ---------------------------------------------------------------------------
// Static branch -> g_sbuf
// ---------------------------------------------------------------------------
__global__ __launch_bounds__(256) void static_kernel(
    const float* __restrict__ x, const float* __restrict__ w0, const float* __restrict__ b0,
    const float* __restrict__ w1, const float* __restrict__ b1)
{
    int b = blockIdx.x * blockDim.x + threadIdx.x;
    if (b >= BATCH) return;
    float xin[FSTAT];
#pragma unroll
    for (int i = 0; i < FSTAT; ++i) xin[i] = x[b * FSTAT + i];
    float h0[16];
#pragma unroll
    for (int j = 0; j < 16; ++j) {
        float a = b0[j];
#pragma unroll
        for (int i = 0; i < FSTAT; ++i) a += xin[i] * w0[i * 16 + j];
        h0[j] = fmaxf(a, 0.f);
    }
#pragma unroll
    for (int j = 0; j < 16; ++j) {
        float a = b1[j];
#pragma unroll
        for (int i = 0; i < 16; ++i) a += h0[i] * w1[i * 16 + j];
        g_sbuf[b * 16 + j] = fmaxf(a, 0.f);
    }
}

// ---------------------------------------------------------------------------
// Input-projection GEMM via mma -> g_xpre16.
// Grid: (8 N-blocks [x, fastest], 2704 M-tiles [y]) so the 8 N-blocks of one
// M-tile run concurrently and share the A tile through L2.
// layer==0: A = x_dyn (float, K=36). layer==1: A = g_cur0h (half, K=256).
// ---------------------------------------------------------------------------
__global__ __launch_bounds__(256) void xpre_gemm_mma(
    const float* __restrict__ Afloat, int K, int layer,
    const int* __restrict__ seq_len)
{
    __shared__ __half A_sm[64 * 40];
    __shared__ __half B_sm[32 * 136];

    const int m0 = blockIdx.y * 64;
    const int nb = blockIdx.x * 128;
    const int tid = threadIdx.x;

    int act = 0;
    if (tid < 64) {
        int m = m0 + tid;
        int bi = m / TT;
        int t = m - bi * TT;
        act = (t < seq_len[bi]) ? 1 : 0;
    }
    if (!__syncthreads_or(act)) return;

    const __half* Bw = (layer == 0) ? g_wx0 : g_wx1;
    const float* bias = (layer == 0) ? g_bx0 : g_bx1;

    const int warp = tid >> 5;
    const int lane = tid & 31;
    const int wy = warp >> 1;
    const int wx = warp & 1;

    float c[8][4];
#pragma unroll
    for (int i = 0; i < 8; ++i) {
#pragma unroll
        for (int j = 0; j < 4; ++j) c[i][j] = 0.f;
    }

    for (int k0 = 0; k0 < K; k0 += 32) {
        if (layer == 1) {
            int row = tid >> 2;
            int colc = (tid & 3) * 8;
            uint4 v = *(const uint4*)&g_cur0h[(size_t)(m0 + row) * 256 + k0 + colc];
            *(uint4*)&A_sm[row * 40 + colc] = v;
        } else {
#pragma unroll
            for (int j = 0; j < 8; ++j) {
                int i = tid + j * 256;
                int row = i >> 5;
                int col = i & 31;
                int k = k0 + col;
                __half hv = __float2half(0.f);
                if (k < K) hv = __float2half(Afloat[(size_t)(m0 + row) * K + k]);
                A_sm[row * 40 + col] = hv;
            }
        }
#pragma unroll
        for (int j = 0; j < 2; ++j) {
            int i = tid + j * 256;
            int row = i >> 4;
            int c8 = i & 15;
            int k = k0 + row;
            uint4 v = make_uint4(0u, 0u, 0u, 0u);
            if (k < K) v = *(const uint4*)&Bw[(size_t)k * 1024 + nb + c8 * 8];
            *(uint4*)&B_sm[row * 136 + c8 * 8] = v;
        }
        __syncthreads();

#pragma unroll
        for (int kk = 0; kk < 2; ++kk) {
            unsigned a0, a1, a2, a3;
            unsigned aaddr = smem_u32(&A_sm[(wy * 16 + (lane & 15)) * 40 + kk * 16 + (lane >> 4) * 8]);
            ldsm_x4(a0, a1, a2, a3, aaddr);
#pragma unroll
            for (int np = 0; np < 4; ++np) {
                unsigned q0, q1, q2, q3;
                unsigned baddr = smem_u32(&B_sm[(kk * 16 + (lane & 15)) * 136 + wx * 64 + np * 16 + (lane >> 4) * 8]);
                ldsm_x4_t(q0, q1, q2, q3, baddr);
                mma16816(c[np * 2],     a0, a1, a2, a3, q0, q1);
                mma16816(c[np * 2 + 1], a0, a1, a2, a3, q2, q3);
            }
        }
        __syncthreads();
    }

    const int r = lane >> 2;
    const int cb = (lane & 3) * 2;
#pragma unroll
    for (int nt = 0; nt < 8; ++nt) {
        int gn = nb + wx * 64 + nt * 8 + cb;
        float bx = bias[gn];
        float by = bias[gn + 1];
        int m1 = m0 + wy * 16 + r;
        int m2 = m1 + 8;
        __half2 lo = __floats2half2_rn(c[nt][0] + bx, c[nt][1] + by);
        __half2 hi = __floats2half2_rn(c[nt][2] + bx, c[nt][3] + by);
        *(__half2*)&g_xpre16[(size_t)m1 * 1024 + gn] = lo;
        *(__half2*)&g_xpre16[(size_t)m2 * 1024 + gn] = hi;
    }
}

// ---------------------------------------------------------------------------
// Persistent recurrent kernel v3.
// 512 threads (16 warps), 128 blocks (0..63 fw, 64..127 bw), 16 batch rows.
// Wh in register fragments; tanh.approx activations (5 MUFU/cell);
// main loop runs to Lmax only, then barrier-free zero tail.
// ---------------------------------------------------------------------------
#define WH_STRIDE 520
#define HS_STRIDE 136
#define GS_STRIDE 520
#define SM_HS_OFF 133120
#define SM_GS_OFF 137472
#define SM_LS_OFF 170752
#define REC_SMEM  170880

__global__ __launch_bounds__(512) void rec_mma(const int* __restrict__ seq_len, int layer)
{
    extern __shared__ char smraw[];
    __half* WH = (__half*)(smraw);
    __half* HS = (__half*)(smraw + SM_HS_OFF);
    float*  GS = (float*)(smraw + SM_GS_OFF);
    int*    LS = (int*)(smraw + SM_LS_OFF);

    const int blk = blockIdx.x;
    const int dir = blk >> 6;
    const int b0 = (blk & 63) * 16;
    const int xoff = dir * 512;
    const int ooff = dir * 128;
    const int tid = threadIdx.x;

    __half* outh = (layer == 0) ? g_cur0h : g_cur1h;

    // stage Wh into smem once
    const __half* wg = g_wh16 + (size_t)(layer * 2 + dir) * 65536;
#pragma unroll 4
    for (int i = tid; i < 8192; i += 512) {
        int r = i >> 6;
        int c8 = i & 63;
        *(uint4*)&WH[r * WH_STRIDE + c8 * 8] = ((const uint4*)wg)[i];
    }
    for (int i = tid; i < (16 * HS_STRIDE) / 2; i += 512) ((unsigned*)HS)[i] = 0u;
    if (tid < 16) LS[tid] = seq_len[b0 + tid];
    __syncthreads();
    if (tid == 0) {
        int m = 0;
#pragma unroll
        for (int i = 0; i < 16; ++i) m = max(m, LS[i]);
        LS[16] = m;
    }
    __syncthreads();
    const int Lmax = LS[16];

    const int warp = tid >> 5;
    const int lane = tid & 31;
    const int n_base = warp * 32;
    const int arow = lane & 15;
    const int acol8 = (lane >> 4) * 8;

    // load Wh B-fragments into registers (once)
    unsigned bfr[8][8];
#pragma unroll
    for (int kk = 0; kk < 8; ++kk) {
#pragma unroll
        for (int nt2 = 0; nt2 < 2; ++nt2) {
            unsigned baddr = smem_u32(&WH[(kk * 16 + arow) * WH_STRIDE + n_base + nt2 * 16 + acol8]);
            ldsm_x4_t(bfr[kk][nt2 * 4 + 0], bfr[kk][nt2 * 4 + 1],
                      bfr[kk][nt2 * 4 + 2], bfr[kk][nt2 * 4 + 3], baddr);
        }
    }

    const int r2 = warp;
    const int h2 = lane * 4;
    const int L = LS[r2];
    const size_t bR = (size_t)(b0 + r2);

    float c_reg[4] = {0.f, 0.f, 0.f, 0.f};

    for (int step = 0; step < Lmax; ++step) {
        const bool active = (step < L);
        const int in_idx = active ? (dir ? (L - 1 - step) : step) : 0;
        uint2 vi, vj, vf, vo;
        if (active) {
            const __half* xp = g_xpre16 + (bR * TT + in_idx) * 1024 + xoff + h2;
            vi = *(const uint2*)(xp);
            vj = *(const uint2*)(xp + 128);
            vf = *(const uint2*)(xp + 256);
            vo = *(const uint2*)(xp + 384);
        }

        {
            float c[4][4];
#pragma unroll
            for (int i = 0; i < 4; ++i) {
#pragma unroll
                for (int j = 0; j < 4; ++j) c[i][j] = 0.f;
            }
#pragma unroll
            for (int kk = 0; kk < 8; ++kk) {
                unsigned a0, a1, a2, a3;
                unsigned aaddr = smem_u32(&HS[arow * HS_STRIDE + kk * 16 + acol8]);
                ldsm_x4(a0, a1, a2, a3, aaddr);
                mma16816(c[0], a0, a1, a2, a3, bfr[kk][0], bfr[kk][1]);
                mma16816(c[1], a0, a1, a2, a3, bfr[kk][2], bfr[kk][3]);
                mma16816(c[2], a0, a1, a2, a3, bfr[kk][4], bfr[kk][5]);
                mma16816(c[3], a0, a1, a2, a3, bfr[kk][6], bfr[kk][7]);
            }
            const int rr = lane >> 2;
            const int cb = (lane & 3) * 2;
#pragma unroll
            for (int nt = 0; nt < 4; ++nt) {
                int n = n_base + nt * 8 + cb;
                *(float2*)&GS[rr * GS_STRIDE + n]       = make_float2(c[nt][0], c[nt][1]);
                *(float2*)&GS[(rr + 8) * GS_STRIDE + n] = make_float2(c[nt][2], c[nt][3]);
            }
        }
        __syncthreads();

        float hv[4];
        int pos;
        if (active) {
            pos = in_idx;
            const __half* pi = (const __half*)&vi;
            const __half* pj = (const __half*)&vj;
            const __half* pf = (const __half*)&vf;
            const __half* po = (const __half*)&vo;
            const float* gsr = &GS[r2 * GS_STRIDE];
#pragma unroll
            for (int u = 0; u < 4; ++u) {
                float gi = __half2float(pi[u]) + gsr[h2 + u];
                float gj = __half2float(pj[u]) + gsr[128 + h2 + u];
                float gf = __half2float(pf[u]) + gsr[256 + h2 + u];
                float go = __half2float(po[u]) + gsr[384 + h2 + u];
                float ig = sig_apx(gi);
                float fg = sig_apx(gf + 1.f);
                float og = sig_apx(go);
                float jg = tanh_apx(gj);
                float cn = c_reg[u] * fg + ig * jg;
                c_reg[u] = cn;
                hv[u] = tanh_apx(cn) * og;
            }
        } else {
            pos = step;
#pragma unroll
            for (int u = 0; u < 4; ++u) hv[u] = 0.f;
        }

        __half hb[4];
#pragma unroll
        for (int u = 0; u < 4; ++u) hb[u] = __float2half(hv[u]);
        *(uint2*)&outh[(bR * TT + pos) * 256 + ooff + h2] = *(uint2*)hb;
        if (active) {
            *(uint2*)&HS[r2 * HS_STRIDE + h2] = *(uint2*)hb;
        }
        __syncthreads();
    }

    // barrier-free zero tail: positions [Lmax, TT) are zero for every row
    for (int step = Lmax; step < TT; ++step) {
        *(uint2*)&outh[(bR * TT + step) * 256 + ooff + h2] = make_uint2(0u, 0u);
    }
}

// ---------------------------------------------------------------------------
// Attention pooling (single pass, smem-resident tile): g_cur1h -> g_attb
// Dyn smem: tile[169*256] half | wv[256] f | e[176] f | red[40] f
// ---------------------------------------------------------------------------
#define ATT_TILE_BYTES (TT * 256 * 2)
#define ATT_WV_OFF  ATT_TILE_BYTES
#define ATT_E_OFF   (ATT_WV_OFF + 256 * 4)
#define ATT_RED_OFF (ATT_E_OFF + 176 * 4)
#define ATT_SMEM    (ATT_RED_OFF + 40 * 4)

__global__ __launch_bounds__(256) void att_kernel(
    const float* __restrict__ w_att, const float* __restrict__ b_att)
{
    extern __shared__ char asm_raw[];
    __half* tile = (__half*)(asm_raw);
    float*  wv   = (float*)(asm_raw + ATT_WV_OFF);
    float*  e_sm = (float*)(asm_raw + ATT_E_OFF);
    float*  red  = (float*)(asm_raw + ATT_RED_OFF);

    const int b = blockIdx.x;
    const int tid = threadIdx.x;
    wv[tid] = w_att[tid];

    // load tile once: 169*256 halves = 2704 uint4
    const uint4* src = (const uint4*)&g_cur1h[(size_t)b * TT * 256];
    for (int i = tid; i < TT * 256 / 8; i += 256) {
        ((uint4*)tile)[i] = src[i];
    }
    __syncthreads();

    const int warp = tid >> 5;
    const int lane = tid & 31;

    // scores: warp per timestep; lane owns 8 consecutive cols
    for (int t = warp; t < TT; t += 8) {
        const __half* p = &tile[t * 256 + lane * 8];
        float s = 0.f;
#pragma unroll
        for (int j = 0; j < 4; ++j) {
            __half2 hh = *(const __half2*)(p + j * 2);
            float2 ff = __half22float2(hh);
            s += ff.x * wv[lane * 8 + j * 2] + ff.y * wv[lane * 8 + j * 2 + 1];
        }
#pragma unroll
        for (int off = 16; off > 0; off >>= 1) s += __shfl_down_sync(0xffffffffu, s, off);
        if (lane == 0) e_sm[t] = tanhf(s + b_att[0]);
    }
    __syncthreads();

    float m = -1e30f;
    for (int t = tid; t < TT; t += 256) m = fmaxf(m, e_sm[t]);
#pragma unroll
    for (int off = 16; off > 0; off >>= 1) m = fmaxf(m, __shfl_xor_sync(0xffffffffu, m, off));
    if (lane == 0) red[warp] = m;
    __syncthreads();
    if (tid == 0) {
        float mm = red[0];
        for (int w = 1; w < 8; ++w) mm = fmaxf(mm, red[w]);
        red[32] = mm;
    }
    __syncthreads();
    const float mx = red[32];

    float ssum = 0.f;
    for (int t = tid; t < TT; t += 256) {
        float p = expf(e_sm[t] - mx);
        e_sm[t] = p;
        ssum += p;
    }
#pragma unroll
    for (int off = 16; off > 0; off >>= 1) ssum += __shfl_xor_sync(0xffffffffu, ssum, off);
    if (lane == 0) red[warp] = ssum;
    __syncthreads();
    if (tid == 0) {
        float s2 = 0.f;
        for (int w = 0; w < 8; ++w) s2 += red[w];
        red[33] = s2;
    }
    __syncthreads();
    const float inv = 1.f / red[33];

    // weighted sum: thread owns one column
    float acc = 0.f;
    const __half* base = &tile[tid];
    for (int t = 0; t < TT; ++t) {
        acc += e_sm[t] * __half2float(base[t * 256]);
    }
    g_attb[b * 256 + tid] = acc * inv;
}

// ---------------------------------------------------------------------------
// Classifier head: [g_sbuf, g_attb] -> out
// ---------------------------------------------------------------------------
__global__ __launch_bounds__(64) void head_kernel(
    const float* __restrict__ w1, const float* __restrict__ b1,
    const float* __restrict__ w2, const float* __restrict__ b2,
    float* __restrict__ out)
{
    const int b = blockIdx.x;
    const int tid = threadIdx.x;
    __shared__ float cat[272];
    __shared__ float h1[64];
    if (tid < 16) cat[tid] = g_sbuf[b * 16 + tid];
    for (int j = tid; j < 256; j += 64) cat[16 + j] = g_attb[b * 256 + j];
    __syncthreads();
    float a = b1[tid];
#pragma unroll 4
    for (int k = 0; k < 272; ++k) a += cat[k] * w1[k * 64 + tid];
    h1[tid] = fmaxf(a, 0.f);
    __syncthreads();
    if (tid < 32) {
        float a2 = b2[tid];
#pragma unroll
        for (int k = 0; k < 64; ++k) a2 += h1[k] * w2[k * 32 + tid];
        out[b * 32 + tid] = fmaxf(a2, 0.f);
    }
}

// ---------------------------------------------------------------------------
// Launch
// ---------------------------------------------------------------------------
extern "C" void kernel_launch(void* const* d_in, const int* in_sizes, int n_in,
                              void* d_out, int out_size)
{
    const float* x_static = (const float*)d_in[0];
    const float* x_dyn    = (const float*)d_in[1];
    const int*   seq      = (const int*)  d_in[2];
    const float* w_s0  = (const float*)d_in[3];
    const float* b_s0  = (const float*)d_in[4];
    const float* w_s1  = (const float*)d_in[5];
    const float* b_s1  = (const float*)d_in[6];
    const float* Wx_f0 = (const float*)d_in[7];
    const float* Wh_f0 = (const float*)d_in[8];
    const float* bb_f0 = (const float*)d_in[9];
    const float* Wx_b0 = (const float*)d_in[10];
    const float* Wh_b0 = (const float*)d_in[11];
    const float* bb_b0 = (const float*)d_in[12];
    const float* Wx_f1 = (const float*)d_in[13];
    const float* Wh_f1 = (const float*)d_in[14];
    const float* bb_f1 = (const float*)d_in[15];
    const float* Wx_b1 = (const float*)d_in[16];
    const float* Wh_b1 = (const float*)d_in[17];
    const float* bb_b1 = (const float*)d_in[18];
    const float* w_att = (const float*)d_in[19];
    const float* b_att = (const float*)d_in[20];
    const float* w_c1  = (const float*)d_in[21];
    const float* b_c1  = (const float*)d_in[22];
    const float* w_c2  = (const float*)d_in[23];
    const float* b_c2  = (const float*)d_in[24];
    float* out = (float*)d_out;

    cudaFuncSetAttribute(rec_mma, cudaFuncAttributeMaxDynamicSharedMemorySize, REC_SMEM);
    cudaFuncSetAttribute(att_kernel, cudaFuncAttributeMaxDynamicSharedMemorySize, ATT_SMEM);

    prep_kernel<<<256, 256>>>(Wh_f0, Wh_b0, Wh_f1, Wh_b1,
                              Wx_f0, Wx_b0, Wx_f1, Wx_b1,
                              bb_f0, bb_b0, bb_f1, bb_b1);
    static_kernel<<<(BATCH + 255) / 256, 256>>>(x_static, w_s0, b_s0, w_s1, b_s1);

    dim3 ggrid(8, MTOT / 64);
    xpre_gemm_mma<<<ggrid, 256>>>(x_dyn, FDYN, 0, seq);
    rec_mma<<<128, 512, REC_SMEM>>>(seq, 0);
    xpre_gemm_mma<<<ggrid, 256>>>(nullptr, 256, 1, seq);
    rec_mma<<<128, 512, REC_SMEM>>>(seq, 1);
    att_kernel<<<BATCH, 256, ATT_SMEM>>>(w_att, b_att);
    head_kernel<<<BATCH, 64>>>(w_c1, b_c1, w_c2, b_c2, out);
}

// round 13
// speedup vs baseline: 8.4497x; 1.0049x over previous
#include <cuda_runtime.h>
#include <cuda_fp16.h>
#include <cstdint>
#include <math.h>

// Problem constants
#define BATCH 1024
#define TT    169
#define FDYN  36
#define FSTAT 19
#define HID   128
#define MTOT  (BATCH * TT)

// ---------------------------------------------------------------------------
// Scratch (device globals)
// ---------------------------------------------------------------------------
__device__ __half g_xpre16[(size_t)MTOT * 1024];
__device__ __half g_cur0h[(size_t)MTOT * 256];
__device__ __half g_cur1h[(size_t)MTOT * 256];
__device__ float  g_sbuf[BATCH * 16];
__device__ float  g_attb[BATCH * 256];
__device__ __half g_wh16[4 * 128 * 512];   // column-REORDERED: col = (h>>3)*32 + gate*8 + (h&7)
__device__ __half g_wx0[36 * 1024];
__device__ __half g_wx1[256 * 1024];
__device__ float  g_bx0[1024];
__device__ float  g_bx1[1024];

// ---------------------------------------------------------------------------
// MMA / ldmatrix / fast-math helpers
// ---------------------------------------------------------------------------
__device__ __forceinline__ unsigned smem_u32(const void* p) {
    return (unsigned)__cvta_generic_to_shared(p);
}
__device__ __forceinline__ void ldsm_x4(unsigned& r0, unsigned& r1, unsigned& r2, unsigned& r3, unsigned a) {
    asm volatile("ldmatrix.sync.aligned.m8n8.x4.shared.b16 {%0,%1,%2,%3}, [%4];"
                 : "=r"(r0), "=r"(r1), "=r"(r2), "=r"(r3) : "r"(a));
}
__device__ __forceinline__ void ldsm_x4_t(unsigned& r0, unsigned& r1, unsigned& r2, unsigned& r3, unsigned a) {
    asm volatile("ldmatrix.sync.aligned.m8n8.x4.trans.shared.b16 {%0,%1,%2,%3}, [%4];"
                 : "=r"(r0), "=r"(r1), "=r"(r2), "=r"(r3) : "r"(a));
}
__device__ __forceinline__ void mma16816(float* c, unsigned a0, unsigned a1, unsigned a2, unsigned a3,
                                         unsigned b0, unsigned b1) {
    asm volatile("mma.sync.aligned.m16n8k16.row.col.f32.f16.f16.f32 "
                 "{%0,%1,%2,%3}, {%4,%5,%6,%7}, {%8,%9}, {%0,%1,%2,%3};"
                 : "+f"(c[0]), "+f"(c[1]), "+f"(c[2]), "+f"(c[3])
                 : "r"(a0), "r"(a1), "r"(a2), "r"(a3), "r"(b0), "r"(b1));
}
__device__ __forceinline__ float tanh_apx(float x) {
    float r; asm("tanh.approx.f32 %0, %1;" : "=f"(r) : "f"(x)); return r;
}
__device__ __forceinline__ float sig_apx(float x) {
    return fmaf(tanh_apx(0.5f * x), 0.5f, 0.5f);
}

// ---------------------------------------------------------------------------
// Weight conversion to fp16 (once per launch). Wh columns are permuted so
// that MMA warp w's 32 output columns are gates {i,j,f,o} x 8 for h in
// [w*8, w*8+8): newcol = (h>>3)*32 + gate*8 + (h&7).
// ---------------------------------------------------------------------------
__global__ __launch_bounds__(256) void prep_kernel(
    const float* __restrict__ Wh_f0, const float* __restrict__ Wh_b0,
    const float* __restrict__ Wh_f1, const float* __restrict__ Wh_b1,
    const float* __restrict__ Wx_f0, const float* __restrict__ Wx_b0,
    const float* __restrict__ Wx_f1, const float* __restrict__ Wx_b1,
    const float* __restrict__ bb_f0, const float* __restrict__ bb_b0,
    const float* __restrict__ bb_f1, const float* __restrict__ bb_b1)
{
    const int N_WH = 4 * 65536;
    const int N_W0 = 36 * 1024;
    const int N_W1 = 256 * 1024;
    const int N_ALL = N_WH + N_W0 + N_W1 + 2048;
    for (int idx = blockIdx.x * 256 + threadIdx.x; idx < N_ALL; idx += gridDim.x * 256) {
        if (idx < N_WH) {
            int which = idx >> 16;
            int off = idx & 65535;
            int k = off >> 9;
            int c_orig = off & 511;
            int gate = c_orig >> 7;
            int h = c_orig & 127;
            int newc = (h >> 3) * 32 + gate * 8 + (h & 7);
            const float* src = (which == 0) ? Wh_f0 : (which == 1) ? Wh_b0 : (which == 2) ? Wh_f1 : Wh_b1;
            g_wh16[which * 65536 + k * 512 + newc] = __float2half(src[off]);
        } else if (idx < N_WH + N_W0) {
            int j = idx - N_WH;
            int k = j >> 10;
            int n = j & 1023;
            float v = (n < 512) ? Wx_f0[k * 512 + n] : Wx_b0[k * 512 + (n - 512)];
            g_wx0[j] = __float2half(v);
        } else if (idx < N_WH + N_W0 + N_W1) {
            int j = idx - N_WH - N_W0;
            int k = j >> 10;
            int n = j & 1023;
            float v = (n < 512) ? Wx_f1[k * 512 + n] : Wx_b1[k * 512 + (n - 512)];
            g_wx1[j] = __float2half(v);
        } else {
            int j = idx - N_WH - N_W0 - N_W1;
            int n = j & 1023;
            if (j < 1024) { g_bx0[n] = (n < 512) ? bb_f0[n] : bb_b0[n - 512]; }
            else          { g_bx1[n] = (n < 512) ? bb_f1[n] : bb_b1[n - 512]; }
        }
    }
}

// ---------------------------------------------------------------------------
// Static branch -> g_sbuf
// ---------------------------------------------------------------------------
__global__ __launch_bounds__(256) void static_kernel(
    const float* __restrict__ x, const float* __restrict__ w0, const float* __restrict__ b0,
    const float* __restrict__ w1, const float* __restrict__ b1)
{
    int b = blockIdx.x * blockDim.x + threadIdx.x;
    if (b >= BATCH) return;
    float xin[FSTAT];
#pragma unroll
    for (int i = 0; i < FSTAT; ++i) xin[i] = x[b * FSTAT + i];
    float h0[16];
#pragma unroll
    for (int j = 0; j < 16; ++j) {
        float a = b0[j];
#pragma unroll
        for (int i = 0; i < FSTAT; ++i) a += xin[i] * w0[i * 16 + j];
        h0[j] = fmaxf(a, 0.f);
    }
#pragma unroll
    for (int j = 0; j < 16; ++j) {
        float a = b1[j];
#pragma unroll
        for (int i = 0; i < 16; ++i) a += h0[i] * w1[i * 16 + j];
        g_sbuf[b * 16 + j] = fmaxf(a, 0.f);
    }
}

// ---------------------------------------------------------------------------
// Input-projection GEMM via mma -> g_xpre16 (layout: gates at +0/+128/+256/+384).
// Grid: (8 N-blocks [x, fastest], 2704 M-tiles [y]).
// ---------------------------------------------------------------------------
__global__ __launch_bounds__(256) void xpre_gemm_mma(
    const float* __restrict__ Afloat, int K, int layer,
    const int* __restrict__ seq_len)
{
    __shared__ __half A_sm[64 * 40];
    __shared__ __half B_sm[32 * 136];

    const int m0 = blockIdx.y * 64;
    const int nb = blockIdx.x * 128;
    const int tid = threadIdx.x;

    int act = 0;
    if (tid < 64) {
        int m = m0 + tid;
        int bi = m / TT;
        int t = m - bi * TT;
        act = (t < seq_len[bi]) ? 1 : 0;
    }
    if (!__syncthreads_or(act)) return;

    const __half* Bw = (layer == 0) ? g_wx0 : g_wx1;
    const float* bias = (layer == 0) ? g_bx0 : g_bx1;

    const int warp = tid >> 5;
    const int lane = tid & 31;
    const int wy = warp >> 1;
    const int wx = warp & 1;

    float c[8][4];
#pragma unroll
    for (int i = 0; i < 8; ++i) {
#pragma unroll
        for (int j = 0; j < 4; ++j) c[i][j] = 0.f;
    }

    for (int k0 = 0; k0 < K; k0 += 32) {
        if (layer == 1) {
            int row = tid >> 2;
            int colc = (tid & 3) * 8;
            uint4 v = *(const uint4*)&g_cur0h[(size_t)(m0 + row) * 256 + k0 + colc];
            *(uint4*)&A_sm[row * 40 + colc] = v;
        } else {
#pragma unroll
            for (int j = 0; j < 8; ++j) {
                int i = tid + j * 256;
                int row = i >> 5;
                int col = i & 31;
                int k = k0 + col;
                __half hv = __float2half(0.f);
                if (k < K) hv = __float2half(Afloat[(size_t)(m0 + row) * K + k]);
                A_sm[row * 40 + col] = hv;
            }
        }
#pragma unroll
        for (int j = 0; j < 2; ++j) {
            int i = tid + j * 256;
            int row = i >> 4;
            int c8 = i & 15;
            int k = k0 + row;
            uint4 v = make_uint4(0u, 0u, 0u, 0u);
            if (k < K) v = *(const uint4*)&Bw[(size_t)k * 1024 + nb + c8 * 8];
            *(uint4*)&B_sm[row * 136 + c8 * 8] = v;
        }
        __syncthreads();

#pragma unroll
        for (int kk = 0; kk < 2; ++kk) {
            unsigned a0, a1, a2, a3;
            unsigned aaddr = smem_u32(&A_sm[(wy * 16 + (lane & 15)) * 40 + kk * 16 + (lane >> 4) * 8]);
            ldsm_x4(a0, a1, a2, a3, aaddr);
#pragma unroll
            for (int np = 0; np < 4; ++np) {
                unsigned q0, q1, q2, q3;
                unsigned baddr = smem_u32(&B_sm[(kk * 16 + (lane & 15)) * 136 + wx * 64 + np * 16 + (lane >> 4) * 8]);
                ldsm_x4_t(q0, q1, q2, q3, baddr);
                mma16816(c[np * 2],     a0, a1, a2, a3, q0, q1);
                mma16816(c[np * 2 + 1], a0, a1, a2, a3, q2, q3);
            }
        }
        __syncthreads();
    }

    const int r = lane >> 2;
    const int cb = (lane & 3) * 2;
#pragma unroll
    for (int nt = 0; nt < 8; ++nt) {
        int gn = nb + wx * 64 + nt * 8 + cb;
        float bx = bias[gn];
        float by = bias[gn + 1];
        int m1 = m0 + wy * 16 + r;
        int m2 = m1 + 8;
        __half2 lo = __floats2half2_rn(c[nt][0] + bx, c[nt][1] + by);
        __half2 hi = __floats2half2_rn(c[nt][2] + bx, c[nt][3] + by);
        *(__half2*)&g_xpre16[(size_t)m1 * 1024 + gn] = lo;
        *(__half2*)&g_xpre16[(size_t)m2 * 1024 + gn] = hi;
    }
}

// ---------------------------------------------------------------------------
// Persistent recurrent kernel v5 — in-register gate handoff.
// 512 threads (16 warps), 128 blocks (0..63 fw, 64..127 bw), 16 batch rows.
// Wh columns pre-reordered so each warp's MMA accumulators ARE the 4 gates of
// its own cells: no gate smem round-trip, ping-pong HS, ONE barrier per step.
// Lane (rr=lane>>2, cb=(lane&3)*2) owns cells (row rr, h=w*8+cb..+1) and
// (row rr+8, same h): c[gate][0,1]=row rr, c[gate][2,3]=row rr+8.
// ---------------------------------------------------------------------------
#define WH_STRIDE 520
#define HS_STRIDE 136
#define HS_BUFSZ  (16 * HS_STRIDE)            // halves per buffer
#define SM_HS_OFF 133120
#define SM_LS_OFF (SM_HS_OFF + 2 * HS_BUFSZ * 2)
#define REC_SMEM  (SM_LS_OFF + 128)

__global__ __launch_bounds__(512) void rec_mma(const int* __restrict__ seq_len, int layer)
{
    extern __shared__ char smraw[];
    __half* WH = (__half*)(smraw);
    __half* HS = (__half*)(smraw + SM_HS_OFF);   // two ping-pong buffers
    int*    LS = (int*)(smraw + SM_LS_OFF);

    const int blk = blockIdx.x;
    const int dir = blk >> 6;
    const int b0 = (blk & 63) * 16;
    const int xoff = dir * 512;
    const int ooff = dir * 128;
    const int tid = threadIdx.x;

    __half* outh = (layer == 0) ? g_cur0h : g_cur1h;

    // stage (reordered) Wh into smem once
    const __half* wg = g_wh16 + (size_t)(layer * 2 + dir) * 65536;
#pragma unroll 4
    for (int i = tid; i < 8192; i += 512) {
        int r = i >> 6;
        int c8 = i & 63;
        *(uint4*)&WH[r * WH_STRIDE + c8 * 8] = ((const uint4*)wg)[i];
    }
    for (int i = tid; i < HS_BUFSZ; i += 512) { ((unsigned*)HS)[i] = 0u; }  // both buffers
    if (tid < 16) LS[tid] = seq_len[b0 + tid];
    __syncthreads();
    if (tid == 0) {
        int m = 0;
#pragma unroll
        for (int i = 0; i < 16; ++i) m = max(m, LS[i]);
        LS[16] = m;
    }
    __syncthreads();
    const int Lmax = LS[16];

    const int warp = tid >> 5;
    const int lane = tid & 31;
    const int n_base = warp * 32;
    const int arow = lane & 15;
    const int acol8 = (lane >> 4) * 8;

    // load Wh B-fragments into registers (once)
    unsigned bfr[8][8];
#pragma unroll
    for (int kk = 0; kk < 8; ++kk) {
#pragma unroll
        for (int nt2 = 0; nt2 < 2; ++nt2) {
            unsigned baddr = smem_u32(&WH[(kk * 16 + arow) * WH_STRIDE + n_base + nt2 * 16 + acol8]);
            ldsm_x4_t(bfr[kk][nt2 * 4 + 0], bfr[kk][nt2 * 4 + 1],
                      bfr[kk][nt2 * 4 + 2], bfr[kk][nt2 * 4 + 3], baddr);
        }
    }

    // cell ownership
    const int rr = lane >> 2;
    const int cb = (lane & 3) * 2;
    const int hp = warp * 8 + cb;           // hidden pair base
    const int L0 = LS[rr];
    const int L1 = LS[rr + 8];
    const size_t bR0 = (size_t)(b0 + rr);
    const size_t bR1 = (size_t)(b0 + rr + 8);

    float c_reg[4] = {0.f, 0.f, 0.f, 0.f};  // (r0,h0),(r0,h1),(r1,h0),(r1,h1)

    for (int step = 0; step < Lmax; ++step) {
        const bool act0 = (step < L0);
        const bool act1 = (step < L1);
        const int idx0 = act0 ? (dir ? (L0 - 1 - step) : step) : step;
        const int idx1 = act1 ? (dir ? (L1 - 1 - step) : step) : step;

        // issue xpre loads early (latency hidden under the MMA below)
        unsigned xi0 = 0u, xj0 = 0u, xf0 = 0u, xo0 = 0u;
        unsigned xi1 = 0u, xj1 = 0u, xf1 = 0u, xo1 = 0u;
        if (act0) {
            const __half* p = g_xpre16 + (bR0 * TT + idx0) * 1024 + xoff + hp;
            xi0 = *(const unsigned*)(p);
            xj0 = *(const unsigned*)(p + 128);
            xf0 = *(const unsigned*)(p + 256);
            xo0 = *(const unsigned*)(p + 384);
        }
        if (act1) {
            const __half* p = g_xpre16 + (bR1 * TT + idx1) * 1024 + xoff + hp;
            xi1 = *(const unsigned*)(p);
            xj1 = *(const unsigned*)(p + 128);
            xf1 = *(const unsigned*)(p + 256);
            xo1 = *(const unsigned*)(p + 384);
        }

        // ---- phase1: gates in registers via mma ----
        float c[4][4];
#pragma unroll
        for (int i = 0; i < 4; ++i) {
#pragma unroll
            for (int j = 0; j < 4; ++j) c[i][j] = 0.f;
        }
        {
            const __half* hsrc = HS + (step & 1) * HS_BUFSZ;
#pragma unroll
            for (int kk = 0; kk < 8; ++kk) {
                unsigned a0, a1, a2, a3;
                unsigned aaddr = smem_u32(&hsrc[arow * HS_STRIDE + kk * 16 + acol8]);
                ldsm_x4(a0, a1, a2, a3, aaddr);
                mma16816(c[0], a0, a1, a2, a3, bfr[kk][0], bfr[kk][1]);   // gate i
                mma16816(c[1], a0, a1, a2, a3, bfr[kk][2], bfr[kk][3]);   // gate j
                mma16816(c[2], a0, a1, a2, a3, bfr[kk][4], bfr[kk][5]);   // gate f
                mma16816(c[3], a0, a1, a2, a3, bfr[kk][6], bfr[kk][7]);   // gate o
            }
        }

        // ---- phase2: cell update straight from accumulators ----
        __half* hdst = HS + ((step + 1) & 1) * HS_BUFSZ;

        {   // row rr
            float2 xi = __half22float2(*(__half2*)&xi0);
            float2 xj = __half22float2(*(__half2*)&xj0);
            float2 xf = __half22float2(*(__half2*)&xf0);
            float2 xo = __half22float2(*(__half2*)&xo0);
            float hv0 = 0.f, hv1 = 0.f;
            if (act0) {
                float gi0 = c[0][0] + xi.x, gi1 = c[0][1] + xi.y;
                float gj0 = c[1][0] + xj.x, gj1 = c[1][1] + xj.y;
                float gf0 = c[2][0] + xf.x + 1.f, gf1 = c[2][1] + xf.y + 1.f;
                float go0 = c[3][0] + xo.x, go1 = c[3][1] + xo.y;
                float cn0 = fmaf(c_reg[0], sig_apx(gf0), sig_apx(gi0) * tanh_apx(gj0));
                float cn1 = fmaf(c_reg[1], sig_apx(gf1), sig_apx(gi1) * tanh_apx(gj1));
                c_reg[0] = cn0; c_reg[1] = cn1;
                hv0 = tanh_apx(cn0) * sig_apx(go0);
                hv1 = tanh_apx(cn1) * sig_apx(go1);
            }
            __half2 hb = __floats2half2_rn(hv0, hv1);
            *(__half2*)&outh[(bR0 * TT + idx0) * 256 + ooff + hp] = hb;
            if (act0) *(__half2*)&hdst[rr * HS_STRIDE + hp] = hb;
        }
        {   // row rr+8
            float2 xi = __half22float2(*(__half2*)&xi1);
            float2 xj = __half22float2(*(__half2*)&xj1);
            float2 xf = __half22float2(*(__half2*)&xf1);
            float2 xo = __half22float2(*(__half2*)&xo1);
            float hv0 = 0.f, hv1 = 0.f;
            if (act1) {
                float gi0 = c[0][2] + xi.x, gi1 = c[0][3] + xi.y;
                float gj0 = c[1][2] + xj.x, gj1 = c[1][3] + xj.y;
                float gf0 = c[2][2] + xf.x + 1.f, gf1 = c[2][3] + xf.y + 1.f;
                float go0 = c[3][2] + xo.x, go1 = c[3][3] + xo.y;
                float cn0 = fmaf(c_reg[2], sig_apx(gf0), sig_apx(gi0) * tanh_apx(gj0));
                float cn1 = fmaf(c_reg[3], sig_apx(gf1), sig_apx(gi1) * tanh_apx(gj1));
                c_reg[2] = cn0; c_reg[3] = cn1;
                hv0 = tanh_apx(cn0) * sig_apx(go0);
                hv1 = tanh_apx(cn1) * sig_apx(go1);
            }
            __half2 hb = __floats2half2_rn(hv0, hv1);
            *(__half2*)&outh[(bR1 * TT + idx1) * 256 + ooff + hp] = hb;
            if (act1) *(__half2*)&hdst[(rr + 8) * HS_STRIDE + hp] = hb;
        }

        __syncthreads();   // single barrier: HS writes visible before next phase1
    }

    // barrier-free zero tail: positions [Lmax, TT) are zero for every row
    for (int step = Lmax; step < TT; ++step) {
        *(unsigned*)&outh[(bR0 * TT + step) * 256 + ooff + hp] = 0u;
        *(unsigned*)&outh[(bR1 * TT + step) * 256 + ooff + hp] = 0u;
    }
}

// ---------------------------------------------------------------------------
// Attention pooling (single pass, smem-resident tile): g_cur1h -> g_attb
// ---------------------------------------------------------------------------
#define ATT_TILE_BYTES (TT * 256 * 2)
#define ATT_WV_OFF  ATT_TILE_BYTES
#define ATT_E_OFF   (ATT_WV_OFF + 256 * 4)
#define ATT_RED_OFF (ATT_E_OFF + 176 * 4)
#define ATT_SMEM    (ATT_RED_OFF + 40 * 4)

__global__ __launch_bounds__(256) void att_kernel(
    const float* __restrict__ w_att, const float* __restrict__ b_att)
{
    extern __shared__ char asm_raw[];
    __half* tile = (__half*)(asm_raw);
    float*  wv   = (float*)(asm_raw + ATT_WV_OFF);
    float*  e_sm = (float*)(asm_raw + ATT_E_OFF);
    float*  red  = (float*)(asm_raw + ATT_RED_OFF);

    const int b = blockIdx.x;
    const int tid = threadIdx.x;
    wv[tid] = w_att[tid];

    const uint4* src = (const uint4*)&g_cur1h[(size_t)b * TT * 256];
    for (int i = tid; i < TT * 256 / 8; i += 256) {
        ((uint4*)tile)[i] = src[i];
    }
    __syncthreads();

    const int warp = tid >> 5;
    const int lane = tid & 31;

    for (int t = warp; t < TT; t += 8) {
        const __half* p = &tile[t * 256 + lane * 8];
        float s = 0.f;
#pragma unroll
        for (int j = 0; j < 4; ++j) {
            __half2 hh = *(const __half2*)(p + j * 2);
            float2 ff = __half22float2(hh);
            s += ff.x * wv[lane * 8 + j * 2] + ff.y * wv[lane * 8 + j * 2 + 1];
        }
#pragma unroll
        for (int off = 16; off > 0; off >>= 1) s += __shfl_down_sync(0xffffffffu, s, off);
        if (lane == 0) e_sm[t] = tanhf(s + b_att[0]);
    }
    __syncthreads();

    float m = -1e30f;
    for (int t = tid; t < TT; t += 256) m = fmaxf(m, e_sm[t]);
#pragma unroll
    for (int off = 16; off > 0; off >>= 1) m = fmaxf(m, __shfl_xor_sync(0xffffffffu, m, off));
    if (lane == 0) red[warp] = m;
    __syncthreads();
    if (tid == 0) {
        float mm = red[0];
        for (int w = 1; w < 8; ++w) mm = fmaxf(mm, red[w]);
        red[32] = mm;
    }
    __syncthreads();
    const float mx = red[32];

    float ssum = 0.f;
    for (int t = tid; t < TT; t += 256) {
        float p = expf(e_sm[t] - mx);
        e_sm[t] = p;
        ssum += p;
    }
#pragma unroll
    for (int off = 16; off > 0; off >>= 1) ssum += __shfl_xor_sync(0xffffffffu, ssum, off);
    if (lane == 0) red[warp] = ssum;
    __syncthreads();
    if (tid == 0) {
        float s2 = 0.f;
        for (int w = 0; w < 8; ++w) s2 += red[w];
        red[33] = s2;
    }
    __syncthreads();
    const float inv = 1.f / red[33];

    float acc = 0.f;
    const __half* base = &tile[tid];
    for (int t = 0; t < TT; ++t) {
        acc += e_sm[t] * __half2float(base[t * 256]);
    }
    g_attb[b * 256 + tid] = acc * inv;
}

// ---------------------------------------------------------------------------
// Classifier head: [g_sbuf, g_attb] -> out
// ---------------------------------------------------------------------------
__global__ __launch_bounds__(64) void head_kernel(
    const float* __restrict__ w1, const float* __restrict__ b1,
    const float* __restrict__ w2, const float* __restrict__ b2,
    float* __restrict__ out)
{
    const int b = blockIdx.x;
    const int tid = threadIdx.x;
    __shared__ float cat[272];
    __shared__ float h1[64];
    if (tid < 16) cat[tid] = g_sbuf[b * 16 + tid];
    for (int j = tid; j < 256; j += 64) cat[16 + j] = g_attb[b * 256 + j];
    __syncthreads();
    float a = b1[tid];
#pragma unroll 4
    for (int k = 0; k < 272; ++k) a += cat[k] * w1[k * 64 + tid];
    h1[tid] = fmaxf(a, 0.f);
    __syncthreads();
    if (tid < 32) {
        float a2 = b2[tid];
#pragma unroll
        for (int k = 0; k < 64; ++k) a2 += h1[k] * w2[k * 32 + tid];
        out[b * 32 + tid] = fmaxf(a2, 0.f);
    }
}

// ---------------------------------------------------------------------------
// Launch
// ---------------------------------------------------------------------------
extern "C" void kernel_launch(void* const* d_in, const int* in_sizes, int n_in,
                              void* d_out, int out_size)
{
    const float* x_static = (const float*)d_in[0];
    const float* x_dyn    = (const float*)d_in[1];
    const int*   seq      = (const int*)  d_in[2];
    const float* w_s0  = (const float*)d_in[3];
    const float* b_s0  = (const float*)d_in[4];
    const float* w_s1  = (const float*)d_in[5];
    const float* b_s1  = (const float*)d_in[6];
    const float* Wx_f0 = (const float*)d_in[7];
    const float* Wh_f0 = (const float*)d_in[8];
    const float* bb_f0 = (const float*)d_in[9];
    const float* Wx_b0 = (const float*)d_in[10];
    const float* Wh_b0 = (const float*)d_in[11];
    const float* bb_b0 = (const float*)d_in[12];
    const float* Wx_f1 = (const float*)d_in[13];
    const float* Wh_f1 = (const float*)d_in[14];
    const float* bb_f1 = (const float*)d_in[15];
    const float* Wx_b1 = (const float*)d_in[16];
    const float* Wh_b1 = (const float*)d_in[17];
    const float* bb_b1 = (const float*)d_in[18];
    const float* w_att = (const float*)d_in[19];
    const float* b_att = (const float*)d_in[20];
    const float* w_c1  = (const float*)d_in[21];
    const float* b_c1  = (const float*)d_in[22];
    const float* w_c2  = (const float*)d_in[23];
    const float* b_c2  = (const float*)d_in[24];
    float* out = (float*)d_out;

    cudaFuncSetAttribute(rec_mma, cudaFuncAttributeMaxDynamicSharedMemorySize, REC_SMEM);
    cudaFuncSetAttribute(att_kernel, cudaFuncAttributeMaxDynamicSharedMemorySize, ATT_SMEM);

    prep_kernel<<<256, 256>>>(Wh_f0, Wh_b0, Wh_f1, Wh_b1,
                              Wx_f0, Wx_b0, Wx_f1, Wx_b1,
                              bb_f0, bb_b0, bb_f1, bb_b1);
    static_kernel<<<(BATCH + 255) / 256, 256>>>(x_static, w_s0, b_s0, w_s1, b_s1);

    dim3 ggrid(8, MTOT / 64);
    xpre_gemm_mma<<<ggrid, 256>>>(x_dyn, FDYN, 0, seq);
    rec_mma<<<128, 512, REC_SMEM>>>(seq, 0);
    xpre_gemm_mma<<<ggrid, 256>>>(nullptr, 256, 1, seq);
    rec_mma<<<128, 512, REC_SMEM>>>(seq, 1);
    att_kernel<<<BATCH, 256, ATT_SMEM>>>(w_att, b_att);
    head_kernel<<<BATCH, 64>>>(w_c1, b_c1, w_c2, b_c2, out);
}

// round 14
// speedup vs baseline: 8.8061x; 1.0422x over previous
#include <cuda_runtime.h>
#include <cuda_fp16.h>
#include <cstdint>
#include <math.h>

// Problem constants
#define BATCH 1024
#define TT    169
#define FDYN  36
#define FSTAT 19
#define HID   128
#define MTOT  (BATCH * TT)

// ---------------------------------------------------------------------------
// Scratch (device globals)
// ---------------------------------------------------------------------------
__device__ __half g_xpre16[(size_t)MTOT * 1024];  // per-dir cols: [warp(16)][cbg(4)][gate(4)][2] interleave
__device__ __half g_cur0h[(size_t)MTOT * 256];
__device__ __half g_cur1h[(size_t)MTOT * 256];
__device__ float  g_sbuf[BATCH * 16];
__device__ float  g_attb[BATCH * 256];
__device__ __half g_wh16[4 * 128 * 512];   // column-REORDERED: col = (h>>3)*32 + gate*8 + (h&7)
__device__ __half g_wx0[36 * 1024];        // column-REORDERED for coalesced xpre reads
__device__ __half g_wx1[256 * 1024];       // (same interleave)
__device__ float  g_bx0[1024];             // bias in the same permuted order
__device__ float  g_bx1[1024];

// ---------------------------------------------------------------------------
// MMA / ldmatrix / fast-math helpers
// ---------------------------------------------------------------------------
__device__ __forceinline__ unsigned smem_u32(const void* p) {
    return (unsigned)__cvta_generic_to_shared(p);
}
__device__ __forceinline__ void ldsm_x4(unsigned& r0, unsigned& r1, unsigned& r2, unsigned& r3, unsigned a) {
    asm volatile("ldmatrix.sync.aligned.m8n8.x4.shared.b16 {%0,%1,%2,%3}, [%4];"
                 : "=r"(r0), "=r"(r1), "=r"(r2), "=r"(r3) : "r"(a));
}
__device__ __forceinline__ void ldsm_x4_t(unsigned& r0, unsigned& r1, unsigned& r2, unsigned& r3, unsigned a) {
    asm volatile("ldmatrix.sync.aligned.m8n8.x4.trans.shared.b16 {%0,%1,%2,%3}, [%4];"
                 : "=r"(r0), "=r"(r1), "=r"(r2), "=r"(r3) : "r"(a));
}
__device__ __forceinline__ void mma16816(float* c, unsigned a0, unsigned a1, unsigned a2, unsigned a3,
                                         unsigned b0, unsigned b1) {
    asm volatile("mma.sync.aligned.m16n8k16.row.col.f32.f16.f16.f32 "
                 "{%0,%1,%2,%3}, {%4,%5,%6,%7}, {%8,%9}, {%0,%1,%2,%3};"
                 : "+f"(c[0]), "+f"(c[1]), "+f"(c[2]), "+f"(c[3])
                 : "r"(a0), "r"(a1), "r"(a2), "r"(a3), "r"(b0), "r"(b1));
}
__device__ __forceinline__ float tanh_apx(float x) {
    float r; asm("tanh.approx.f32 %0, %1;" : "=f"(r) : "f"(x)); return r;
}
__device__ __forceinline__ float sig_apx(float x) {
    return fmaf(tanh_apx(0.5f * x), 0.5f, 0.5f);
}

// xpre column interleave within a direction: lane-contiguous 16B per (row, hp)
__device__ __forceinline__ int xpre_newc(int c) {
    int gate = c >> 7;
    int h = c & 127;
    return (h >> 3) * 32 + ((h & 7) >> 1) * 8 + gate * 2 + (h & 1);
}

// ---------------------------------------------------------------------------
// Weight conversion to fp16 (once per launch).
// Wh columns permuted for in-register gate handoff (gate*8 interleave).
// Wx columns + bias permuted for coalesced uint4 xpre reads in rec.
// ---------------------------------------------------------------------------
__global__ __launch_bounds__(256) void prep_kernel(
    const float* __restrict__ Wh_f0, const float* __restrict__ Wh_b0,
    const float* __restrict__ Wh_f1, const float* __restrict__ Wh_b1,
    const float* __restrict__ Wx_f0, const float* __restrict__ Wx_b0,
    const float* __restrict__ Wx_f1, const float* __restrict__ Wx_b1,
    const float* __restrict__ bb_f0, const float* __restrict__ bb_b0,
    const float* __restrict__ bb_f1, const float* __restrict__ bb_b1)
{
    const int N_WH = 4 * 65536;
    const int N_W0 = 36 * 1024;
    const int N_W1 = 256 * 1024;
    const int N_ALL = N_WH + N_W0 + N_W1 + 2048;
    for (int idx = blockIdx.x * 256 + threadIdx.x; idx < N_ALL; idx += gridDim.x * 256) {
        if (idx < N_WH) {
            int which = idx >> 16;
            int off = idx & 65535;
            int k = off >> 9;
            int c_orig = off & 511;
            int gate = c_orig >> 7;
            int h = c_orig & 127;
            int newc = (h >> 3) * 32 + gate * 8 + (h & 7);
            const float* src = (which == 0) ? Wh_f0 : (which == 1) ? Wh_b0 : (which == 2) ? Wh_f1 : Wh_b1;
            g_wh16[which * 65536 + k * 512 + newc] = __float2half(src[off]);
        } else if (idx < N_WH + N_W0) {
            int j = idx - N_WH;
            int k = j >> 10;
            int n = j & 1023;
            int dirbase = (n < 512) ? 0 : 512;
            int c = n & 511;
            float v = (n < 512) ? Wx_f0[k * 512 + c] : Wx_b0[k * 512 + c];
            g_wx0[k * 1024 + dirbase + xpre_newc(c)] = __float2half(v);
        } else if (idx < N_WH + N_W0 + N_W1) {
            int j = idx - N_WH - N_W0;
            int k = j >> 10;
            int n = j & 1023;
            int dirbase = (n < 512) ? 0 : 512;
            int c = n & 511;
            float v = (n < 512) ? Wx_f1[k * 512 + c] : Wx_b1[k * 512 + c];
            g_wx1[k * 1024 + dirbase + xpre_newc(c)] = __float2half(v);
        } else {
            int j = idx - N_WH - N_W0 - N_W1;
            int n = j & 1023;
            int dirbase = (n < 512) ? 0 : 512;
            int c = n & 511;
            if (j < 1024) {
                float v = (n < 512) ? bb_f0[c] : bb_b0[c];
                g_bx0[dirbase + xpre_newc(c)] = v;
            } else {
                float v = (n < 512) ? bb_f1[c] : bb_b1[c];
                g_bx1[dirbase + xpre_newc(c)] = v;
            }
        }
    }
}

// ---------------------------------------------------------------------------
// Static branch -> g_sbuf
// ---------------------------------------------------------------------------
__global__ __launch_bounds__(256) void static_kernel(
    const float* __restrict__ x, const float* __restrict__ w0, const float* __restrict__ b0,
    const float* __restrict__ w1, const float* __restrict__ b1)
{
    int b = blockIdx.x * blockDim.x + threadIdx.x;
    if (b >= BATCH) return;
    float xin[FSTAT];
#pragma unroll
    for (int i = 0; i < FSTAT; ++i) xin[i] = x[b * FSTAT + i];
    float h0[16];
#pragma unroll
    for (int j = 0; j < 16; ++j) {
        float a = b0[j];
#pragma unroll
        for (int i = 0; i < FSTAT; ++i) a += xin[i] * w0[i * 16 + j];
        h0[j] = fmaxf(a, 0.f);
    }
#pragma unroll
    for (int j = 0; j < 16; ++j) {
        float a = b1[j];
#pragma unroll
        for (int i = 0; i < 16; ++i) a += h0[i] * w1[i * 16 + j];
        g_sbuf[b * 16 + j] = fmaxf(a, 0.f);
    }
}

// ---------------------------------------------------------------------------
// Input-projection GEMM via mma -> g_xpre16 (columns already permuted via Bw).
// Grid: (8 N-blocks [x, fastest], 2704 M-tiles [y]).
// ---------------------------------------------------------------------------
__global__ __launch_bounds__(256) void xpre_gemm_mma(
    const float* __restrict__ Afloat, int K, int layer,
    const int* __restrict__ seq_len)
{
    __shared__ __half A_sm[64 * 40];
    __shared__ __half B_sm[32 * 136];

    const int m0 = blockIdx.y * 64;
    const int nb = blockIdx.x * 128;
    const int tid = threadIdx.x;

    int act = 0;
    if (tid < 64) {
        int m = m0 + tid;
        int bi = m / TT;
        int t = m - bi * TT;
        act = (t < seq_len[bi]) ? 1 : 0;
    }
    if (!__syncthreads_or(act)) return;

    const __half* Bw = (layer == 0) ? g_wx0 : g_wx1;
    const float* bias = (layer == 0) ? g_bx0 : g_bx1;

    const int warp = tid >> 5;
    const int lane = tid & 31;
    const int wy = warp >> 1;
    const int wx = warp & 1;

    float c[8][4];
#pragma unroll
    for (int i = 0; i < 8; ++i) {
#pragma unroll
        for (int j = 0; j < 4; ++j) c[i][j] = 0.f;
    }

    for (int k0 = 0; k0 < K; k0 += 32) {
        if (layer == 1) {
            int row = tid >> 2;
            int colc = (tid & 3) * 8;
            uint4 v = *(const uint4*)&g_cur0h[(size_t)(m0 + row) * 256 + k0 + colc];
            *(uint4*)&A_sm[row * 40 + colc] = v;
        } else {
#pragma unroll
            for (int j = 0; j < 8; ++j) {
                int i = tid + j * 256;
                int row = i >> 5;
                int col = i & 31;
                int k = k0 + col;
                __half hv = __float2half(0.f);
                if (k < K) hv = __float2half(Afloat[(size_t)(m0 + row) * K + k]);
                A_sm[row * 40 + col] = hv;
            }
        }
#pragma unroll
        for (int j = 0; j < 2; ++j) {
            int i = tid + j * 256;
            int row = i >> 4;
            int c8 = i & 15;
            int k = k0 + row;
            uint4 v = make_uint4(0u, 0u, 0u, 0u);
            if (k < K) v = *(const uint4*)&Bw[(size_t)k * 1024 + nb + c8 * 8];
            *(uint4*)&B_sm[row * 136 + c8 * 8] = v;
        }
        __syncthreads();

#pragma unroll
        for (int kk = 0; kk < 2; ++kk) {
            unsigned a0, a1, a2, a3;
            unsigned aaddr = smem_u32(&A_sm[(wy * 16 + (lane & 15)) * 40 + kk * 16 + (lane >> 4) * 8]);
            ldsm_x4(a0, a1, a2, a3, aaddr);
#pragma unroll
            for (int np = 0; np < 4; ++np) {
                unsigned q0, q1, q2, q3;
                unsigned baddr = smem_u32(&B_sm[(kk * 16 + (lane & 15)) * 136 + wx * 64 + np * 16 + (lane >> 4) * 8]);
                ldsm_x4_t(q0, q1, q2, q3, baddr);
                mma16816(c[np * 2],     a0, a1, a2, a3, q0, q1);
                mma16816(c[np * 2 + 1], a0, a1, a2, a3, q2, q3);
            }
        }
        __syncthreads();
    }

    const int r = lane >> 2;
    const int cb = (lane & 3) * 2;
#pragma unroll
    for (int nt = 0; nt < 8; ++nt) {
        int gn = nb + wx * 64 + nt * 8 + cb;
        float bx = bias[gn];
        float by = bias[gn + 1];
        int m1 = m0 + wy * 16 + r;
        int m2 = m1 + 8;
        __half2 lo = __floats2half2_rn(c[nt][0] + bx, c[nt][1] + by);
        __half2 hi = __floats2half2_rn(c[nt][2] + bx, c[nt][3] + by);
        *(__half2*)&g_xpre16[(size_t)m1 * 1024 + gn] = lo;
        *(__half2*)&g_xpre16[(size_t)m2 * 1024 + gn] = hi;
    }
}

// ---------------------------------------------------------------------------
// Persistent recurrent kernel v6 — in-register gate handoff + coalesced xpre.
// 512 threads (16 warps), 128 blocks (0..63 fw, 64..127 bw), 16 batch rows.
// xpre now read as ONE uint4 per (row, lane): (i0,i1,j0,j1,f0,f1,o0,o1).
// ---------------------------------------------------------------------------
#define WH_STRIDE 520
#define HS_STRIDE 136
#define HS_BUFSZ  (16 * HS_STRIDE)            // halves per buffer
#define SM_HS_OFF 133120
#define SM_LS_OFF (SM_HS_OFF + 2 * HS_BUFSZ * 2)
#define REC_SMEM  (SM_LS_OFF + 128)

__global__ __launch_bounds__(512) void rec_mma(const int* __restrict__ seq_len, int layer)
{
    extern __shared__ char smraw[];
    __half* WH = (__half*)(smraw);
    __half* HS = (__half*)(smraw + SM_HS_OFF);   // two ping-pong buffers
    int*    LS = (int*)(smraw + SM_LS_OFF);

    const int blk = blockIdx.x;
    const int dir = blk >> 6;
    const int b0 = (blk & 63) * 16;
    const int xoff = dir * 512;
    const int ooff = dir * 128;
    const int tid = threadIdx.x;

    __half* outh = (layer == 0) ? g_cur0h : g_cur1h;

    // stage (reordered) Wh into smem once
    const __half* wg = g_wh16 + (size_t)(layer * 2 + dir) * 65536;
#pragma unroll 4
    for (int i = tid; i < 8192; i += 512) {
        int r = i >> 6;
        int c8 = i & 63;
        *(uint4*)&WH[r * WH_STRIDE + c8 * 8] = ((const uint4*)wg)[i];
    }
    for (int i = tid; i < HS_BUFSZ; i += 512) { ((unsigned*)HS)[i] = 0u; }  // both buffers
    if (tid < 16) LS[tid] = seq_len[b0 + tid];
    __syncthreads();
    if (tid == 0) {
        int m = 0;
#pragma unroll
        for (int i = 0; i < 16; ++i) m = max(m, LS[i]);
        LS[16] = m;
    }
    __syncthreads();
    const int Lmax = LS[16];

    const int warp = tid >> 5;
    const int lane = tid & 31;
    const int n_base = warp * 32;
    const int arow = lane & 15;
    const int acol8 = (lane >> 4) * 8;

    // load Wh B-fragments into registers (once)
    unsigned bfr[8][8];
#pragma unroll
    for (int kk = 0; kk < 8; ++kk) {
#pragma unroll
        for (int nt2 = 0; nt2 < 2; ++nt2) {
            unsigned baddr = smem_u32(&WH[(kk * 16 + arow) * WH_STRIDE + n_base + nt2 * 16 + acol8]);
            ldsm_x4_t(bfr[kk][nt2 * 4 + 0], bfr[kk][nt2 * 4 + 1],
                      bfr[kk][nt2 * 4 + 2], bfr[kk][nt2 * 4 + 3], baddr);
        }
    }

    // cell ownership
    const int rr = lane >> 2;
    const int cb = (lane & 3) * 2;
    const int hp = warp * 8 + cb;                  // hidden pair base (output layout)
    const int xcol = xoff + warp * 32 + (cb >> 1) * 8;  // xpre interleaved column
    const int L0 = LS[rr];
    const int L1 = LS[rr + 8];
    const size_t bR0 = (size_t)(b0 + rr);
    const size_t bR1 = (size_t)(b0 + rr + 8);

    float c_reg[4] = {0.f, 0.f, 0.f, 0.f};  // (r0,h0),(r0,h1),(r1,h0),(r1,h1)

    for (int step = 0; step < Lmax; ++step) {
        const bool act0 = (step < L0);
        const bool act1 = (step < L1);
        const int idx0 = act0 ? (dir ? (L0 - 1 - step) : step) : step;
        const int idx1 = act1 ? (dir ? (L1 - 1 - step) : step) : step;

        // coalesced xpre loads (one uint4 per row; latency hidden under MMA)
        uint4 xv0 = make_uint4(0u, 0u, 0u, 0u);
        uint4 xv1 = make_uint4(0u, 0u, 0u, 0u);
        if (act0) xv0 = *(const uint4*)(g_xpre16 + (bR0 * TT + idx0) * 1024 + xcol);
        if (act1) xv1 = *(const uint4*)(g_xpre16 + (bR1 * TT + idx1) * 1024 + xcol);

        // ---- phase1: gates in registers via mma ----
        float c[4][4];
#pragma unroll
        for (int i = 0; i < 4; ++i) {
#pragma unroll
            for (int j = 0; j < 4; ++j) c[i][j] = 0.f;
        }
        {
            const __half* hsrc = HS + (step & 1) * HS_BUFSZ;
#pragma unroll
            for (int kk = 0; kk < 8; ++kk) {
                unsigned a0, a1, a2, a3;
                unsigned aaddr = smem_u32(&hsrc[arow * HS_STRIDE + kk * 16 + acol8]);
                ldsm_x4(a0, a1, a2, a3, aaddr);
                mma16816(c[0], a0, a1, a2, a3, bfr[kk][0], bfr[kk][1]);   // gate i
                mma16816(c[1], a0, a1, a2, a3, bfr[kk][2], bfr[kk][3]);   // gate j
                mma16816(c[2], a0, a1, a2, a3, bfr[kk][4], bfr[kk][5]);   // gate f
                mma16816(c[3], a0, a1, a2, a3, bfr[kk][6], bfr[kk][7]);   // gate o
            }
        }

        // ---- phase2: cell update straight from accumulators ----
        __half* hdst = HS + ((step + 1) & 1) * HS_BUFSZ;

        {   // row rr
            float2 xi = __half22float2(*(__half2*)&xv0.x);
            float2 xj = __half22float2(*(__half2*)&xv0.y);
            float2 xf = __half22float2(*(__half2*)&xv0.z);
            float2 xo = __half22float2(*(__half2*)&xv0.w);
            float hv0 = 0.f, hv1 = 0.f;
            if (act0) {
                float gi0 = c[0][0] + xi.x, gi1 = c[0][1] + xi.y;
                float gj0 = c[1][0] + xj.x, gj1 = c[1][1] + xj.y;
                float gf0 = c[2][0] + xf.x + 1.f, gf1 = c[2][1] + xf.y + 1.f;
                float go0 = c[3][0] + xo.x, go1 = c[3][1] + xo.y;
                float cn0 = fmaf(c_reg[0], sig_apx(gf0), sig_apx(gi0) * tanh_apx(gj0));
                float cn1 = fmaf(c_reg[1], sig_apx(gf1), sig_apx(gi1) * tanh_apx(gj1));
                c_reg[0] = cn0; c_reg[1] = cn1;
                hv0 = tanh_apx(cn0) * sig_apx(go0);
                hv1 = tanh_apx(cn1) * sig_apx(go1);
            }
            __half2 hb = __floats2half2_rn(hv0, hv1);
            *(__half2*)&outh[(bR0 * TT + idx0) * 256 + ooff + hp] = hb;
            if (act0) *(__half2*)&hdst[rr * HS_STRIDE + hp] = hb;
        }
        {   // row rr+8
            float2 xi = __half22float2(*(__half2*)&xv1.x);
            float2 xj = __half22float2(*(__half2*)&xv1.y);
            float2 xf = __half22float2(*(__half2*)&xv1.z);
            float2 xo = __half22float2(*(__half2*)&xv1.w);
            float hv0 = 0.f, hv1 = 0.f;
            if (act1) {
                float gi0 = c[0][2] + xi.x, gi1 = c[0][3] + xi.y;
                float gj0 = c[1][2] + xj.x, gj1 = c[1][3] + xj.y;
                float gf0 = c[2][2] + xf.x + 1.f, gf1 = c[2][3] + xf.y + 1.f;
                float go0 = c[3][2] + xo.x, go1 = c[3][3] + xo.y;
                float cn0 = fmaf(c_reg[2], sig_apx(gf0), sig_apx(gi0) * tanh_apx(gj0));
                float cn1 = fmaf(c_reg[3], sig_apx(gf1), sig_apx(gi1) * tanh_apx(gj1));
                c_reg[2] = cn0; c_reg[3] = cn1;
                hv0 = tanh_apx(cn0) * sig_apx(go0);
                hv1 = tanh_apx(cn1) * sig_apx(go1);
            }
            __half2 hb = __floats2half2_rn(hv0, hv1);
            *(__half2*)&outh[(bR1 * TT + idx1) * 256 + ooff + hp] = hb;
            if (act1) *(__half2*)&hdst[(rr + 8) * HS_STRIDE + hp] = hb;
        }

        __syncthreads();   // single barrier: HS writes visible before next phase1
    }

    // barrier-free zero tail: positions [Lmax, TT) are zero for every row
    for (int step = Lmax; step < TT; ++step) {
        *(unsigned*)&outh[(bR0 * TT + step) * 256 + ooff + hp] = 0u;
        *(unsigned*)&outh[(bR1 * TT + step) * 256 + ooff + hp] = 0u;
    }
}

// ---------------------------------------------------------------------------
// Attention pooling (single pass, smem-resident tile): g_cur1h -> g_attb
// ---------------------------------------------------------------------------
#define ATT_TILE_BYTES (TT * 256 * 2)
#define ATT_WV_OFF  ATT_TILE_BYTES
#define ATT_E_OFF   (ATT_WV_OFF + 256 * 4)
#define ATT_RED_OFF (ATT_E_OFF + 176 * 4)
#define ATT_SMEM    (ATT_RED_OFF + 40 * 4)

__global__ __launch_bounds__(256) void att_kernel(
    const float* __restrict__ w_att, const float* __restrict__ b_att)
{
    extern __shared__ char asm_raw[];
    __half* tile = (__half*)(asm_raw);
    float*  wv   = (float*)(asm_raw + ATT_WV_OFF);
    float*  e_sm = (float*)(asm_raw + ATT_E_OFF);
    float*  red  = (float*)(asm_raw + ATT_RED_OFF);

    const int b = blockIdx.x;
    const int tid = threadIdx.x;
    wv[tid] = w_att[tid];

    const uint4* src = (const uint4*)&g_cur1h[(size_t)b * TT * 256];
    for (int i = tid; i < TT * 256 / 8; i += 256) {
        ((uint4*)tile)[i] = src[i];
    }
    __syncthreads();

    const int warp = tid >> 5;
    const int lane = tid & 31;

    for (int t = warp; t < TT; t += 8) {
        const __half* p = &tile[t * 256 + lane * 8];
        float s = 0.f;
#pragma unroll
        for (int j = 0; j < 4; ++j) {
            __half2 hh = *(const __half2*)(p + j * 2);
            float2 ff = __half22float2(hh);
            s += ff.x * wv[lane * 8 + j * 2] + ff.y * wv[lane * 8 + j * 2 + 1];
        }
#pragma unroll
        for (int off = 16; off > 0; off >>= 1) s += __shfl_down_sync(0xffffffffu, s, off);
        if (lane == 0) e_sm[t] = tanhf(s + b_att[0]);
    }
    __syncthreads();

    float m = -1e30f;
    for (int t = tid; t < TT; t += 256) m = fmaxf(m, e_sm[t]);
#pragma unroll
    for (int off = 16; off > 0; off >>= 1) m = fmaxf(m, __shfl_xor_sync(0xffffffffu, m, off));
    if (lane == 0) red[warp] = m;
    __syncthreads();
    if (tid == 0) {
        float mm = red[0];
        for (int w = 1; w < 8; ++w) mm = fmaxf(mm, red[w]);
        red[32] = mm;
    }
    __syncthreads();
    const float mx = red[32];

    float ssum = 0.f;
    for (int t = tid; t < TT; t += 256) {
        float p = expf(e_sm[t] - mx);
        e_sm[t] = p;
        ssum += p;
    }
#pragma unroll
    for (int off = 16; off > 0; off >>= 1) ssum += __shfl_xor_sync(0xffffffffu, ssum, off);
    if (lane == 0) red[warp] = ssum;
    __syncthreads();
    if (tid == 0) {
        float s2 = 0.f;
        for (int w = 0; w < 8; ++w) s2 += red[w];
        red[33] = s2;
    }
    __syncthreads();
    const float inv = 1.f / red[33];

    float acc = 0.f;
    const __half* base = &tile[tid];
    for (int t = 0; t < TT; ++t) {
        acc += e_sm[t] * __half2float(base[t * 256]);
    }
    g_attb[b * 256 + tid] = acc * inv;
}

// ---------------------------------------------------------------------------
// Classifier head: [g_sbuf, g_attb] -> out
// ---------------------------------------------------------------------------
__global__ __launch_bounds__(64) void head_kernel(
    const float* __restrict__ w1, const float* __restrict__ b1,
    const float* __restrict__ w2, const float* __restrict__ b2,
    float* __restrict__ out)
{
    const int b = blockIdx.x;
    const int tid = threadIdx.x;
    __shared__ float cat[272];
    __shared__ float h1[64];
    if (tid < 16) cat[tid] = g_sbuf[b * 16 + tid];
    for (int j = tid; j < 256; j += 64) cat[16 + j] = g_attb[b * 256 + j];
    __syncthreads();
    float a = b1[tid];
#pragma unroll 4
    for (int k = 0; k < 272; ++k) a += cat[k] * w1[k * 64 + tid];
    h1[tid] = fmaxf(a, 0.f);
    __syncthreads();
    if (tid < 32) {
        float a2 = b2[tid];
#pragma unroll
        for (int k = 0; k < 64; ++k) a2 += h1[k] * w2[k * 32 + tid];
        out[b * 32 + tid] = fmaxf(a2, 0.f);
    }
}

// ---------------------------------------------------------------------------
// Launch
// ---------------------------------------------------------------------------
extern "C" void kernel_launch(void* const* d_in, const int* in_sizes, int n_in,
                              void* d_out, int out_size)
{
    const float* x_static = (const float*)d_in[0];
    const float* x_dyn    = (const float*)d_in[1];
    const int*   seq      = (const int*)  d_in[2];
    const float* w_s0  = (const float*)d_in[3];
    const float* b_s0  = (const float*)d_in[4];
    const float* w_s1  = (const float*)d_in[5];
    const float* b_s1  = (const float*)d_in[6];
    const float* Wx_f0 = (const float*)d_in[7];
    const float* Wh_f0 = (const float*)d_in[8];
    const float* bb_f0 = (const float*)d_in[9];
    const float* Wx_b0 = (const float*)d_in[10];
    const float* Wh_b0 = (const float*)d_in[11];
    const float* bb_b0 = (const float*)d_in[12];
    const float* Wx_f1 = (const float*)d_in[13];
    const float* Wh_f1 = (const float*)d_in[14];
    const float* bb_f1 = (const float*)d_in[15];
    const float* Wx_b1 = (const float*)d_in[16];
    const float* Wh_b1 = (const float*)d_in[17];
    const float* bb_b1 = (const float*)d_in[18];
    const float* w_att = (const float*)d_in[19];
    const float* b_att = (const float*)d_in[20];
    const float* w_c1  = (const float*)d_in[21];
    const float* b_c1  = (const float*)d_in[22];
    const float* w_c2  = (const float*)d_in[23];
    const float* b_c2  = (const float*)d_in[24];
    float* out = (float*)d_out;

    cudaFuncSetAttribute(rec_mma, cudaFuncAttributeMaxDynamicSharedMemorySize, REC_SMEM);
    cudaFuncSetAttribute(att_kernel, cudaFuncAttributeMaxDynamicSharedMemorySize, ATT_SMEM);

    prep_kernel<<<256, 256>>>(Wh_f0, Wh_b0, Wh_f1, Wh_b1,
                              Wx_f0, Wx_b0, Wx_f1, Wx_b1,
                              bb_f0, bb_b0, bb_f1, bb_b1);
    static_kernel<<<(BATCH + 255) / 256, 256>>>(x_static, w_s0, b_s0, w_s1, b_s1);

    dim3 ggrid(8, MTOT / 64);
    xpre_gemm_mma<<<ggrid, 256>>>(x_dyn, FDYN, 0, seq);
    rec_mma<<<128, 512, REC_SMEM>>>(seq, 0);
    xpre_gemm_mma<<<ggrid, 256>>>(nullptr, 256, 1, seq);
    rec_mma<<<128, 512, REC_SMEM>>>(seq, 1);
    att_kernel<<<BATCH, 256, ATT_SMEM>>>(w_att, b_att);
    head_kernel<<<BATCH, 64>>>(w_c1, b_c1, w_c2, b_c2, out);
}

// round 15
// speedup vs baseline: 9.3350x; 1.0601x over previous
#include <cuda_runtime.h>
#include <cuda_fp16.h>
#include <cstdint>
#include <math.h>

// Problem constants
#define BATCH 1024
#define TT    169
#define FDYN  36
#define FSTAT 19
#define HID   128
#define MTOT  (BATCH * TT)

// ---------------------------------------------------------------------------
// Scratch (device globals)
// ---------------------------------------------------------------------------
__device__ __half g_xpre16[(size_t)MTOT * 1024];  // per-dir cols: [warp(16)][cbg(4)][gate(4)][2] interleave
__device__ __half g_cur0h[(size_t)MTOT * 256];
__device__ __half g_cur1h[(size_t)MTOT * 256];
__device__ float  g_sbuf[BATCH * 16];
__device__ float  g_attb[BATCH * 256];
__device__ __half g_wh16[4 * 128 * 512];   // column-REORDERED: col = (h>>3)*32 + gate*8 + (h&7)
__device__ __half g_wx0[36 * 1024];        // column-REORDERED for coalesced xpre reads
__device__ __half g_wx1[256 * 1024];       // (same interleave)
__device__ float  g_bx0[1024];             // bias in the same permuted order
__device__ float  g_bx1[1024];

// ---------------------------------------------------------------------------
// MMA / ldmatrix / fast-math helpers
// ---------------------------------------------------------------------------
__device__ __forceinline__ unsigned smem_u32(const void* p) {
    return (unsigned)__cvta_generic_to_shared(p);
}
__device__ __forceinline__ void ldsm_x4(unsigned& r0, unsigned& r1, unsigned& r2, unsigned& r3, unsigned a) {
    asm volatile("ldmatrix.sync.aligned.m8n8.x4.shared.b16 {%0,%1,%2,%3}, [%4];"
                 : "=r"(r0), "=r"(r1), "=r"(r2), "=r"(r3) : "r"(a));
}
__device__ __forceinline__ void ldsm_x4_t(unsigned& r0, unsigned& r1, unsigned& r2, unsigned& r3, unsigned a) {
    asm volatile("ldmatrix.sync.aligned.m8n8.x4.trans.shared.b16 {%0,%1,%2,%3}, [%4];"
                 : "=r"(r0), "=r"(r1), "=r"(r2), "=r"(r3) : "r"(a));
}
__device__ __forceinline__ void mma16816(float* c, unsigned a0, unsigned a1, unsigned a2, unsigned a3,
                                         unsigned b0, unsigned b1) {
    asm volatile("mma.sync.aligned.m16n8k16.row.col.f32.f16.f16.f32 "
                 "{%0,%1,%2,%3}, {%4,%5,%6,%7}, {%8,%9}, {%0,%1,%2,%3};"
                 : "+f"(c[0]), "+f"(c[1]), "+f"(c[2]), "+f"(c[3])
                 : "r"(a0), "r"(a1), "r"(a2), "r"(a3), "r"(b0), "r"(b1));
}
__device__ __forceinline__ float tanh_apx(float x) {
    float r; asm("tanh.approx.f32 %0, %1;" : "=f"(r) : "f"(x)); return r;
}
__device__ __forceinline__ float sig_apx(float x) {
    return fmaf(tanh_apx(0.5f * x), 0.5f, 0.5f);
}

// xpre column interleave within a direction: lane-contiguous 16B per (row, hp)
__device__ __forceinline__ int xpre_newc(int c) {
    int gate = c >> 7;
    int h = c & 127;
    return (h >> 3) * 32 + ((h & 7) >> 1) * 8 + gate * 2 + (h & 1);
}

// ---------------------------------------------------------------------------
// Weight conversion to fp16 (once per launch).
// Wh columns permuted for in-register gate handoff (gate*8 interleave).
// Wx columns + bias permuted for coalesced uint4 xpre reads in rec.
// ---------------------------------------------------------------------------
__global__ __launch_bounds__(256) void prep_kernel(
    const float* __restrict__ Wh_f0, const float* __restrict__ Wh_b0,
    const float* __restrict__ Wh_f1, const float* __restrict__ Wh_b1,
    const float* __restrict__ Wx_f0, const float* __restrict__ Wx_b0,
    const float* __restrict__ Wx_f1, const float* __restrict__ Wx_b1,
    const float* __restrict__ bb_f0, const float* __restrict__ bb_b0,
    const float* __restrict__ bb_f1, const float* __restrict__ bb_b1)
{
    const int N_WH = 4 * 65536;
    const int N_W0 = 36 * 1024;
    const int N_W1 = 256 * 1024;
    const int N_ALL = N_WH + N_W0 + N_W1 + 2048;
    for (int idx = blockIdx.x * 256 + threadIdx.x; idx < N_ALL; idx += gridDim.x * 256) {
        if (idx < N_WH) {
            int which = idx >> 16;
            int off = idx & 65535;
            int k = off >> 9;
            int c_orig = off & 511;
            int gate = c_orig >> 7;
            int h = c_orig & 127;
            int newc = (h >> 3) * 32 + gate * 8 + (h & 7);
            const float* src = (which == 0) ? Wh_f0 : (which == 1) ? Wh_b0 : (which == 2) ? Wh_f1 : Wh_b1;
            g_wh16[which * 65536 + k * 512 + newc] = __float2half(src[off]);
        } else if (idx < N_WH + N_W0) {
            int j = idx - N_WH;
            int k = j >> 10;
            int n = j & 1023;
            int dirbase = (n < 512) ? 0 : 512;
            int c = n & 511;
            float v = (n < 512) ? Wx_f0[k * 512 + c] : Wx_b0[k * 512 + c];
            g_wx0[k * 1024 + dirbase + xpre_newc(c)] = __float2half(v);
        } else if (idx < N_WH + N_W0 + N_W1) {
            int j = idx - N_WH - N_W0;
            int k = j >> 10;
            int n = j & 1023;
            int dirbase = (n < 512) ? 0 : 512;
            int c = n & 511;
            float v = (n < 512) ? Wx_f1[k * 512 + c] : Wx_b1[k * 512 + c];
            g_wx1[k * 1024 + dirbase + xpre_newc(c)] = __float2half(v);
        } else {
            int j = idx - N_WH - N_W0 - N_W1;
            int n = j & 1023;
            int dirbase = (n < 512) ? 0 : 512;
            int c = n & 511;
            if (j < 1024) {
                float v = (n < 512) ? bb_f0[c] : bb_b0[c];
                g_bx0[dirbase + xpre_newc(c)] = v;
            } else {
                float v = (n < 512) ? bb_f1[c] : bb_b1[c];
                g_bx1[dirbase + xpre_newc(c)] = v;
            }
        }
    }
}

// ---------------------------------------------------------------------------
// Static branch -> g_sbuf
// ---------------------------------------------------------------------------
__global__ __launch_bounds__(256) void static_kernel(
    const float* __restrict__ x, const float* __restrict__ w0, const float* __restrict__ b0,
    const float* __restrict__ w1, const float* __restrict__ b1)
{
    int b = blockIdx.x * blockDim.x + threadIdx.x;
    if (b >= BATCH) return;
    float xin[FSTAT];
#pragma unroll
    for (int i = 0; i < FSTAT; ++i) xin[i] = x[b * FSTAT + i];
    float h0[16];
#pragma unroll
    for (int j = 0; j < 16; ++j) {
        float a = b0[j];
#pragma unroll
        for (int i = 0; i < FSTAT; ++i) a += xin[i] * w0[i * 16 + j];
        h0[j] = fmaxf(a, 0.f);
    }
#pragma unroll
    for (int j = 0; j < 16; ++j) {
        float a = b1[j];
#pragma unroll
        for (int i = 0; i < 16; ++i) a += h0[i] * w1[i * 16 + j];
        g_sbuf[b * 16 + j] = fmaxf(a, 0.f);
    }
}

// ---------------------------------------------------------------------------
// Input-projection GEMM via mma -> g_xpre16 (columns already permuted via Bw).
// Grid: (8 N-blocks [x, fastest], 2704 M-tiles [y]).
// Epilogue stages the fp16 tile through smem so global stores are uint4,
// fully coalesced (16 threads = one contiguous 256B row).
// ---------------------------------------------------------------------------
#define STG_STRIDE 136

__global__ __launch_bounds__(256) void xpre_gemm_mma(
    const float* __restrict__ Afloat, int K, int layer,
    const int* __restrict__ seq_len)
{
    __shared__ __half A_sm[64 * 40];
    __shared__ __half B_sm[32 * 136];
    __shared__ __align__(16) __half Stage[64 * STG_STRIDE];

    const int m0 = blockIdx.y * 64;
    const int nb = blockIdx.x * 128;
    const int tid = threadIdx.x;

    int act = 0;
    if (tid < 64) {
        int m = m0 + tid;
        int bi = m / TT;
        int t = m - bi * TT;
        act = (t < seq_len[bi]) ? 1 : 0;
    }
    if (!__syncthreads_or(act)) return;

    const __half* Bw = (layer == 0) ? g_wx0 : g_wx1;
    const float* bias = (layer == 0) ? g_bx0 : g_bx1;

    const int warp = tid >> 5;
    const int lane = tid & 31;
    const int wy = warp >> 1;
    const int wx = warp & 1;

    float c[8][4];
#pragma unroll
    for (int i = 0; i < 8; ++i) {
#pragma unroll
        for (int j = 0; j < 4; ++j) c[i][j] = 0.f;
    }

    for (int k0 = 0; k0 < K; k0 += 32) {
        if (layer == 1) {
            int row = tid >> 2;
            int colc = (tid & 3) * 8;
            uint4 v = *(const uint4*)&g_cur0h[(size_t)(m0 + row) * 256 + k0 + colc];
            *(uint4*)&A_sm[row * 40 + colc] = v;
        } else {
#pragma unroll
            for (int j = 0; j < 8; ++j) {
                int i = tid + j * 256;
                int row = i >> 5;
                int col = i & 31;
                int k = k0 + col;
                __half hv = __float2half(0.f);
                if (k < K) hv = __float2half(Afloat[(size_t)(m0 + row) * K + k]);
                A_sm[row * 40 + col] = hv;
            }
        }
#pragma unroll
        for (int j = 0; j < 2; ++j) {
            int i = tid + j * 256;
            int row = i >> 4;
            int c8 = i & 15;
            int k = k0 + row;
            uint4 v = make_uint4(0u, 0u, 0u, 0u);
            if (k < K) v = *(const uint4*)&Bw[(size_t)k * 1024 + nb + c8 * 8];
            *(uint4*)&B_sm[row * 136 + c8 * 8] = v;
        }
        __syncthreads();

#pragma unroll
        for (int kk = 0; kk < 2; ++kk) {
            unsigned a0, a1, a2, a3;
            unsigned aaddr = smem_u32(&A_sm[(wy * 16 + (lane & 15)) * 40 + kk * 16 + (lane >> 4) * 8]);
            ldsm_x4(a0, a1, a2, a3, aaddr);
#pragma unroll
            for (int np = 0; np < 4; ++np) {
                unsigned q0, q1, q2, q3;
                unsigned baddr = smem_u32(&B_sm[(kk * 16 + (lane & 15)) * 136 + wx * 64 + np * 16 + (lane >> 4) * 8]);
                ldsm_x4_t(q0, q1, q2, q3, baddr);
                mma16816(c[np * 2],     a0, a1, a2, a3, q0, q1);
                mma16816(c[np * 2 + 1], a0, a1, a2, a3, q2, q3);
            }
        }
        __syncthreads();
    }

    // epilogue: bias add -> fp16 -> smem stage -> coalesced uint4 stores
    const int r = lane >> 2;
    const int cb2 = (lane & 3) * 2;
#pragma unroll
    for (int nt = 0; nt < 8; ++nt) {
        int col = wx * 64 + nt * 8 + cb2;
        float bx = bias[nb + col];
        float by = bias[nb + col + 1];
        __half2 lo = __floats2half2_rn(c[nt][0] + bx, c[nt][1] + by);
        __half2 hi = __floats2half2_rn(c[nt][2] + bx, c[nt][3] + by);
        *(__half2*)&Stage[(wy * 16 + r) * STG_STRIDE + col]     = lo;
        *(__half2*)&Stage[(wy * 16 + r + 8) * STG_STRIDE + col] = hi;
    }
    __syncthreads();
#pragma unroll
    for (int j = 0; j < 4; ++j) {
        int idx = tid + j * 256;             // 1024 uint4 = 64 rows x 128 cols
        int row = idx >> 4;
        int colc = (idx & 15) * 8;
        *(uint4*)&g_xpre16[(size_t)(m0 + row) * 1024 + nb + colc] =
            *(const uint4*)&Stage[row * STG_STRIDE + colc];
    }
}

// ---------------------------------------------------------------------------
// Persistent recurrent kernel v6 — in-register gate handoff + coalesced xpre.
// 512 threads (16 warps), 128 blocks (0..63 fw, 64..127 bw), 16 batch rows.
// xpre read as ONE uint4 per (row, lane): (i0,i1,j0,j1,f0,f1,o0,o1).
// ---------------------------------------------------------------------------
#define WH_STRIDE 520
#define HS_STRIDE 136
#define HS_BUFSZ  (16 * HS_STRIDE)            // halves per buffer
#define SM_HS_OFF 133120
#define SM_LS_OFF (SM_HS_OFF + 2 * HS_BUFSZ * 2)
#define REC_SMEM  (SM_LS_OFF + 128)

__global__ __launch_bounds__(512) void rec_mma(const int* __restrict__ seq_len, int layer)
{
    extern __shared__ char smraw[];
    __half* WH = (__half*)(smraw);
    __half* HS = (__half*)(smraw + SM_HS_OFF);   // two ping-pong buffers
    int*    LS = (int*)(smraw + SM_LS_OFF);

    const int blk = blockIdx.x;
    const int dir = blk >> 6;
    const int b0 = (blk & 63) * 16;
    const int xoff = dir * 512;
    const int ooff = dir * 128;
    const int tid = threadIdx.x;

    __half* outh = (layer == 0) ? g_cur0h : g_cur1h;

    // stage (reordered) Wh into smem once
    const __half* wg = g_wh16 + (size_t)(layer * 2 + dir) * 65536;
#pragma unroll 4
    for (int i = tid; i < 8192; i += 512) {
        int r = i >> 6;
        int c8 = i & 63;
        *(uint4*)&WH[r * WH_STRIDE + c8 * 8] = ((const uint4*)wg)[i];
    }
    for (int i = tid; i < HS_BUFSZ; i += 512) { ((unsigned*)HS)[i] = 0u; }  // both buffers
    if (tid < 16) LS[tid] = seq_len[b0 + tid];
    __syncthreads();
    if (tid == 0) {
        int m = 0;
#pragma unroll
        for (int i = 0; i < 16; ++i) m = max(m, LS[i]);
        LS[16] = m;
    }
    __syncthreads();
    const int Lmax = LS[16];

    const int warp = tid >> 5;
    const int lane = tid & 31;
    const int n_base = warp * 32;
    const int arow = lane & 15;
    const int acol8 = (lane >> 4) * 8;

    // load Wh B-fragments into registers (once)
    unsigned bfr[8][8];
#pragma unroll
    for (int kk = 0; kk < 8; ++kk) {
#pragma unroll
        for (int nt2 = 0; nt2 < 2; ++nt2) {
            unsigned baddr = smem_u32(&WH[(kk * 16 + arow) * WH_STRIDE + n_base + nt2 * 16 + acol8]);
            ldsm_x4_t(bfr[kk][nt2 * 4 + 0], bfr[kk][nt2 * 4 + 1],
                      bfr[kk][nt2 * 4 + 2], bfr[kk][nt2 * 4 + 3], baddr);
        }
    }

    // cell ownership
    const int rr = lane >> 2;
    const int cb = (lane & 3) * 2;
    const int hp = warp * 8 + cb;                  // hidden pair base (output layout)
    const int xcol = xoff + warp * 32 + (cb >> 1) * 8;  // xpre interleaved column
    const int L0 = LS[rr];
    const int L1 = LS[rr + 8];
    const size_t bR0 = (size_t)(b0 + rr);
    const size_t bR1 = (size_t)(b0 + rr + 8);

    float c_reg[4] = {0.f, 0.f, 0.f, 0.f};  // (r0,h0),(r0,h1),(r1,h0),(r1,h1)

    for (int step = 0; step < Lmax; ++step) {
        const bool act0 = (step < L0);
        const bool act1 = (step < L1);
        const int idx0 = act0 ? (dir ? (L0 - 1 - step) : step) : step;
        const int idx1 = act1 ? (dir ? (L1 - 1 - step) : step) : step;

        // coalesced xpre loads (one uint4 per row; latency hidden under MMA)
        uint4 xv0 = make_uint4(0u, 0u, 0u, 0u);
        uint4 xv1 = make_uint4(0u, 0u, 0u, 0u);
        if (act0) xv0 = *(const uint4*)(g_xpre16 + (bR0 * TT + idx0) * 1024 + xcol);
        if (act1) xv1 = *(const uint4*)(g_xpre16 + (bR1 * TT + idx1) * 1024 + xcol);

        // ---- phase1: gates in registers via mma ----
        float c[4][4];
#pragma unroll
        for (int i = 0; i < 4; ++i) {
#pragma unroll
            for (int j = 0; j < 4; ++j) c[i][j] = 0.f;
        }
        {
            const __half* hsrc = HS + (step & 1) * HS_BUFSZ;
#pragma unroll
            for (int kk = 0; kk < 8; ++kk) {
                unsigned a0, a1, a2, a3;
                unsigned aaddr = smem_u32(&hsrc[arow * HS_STRIDE + kk * 16 + acol8]);
                ldsm_x4(a0, a1, a2, a3, aaddr);
                mma16816(c[0], a0, a1, a2, a3, bfr[kk][0], bfr[kk][1]);   // gate i
                mma16816(c[1], a0, a1, a2, a3, bfr[kk][2], bfr[kk][3]);   // gate j
                mma16816(c[2], a0, a1, a2, a3, bfr[kk][4], bfr[kk][5]);   // gate f
                mma16816(c[3], a0, a1, a2, a3, bfr[kk][6], bfr[kk][7]);   // gate o
            }
        }

        // ---- phase2: cell update straight from accumulators ----
        __half* hdst = HS + ((step + 1) & 1) * HS_BUFSZ;

        {   // row rr
            float2 xi = __half22float2(*(__half2*)&xv0.x);
            float2 xj = __half22float2(*(__half2*)&xv0.y);
            float2 xf = __half22float2(*(__half2*)&xv0.z);
            float2 xo = __half22float2(*(__half2*)&xv0.w);
            float hv0 = 0.f, hv1 = 0.f;
            if (act0) {
                float gi0 = c[0][0] + xi.x, gi1 = c[0][1] + xi.y;
                float gj0 = c[1][0] + xj.x, gj1 = c[1][1] + xj.y;
                float gf0 = c[2][0] + xf.x + 1.f, gf1 = c[2][1] + xf.y + 1.f;
                float go0 = c[3][0] + xo.x, go1 = c[3][1] + xo.y;
                float cn0 = fmaf(c_reg[0], sig_apx(gf0), sig_apx(gi0) * tanh_apx(gj0));
                float cn1 = fmaf(c_reg[1], sig_apx(gf1), sig_apx(gi1) * tanh_apx(gj1));
                c_reg[0] = cn0; c_reg[1] = cn1;
                hv0 = tanh_apx(cn0) * sig_apx(go0);
                hv1 = tanh_apx(cn1) * sig_apx(go1);
            }
            __half2 hb = __floats2half2_rn(hv0, hv1);
            *(__half2*)&outh[(bR0 * TT + idx0) * 256 + ooff + hp] = hb;
            if (act0) *(__half2*)&hdst[rr * HS_STRIDE + hp] = hb;
        }
        {   // row rr+8
            float2 xi = __half22float2(*(__half2*)&xv1.x);
            float2 xj = __half22float2(*(__half2*)&xv1.y);
            float2 xf = __half22float2(*(__half2*)&xv1.z);
            float2 xo = __half22float2(*(__half2*)&xv1.w);
            float hv0 = 0.f, hv1 = 0.f;
            if (act1) {
                float gi0 = c[0][2] + xi.x, gi1 = c[0][3] + xi.y;
                float gj0 = c[1][2] + xj.x, gj1 = c[1][3] + xj.y;
                float gf0 = c[2][2] + xf.x + 1.f, gf1 = c[2][3] + xf.y + 1.f;
                float go0 = c[3][2] + xo.x, go1 = c[3][3] + xo.y;
                float cn0 = fmaf(c_reg[2], sig_apx(gf0), sig_apx(gi0) * tanh_apx(gj0));
                float cn1 = fmaf(c_reg[3], sig_apx(gf1), sig_apx(gi1) * tanh_apx(gj1));
                c_reg[2] = cn0; c_reg[3] = cn1;
                hv0 = tanh_apx(cn0) * sig_apx(go0);
                hv1 = tanh_apx(cn1) * sig_apx(go1);
            }
            __half2 hb = __floats2half2_rn(hv0, hv1);
            *(__half2*)&outh[(bR1 * TT + idx1) * 256 + ooff + hp] = hb;
            if (act1) *(__half2*)&hdst[(rr + 8) * HS_STRIDE + hp] = hb;
        }

        __syncthreads();   // single barrier: HS writes visible before next phase1
    }

    // barrier-free zero tail: positions [Lmax, TT) are zero for every row
    for (int step = Lmax; step < TT; ++step) {
        *(unsigned*)&outh[(bR0 * TT + step) * 256 + ooff + hp] = 0u;
        *(unsigned*)&outh[(bR1 * TT + step) * 256 + ooff + hp] = 0u;
    }
}

// ---------------------------------------------------------------------------
// Attention pooling (single pass, smem-resident tile): g_cur1h -> g_attb
// ---------------------------------------------------------------------------
#define ATT_TILE_BYTES (TT * 256 * 2)
#define ATT_WV_OFF  ATT_TILE_BYTES
#define ATT_E_OFF   (ATT_WV_OFF + 256 * 4)
#define ATT_RED_OFF (ATT_E_OFF + 176 * 4)
#define ATT_SMEM    (ATT_RED_OFF + 40 * 4)

__global__ __launch_bounds__(256) void att_kernel(
    const float* __restrict__ w_att, const float* __restrict__ b_att)
{
    extern __shared__ char asm_raw[];
    __half* tile = (__half*)(asm_raw);
    float*  wv   = (float*)(asm_raw + ATT_WV_OFF);
    float*  e_sm = (float*)(asm_raw + ATT_E_OFF);
    float*  red  = (float*)(asm_raw + ATT_RED_OFF);

    const int b = blockIdx.x;
    const int tid = threadIdx.x;
    wv[tid] = w_att[tid];

    const uint4* src = (const uint4*)&g_cur1h[(size_t)b * TT * 256];
    for (int i = tid; i < TT * 256 / 8; i += 256) {
        ((uint4*)tile)[i] = src[i];
    }
    __syncthreads();

    const int warp = tid >> 5;
    const int lane = tid & 31;

    for (int t = warp; t < TT; t += 8) {
        const __half* p = &tile[t * 256 + lane * 8];
        float s = 0.f;
#pragma unroll
        for (int j = 0; j < 4; ++j) {
            __half2 hh = *(const __half2*)(p + j * 2);
            float2 ff = __half22float2(hh);
            s += ff.x * wv[lane * 8 + j * 2] + ff.y * wv[lane * 8 + j * 2 + 1];
        }
#pragma unroll
        for (int off = 16; off > 0; off >>= 1) s += __shfl_down_sync(0xffffffffu, s, off);
        if (lane == 0) e_sm[t] = tanhf(s + b_att[0]);
    }
    __syncthreads();

    float m = -1e30f;
    for (int t = tid; t < TT; t += 256) m = fmaxf(m, e_sm[t]);
#pragma unroll
    for (int off = 16; off > 0; off >>= 1) m = fmaxf(m, __shfl_xor_sync(0xffffffffu, m, off));
    if (lane == 0) red[warp] = m;
    __syncthreads();
    if (tid == 0) {
        float mm = red[0];
        for (int w = 1; w < 8; ++w) mm = fmaxf(mm, red[w]);
        red[32] = mm;
    }
    __syncthreads();
    const float mx = red[32];

    float ssum = 0.f;
    for (int t = tid; t < TT; t += 256) {
        float p = expf(e_sm[t] - mx);
        e_sm[t] = p;
        ssum += p;
    }
#pragma unroll
    for (int off = 16; off > 0; off >>= 1) ssum += __shfl_xor_sync(0xffffffffu, ssum, off);
    if (lane == 0) red[warp] = ssum;
    __syncthreads();
    if (tid == 0) {
        float s2 = 0.f;
        for (int w = 0; w < 8; ++w) s2 += red[w];
        red[33] = s2;
    }
    __syncthreads();
    const float inv = 1.f / red[33];

    float acc = 0.f;
    const __half* base = &tile[tid];
    for (int t = 0; t < TT; ++t) {
        acc += e_sm[t] * __half2float(base[t * 256]);
    }
    g_attb[b * 256 + tid] = acc * inv;
}

// ---------------------------------------------------------------------------
// Classifier head: [g_sbuf, g_attb] -> out
// ---------------------------------------------------------------------------
__global__ __launch_bounds__(64) void head_kernel(
    const float* __restrict__ w1, const float* __restrict__ b1,
    const float* __restrict__ w2, const float* __restrict__ b2,
    float* __restrict__ out)
{
    const int b = blockIdx.x;
    const int tid = threadIdx.x;
    __shared__ float cat[272];
    __shared__ float h1[64];
    if (tid < 16) cat[tid] = g_sbuf[b * 16 + tid];
    for (int j = tid; j < 256; j += 64) cat[16 + j] = g_attb[b * 256 + j];
    __syncthreads();
    float a = b1[tid];
#pragma unroll 4
    for (int k = 0; k < 272; ++k) a += cat[k] * w1[k * 64 + tid];
    h1[tid] = fmaxf(a, 0.f);
    __syncthreads();
    if (tid < 32) {
        float a2 = b2[tid];
#pragma unroll
        for (int k = 0; k < 64; ++k) a2 += h1[k] * w2[k * 32 + tid];
        out[b * 32 + tid] = fmaxf(a2, 0.f);
    }
}

// ---------------------------------------------------------------------------
// Launch
// ---------------------------------------------------------------------------
extern "C" void kernel_launch(void* const* d_in, const int* in_sizes, int n_in,
                              void* d_out, int out_size)
{
    const float* x_static = (const float*)d_in[0];
    const float* x_dyn    = (const float*)d_in[1];
    const int*   seq      = (const int*)  d_in[2];
    const float* w_s0  = (const float*)d_in[3];
    const float* b_s0  = (const float*)d_in[4];
    const float* w_s1  = (const float*)d_in[5];
    const float* b_s1  = (const float*)d_in[6];
    const float* Wx_f0 = (const float*)d_in[7];
    const float* Wh_f0 = (const float*)d_in[8];
    const float* bb_f0 = (const float*)d_in[9];
    const float* Wx_b0 = (const float*)d_in[10];
    const float* Wh_b0 = (const float*)d_in[11];
    const float* bb_b0 = (const float*)d_in[12];
    const float* Wx_f1 = (const float*)d_in[13];
    const float* Wh_f1 = (const float*)d_in[14];
    const float* bb_f1 = (const float*)d_in[15];
    const float* Wx_b1 = (const float*)d_in[16];
    const float* Wh_b1 = (const float*)d_in[17];
    const float* bb_b1 = (const float*)d_in[18];
    const float* w_att = (const float*)d_in[19];
    const float* b_att = (const float*)d_in[20];
    const float* w_c1  = (const float*)d_in[21];
    const float* b_c1  = (const float*)d_in[22];
    const float* w_c2  = (const float*)d_in[23];
    const float* b_c2  = (const float*)d_in[24];
    float* out = (float*)d_out;

    cudaFuncSetAttribute(rec_mma, cudaFuncAttributeMaxDynamicSharedMemorySize, REC_SMEM);
    cudaFuncSetAttribute(att_kernel, cudaFuncAttributeMaxDynamicSharedMemorySize, ATT_SMEM);

    prep_kernel<<<256, 256>>>(Wh_f0, Wh_b0, Wh_f1, Wh_b1,
                              Wx_f0, Wx_b0, Wx_f1, Wx_b1,
                              bb_f0, bb_b0, bb_f1, bb_b1);
    static_kernel<<<(BATCH + 255) / 256, 256>>>(x_static, w_s0, b_s0, w_s1, b_s1);

    dim3 ggrid(8, MTOT / 64);
    xpre_gemm_mma<<<ggrid, 256>>>(x_dyn, FDYN, 0, seq);
    rec_mma<<<128, 512, REC_SMEM>>>(seq, 0);
    xpre_gemm_mma<<<ggrid, 256>>>(nullptr, 256, 1, seq);
    rec_mma<<<128, 512, REC_SMEM>>>(seq, 1);
    att_kernel<<<BATCH, 256, ATT_SMEM>>>(w_att, b_att);
    head_kernel<<<BATCH, 64>>>(w_c1, b_c1, w_c2, b_c2, out);
}

// round 16
// speedup vs baseline: 10.9854x; 1.1768x over previous
#include <cuda_runtime.h>
#include <cuda_fp16.h>
#include <cstdint>
#include <math.h>

// Problem constants
#define BATCH 1024
#define TT    169
#define FDYN  36
#define FSTAT 19
#define HID   128
#define MTOT  (BATCH * TT)

// ---------------------------------------------------------------------------
// Scratch (device globals)
// ---------------------------------------------------------------------------
__device__ __half g_xpre16[(size_t)MTOT * 1024];  // per-dir cols: interleaved (see xpre_newc)
__device__ __half g_cur0h[(size_t)MTOT * 256];
__device__ __half g_cur1h[(size_t)MTOT * 256];
__device__ float  g_sbuf[BATCH * 16];
__device__ float  g_attb[BATCH * 256];
__device__ __half g_wh16[4 * 128 * 512];   // column-REORDERED: col = (h>>3)*32 + gate*8 + (h&7)
__device__ __half g_wx0[36 * 1024];        // column-REORDERED for coalesced xpre reads
__device__ __half g_wx1[256 * 1024];
__device__ float  g_bx0[1024];
__device__ float  g_bx1[1024];

// ---------------------------------------------------------------------------
// MMA / ldmatrix / fast-math helpers
// ---------------------------------------------------------------------------
__device__ __forceinline__ unsigned smem_u32(const void* p) {
    return (unsigned)__cvta_generic_to_shared(p);
}
__device__ __forceinline__ void ldsm_x4(unsigned& r0, unsigned& r1, unsigned& r2, unsigned& r3, unsigned a) {
    asm volatile("ldmatrix.sync.aligned.m8n8.x4.shared.b16 {%0,%1,%2,%3}, [%4];"
                 : "=r"(r0), "=r"(r1), "=r"(r2), "=r"(r3) : "r"(a));
}
__device__ __forceinline__ void ldsm_x4_t(unsigned& r0, unsigned& r1, unsigned& r2, unsigned& r3, unsigned a) {
    asm volatile("ldmatrix.sync.aligned.m8n8.x4.trans.shared.b16 {%0,%1,%2,%3}, [%4];"
                 : "=r"(r0), "=r"(r1), "=r"(r2), "=r"(r3) : "r"(a));
}
__device__ __forceinline__ void mma16816(float* c, unsigned a0, unsigned a1, unsigned a2, unsigned a3,
                                         unsigned b0, unsigned b1) {
    asm volatile("mma.sync.aligned.m16n8k16.row.col.f32.f16.f16.f32 "
                 "{%0,%1,%2,%3}, {%4,%5,%6,%7}, {%8,%9}, {%0,%1,%2,%3};"
                 : "+f"(c[0]), "+f"(c[1]), "+f"(c[2]), "+f"(c[3])
                 : "r"(a0), "r"(a1), "r"(a2), "r"(a3), "r"(b0), "r"(b1));
}
__device__ __forceinline__ void cp_async16(unsigned dst, const void* src) {
    asm volatile("cp.async.cg.shared.global [%0], [%1], 16;" :: "r"(dst), "l"(src));
}
__device__ __forceinline__ float tanh_apx(float x) {
    float r; asm("tanh.approx.f32 %0, %1;" : "=f"(r) : "f"(x)); return r;
}
__device__ __forceinline__ float sig_apx(float x) {
    return fmaf(tanh_apx(0.5f * x), 0.5f, 0.5f);
}

// xpre column interleave within a direction: lane-contiguous 16B per (row, hp)
__device__ __forceinline__ int xpre_newc(int c) {
    int gate = c >> 7;
    int h = c & 127;
    return (h >> 3) * 32 + ((h & 7) >> 1) * 8 + gate * 2 + (h & 1);
}

// ---------------------------------------------------------------------------
// Weight conversion to fp16 (once per launch).
// ---------------------------------------------------------------------------
__global__ __launch_bounds__(256) void prep_kernel(
    const float* __restrict__ Wh_f0, const float* __restrict__ Wh_b0,
    const float* __restrict__ Wh_f1, const float* __restrict__ Wh_b1,
    const float* __restrict__ Wx_f0, const float* __restrict__ Wx_b0,
    const float* __restrict__ Wx_f1, const float* __restrict__ Wx_b1,
    const float* __restrict__ bb_f0, const float* __restrict__ bb_b0,
    const float* __restrict__ bb_f1, const float* __restrict__ bb_b1)
{
    const int N_WH = 4 * 65536;
    const int N_W0 = 36 * 1024;
    const int N_W1 = 256 * 1024;
    const int N_ALL = N_WH + N_W0 + N_W1 + 2048;
    for (int idx = blockIdx.x * 256 + threadIdx.x; idx < N_ALL; idx += gridDim.x * 256) {
        if (idx < N_WH) {
            int which = idx >> 16;
            int off = idx & 65535;
            int k = off >> 9;
            int c_orig = off & 511;
            int gate = c_orig >> 7;
            int h = c_orig & 127;
            int newc = (h >> 3) * 32 + gate * 8 + (h & 7);
            const float* src = (which == 0) ? Wh_f0 : (which == 1) ? Wh_b0 : (which == 2) ? Wh_f1 : Wh_b1;
            g_wh16[which * 65536 + k * 512 + newc] = __float2half(src[off]);
        } else if (idx < N_WH + N_W0) {
            int j = idx - N_WH;
            int k = j >> 10;
            int n = j & 1023;
            int dirbase = (n < 512) ? 0 : 512;
            int c = n & 511;
            float v = (n < 512) ? Wx_f0[k * 512 + c] : Wx_b0[k * 512 + c];
            g_wx0[k * 1024 + dirbase + xpre_newc(c)] = __float2half(v);
        } else if (idx < N_WH + N_W0 + N_W1) {
            int j = idx - N_WH - N_W0;
            int k = j >> 10;
            int n = j & 1023;
            int dirbase = (n < 512) ? 0 : 512;
            int c = n & 511;
            float v = (n < 512) ? Wx_f1[k * 512 + c] : Wx_b1[k * 512 + c];
            g_wx1[k * 1024 + dirbase + xpre_newc(c)] = __float2half(v);
        } else {
            int j = idx - N_WH - N_W0 - N_W1;
            int n = j & 1023;
            int dirbase = (n < 512) ? 0 : 512;
            int c = n & 511;
            if (j < 1024) {
                float v = (n < 512) ? bb_f0[c] : bb_b0[c];
                g_bx0[dirbase + xpre_newc(c)] = v;
            } else {
                float v = (n < 512) ? bb_f1[c] : bb_b1[c];
                g_bx1[dirbase + xpre_newc(c)] = v;
            }
        }
    }
}

// ---------------------------------------------------------------------------
// Static branch -> g_sbuf
// ---------------------------------------------------------------------------
__global__ __launch_bounds__(256) void static_kernel(
    const float* __restrict__ x, const float* __restrict__ w0, const float* __restrict__ b0,
    const float* __restrict__ w1, const float* __restrict__ b1)
{
    int b = blockIdx.x * blockDim.x + threadIdx.x;
    if (b >= BATCH) return;
    float xin[FSTAT];
#pragma unroll
    for (int i = 0; i < FSTAT; ++i) xin[i] = x[b * FSTAT + i];
    float h0[16];
#pragma unroll
    for (int j = 0; j < 16; ++j) {
        float a = b0[j];
#pragma unroll
        for (int i = 0; i < FSTAT; ++i) a += xin[i] * w0[i * 16 + j];
        h0[j] = fmaxf(a, 0.f);
    }
#pragma unroll
    for (int j = 0; j < 16; ++j) {
        float a = b1[j];
#pragma unroll
        for (int i = 0; i < 16; ++i) a += h0[i] * w1[i * 16 + j];
        g_sbuf[b * 16 + j] = fmaxf(a, 0.f);
    }
}

// ---------------------------------------------------------------------------
// Input-projection GEMM v2 -> g_xpre16.
// BM=128, BN=128, BK=32; 256 threads (8 warps, warp tile 32x64);
// cp.async 2-stage double buffer; inactive-row store skip.
// Grid: (8 N-blocks [x], 1352 M-tiles [y]).
// ---------------------------------------------------------------------------
#define GA_STRIDE 40
#define GB_STRIDE 136
#define GA_BUF    (128 * GA_STRIDE)     // halves per stage
#define GB_BUF    (32 * GB_STRIDE)
#define GB_OFF    20480                  // bytes: 2 * GA_BUF * 2
#define GACT_OFF  37888                  // bytes: GB_OFF + 2 * GB_BUF * 2

__global__ __launch_bounds__(256) void xpre_gemm2(
    const float* __restrict__ Afloat, int K, int layer,
    const int* __restrict__ seq_len)
{
    __shared__ __align__(16) char gsm[38016];
    __half* A_sm = (__half*)(gsm);
    __half* B_sm = (__half*)(gsm + GB_OFF);
    char*   actf = (char*)(gsm + GACT_OFF);
    __half* Stage = (__half*)(gsm);      // epilogue alias (loop finished)

    const int m0 = blockIdx.y * 128;
    const int nb = blockIdx.x * 128;
    const int tid = threadIdx.x;

    // per-row activity flags + tile skip
    if (tid < 128) {
        int m = m0 + tid;
        int bi = m / TT;
        int t = m - bi * TT;
        actf[tid] = (t < seq_len[bi]) ? 1 : 0;
    }
    __syncthreads();
    int anyact = (tid < 128) ? actf[tid] : 0;
    if (!__syncthreads_or(anyact)) return;

    const __half* Bw = (layer == 0) ? g_wx0 : g_wx1;
    const float* bias = (layer == 0) ? g_bx0 : g_bx1;
    const int niter = (K + 31) / 32;

    const int warp = tid >> 5;
    const int lane = tid & 31;
    const int wy = warp >> 1;       // 0..3 -> rows wy*32
    const int wx = warp & 1;        // 0..1 -> cols wx*64

    // stage loader: k-chunk `it` into buffers it&1
    auto load_stage = [&](int it) {
        const int k0 = it * 32;
        __half* As = A_sm + (it & 1) * GA_BUF;
        __half* Bs = B_sm + (it & 1) * GB_BUF;
        if (layer == 1) {
#pragma unroll
            for (int j = 0; j < 2; ++j) {
                int idx = tid + j * 256;          // 512 uint4
                int row = idx >> 2;
                int colc = (idx & 3) * 8;
                cp_async16(smem_u32(&As[row * GA_STRIDE + colc]),
                           &g_cur0h[(size_t)(m0 + row) * 256 + k0 + colc]);
            }
        } else {
#pragma unroll
            for (int j = 0; j < 16; ++j) {
                int idx = tid + j * 256;          // 4096 halves
                int row = idx >> 5;
                int col = idx & 31;
                int k = k0 + col;
                __half hv = __float2half(0.f);
                if (k < K) hv = __float2half(Afloat[(size_t)(m0 + row) * K + k]);
                As[row * GA_STRIDE + col] = hv;
            }
        }
#pragma unroll
        for (int j = 0; j < 2; ++j) {
            int idx = tid + j * 256;              // 512 uint4
            int row = idx >> 4;
            int colc = (idx & 15) * 8;
            int k = k0 + row;
            if (k < K) {
                cp_async16(smem_u32(&Bs[row * GB_STRIDE + colc]),
                           &Bw[(size_t)k * 1024 + nb + colc]);
            } else {
                *(uint4*)&Bs[row * GB_STRIDE + colc] = make_uint4(0u, 0u, 0u, 0u);
            }
        }
        asm volatile("cp.async.commit_group;");
    };

    float c[2][8][4];
#pragma unroll
    for (int mr = 0; mr < 2; ++mr)
#pragma unroll
        for (int i = 0; i < 8; ++i)
#pragma unroll
            for (int j = 0; j < 4; ++j) c[mr][i][j] = 0.f;

    load_stage(0);

    for (int it = 0; it < niter; ++it) {
        if (it + 1 < niter) {
            load_stage(it + 1);
            asm volatile("cp.async.wait_group 1;");
        } else {
            asm volatile("cp.async.wait_group 0;");
        }
        __syncthreads();

        const __half* As = A_sm + (it & 1) * GA_BUF;
        const __half* Bs = B_sm + (it & 1) * GB_BUF;
#pragma unroll
        for (int kk = 0; kk < 2; ++kk) {
            unsigned a[2][4];
#pragma unroll
            for (int mr = 0; mr < 2; ++mr) {
                unsigned aaddr = smem_u32(&As[(wy * 32 + mr * 16 + (lane & 15)) * GA_STRIDE
                                              + kk * 16 + (lane >> 4) * 8]);
                ldsm_x4(a[mr][0], a[mr][1], a[mr][2], a[mr][3], aaddr);
            }
#pragma unroll
            for (int nc = 0; nc < 4; ++nc) {
                unsigned q0, q1, q2, q3;
                unsigned baddr = smem_u32(&Bs[(kk * 16 + (lane & 15)) * GB_STRIDE
                                              + wx * 64 + nc * 16 + (lane >> 4) * 8]);
                ldsm_x4_t(q0, q1, q2, q3, baddr);
#pragma unroll
                for (int mr = 0; mr < 2; ++mr) {
                    mma16816(c[mr][nc * 2],     a[mr][0], a[mr][1], a[mr][2], a[mr][3], q0, q1);
                    mma16816(c[mr][nc * 2 + 1], a[mr][0], a[mr][1], a[mr][2], a[mr][3], q2, q3);
                }
            }
        }
        __syncthreads();
    }

    // epilogue: bias -> fp16 -> smem stage (aliases A/B) -> coalesced stores
    const int r = lane >> 2;
    const int cb2 = (lane & 3) * 2;
#pragma unroll
    for (int mr = 0; mr < 2; ++mr) {
#pragma unroll
        for (int nc2 = 0; nc2 < 8; ++nc2) {
            int col = wx * 64 + nc2 * 8 + cb2;
            float bx = bias[nb + col];
            float by = bias[nb + col + 1];
            int row = wy * 32 + mr * 16 + r;
            __half2 lo = __floats2half2_rn(c[mr][nc2][0] + bx, c[mr][nc2][1] + by);
            __half2 hi = __floats2half2_rn(c[mr][nc2][2] + bx, c[mr][nc2][3] + by);
            *(__half2*)&Stage[row * GB_STRIDE + col]       = lo;
            *(__half2*)&Stage[(row + 8) * GB_STRIDE + col] = hi;
        }
    }
    __syncthreads();
#pragma unroll
    for (int j = 0; j < 8; ++j) {
        int idx = tid + j * 256;                  // 2048 uint4 = 128 rows x 128 cols
        int row = idx >> 4;
        int colc = (idx & 15) * 8;
        if (actf[row]) {
            *(uint4*)&g_xpre16[(size_t)(m0 + row) * 1024 + nb + colc] =
                *(const uint4*)&Stage[row * GB_STRIDE + colc];
        }
    }
}

// ---------------------------------------------------------------------------
// Persistent recurrent kernel v6 — in-register gate handoff + coalesced xpre.
// 512 threads (16 warps), 128 blocks (0..63 fw, 64..127 bw), 16 batch rows.
// ---------------------------------------------------------------------------
#define WH_STRIDE 520
#define HS_STRIDE 136
#define HS_BUFSZ  (16 * HS_STRIDE)            // halves per buffer
#define SM_HS_OFF 133120
#define SM_LS_OFF (SM_HS_OFF + 2 * HS_BUFSZ * 2)
#define REC_SMEM  (SM_LS_OFF + 128)

__global__ __launch_bounds__(512) void rec_mma(const int* __restrict__ seq_len, int layer)
{
    extern __shared__ char smraw[];
    __half* WH = (__half*)(smraw);
    __half* HS = (__half*)(smraw + SM_HS_OFF);   // two ping-pong buffers
    int*    LS = (int*)(smraw + SM_LS_OFF);

    const int blk = blockIdx.x;
    const int dir = blk >> 6;
    const int b0 = (blk & 63) * 16;
    const int xoff = dir * 512;
    const int ooff = dir * 128;
    const int tid = threadIdx.x;

    __half* outh = (layer == 0) ? g_cur0h : g_cur1h;

    // stage (reordered) Wh into smem once
    const __half* wg = g_wh16 + (size_t)(layer * 2 + dir) * 65536;
#pragma unroll 4
    for (int i = tid; i < 8192; i += 512) {
        int r = i >> 6;
        int c8 = i & 63;
        *(uint4*)&WH[r * WH_STRIDE + c8 * 8] = ((const uint4*)wg)[i];
    }
    for (int i = tid; i < HS_BUFSZ; i += 512) { ((unsigned*)HS)[i] = 0u; }  // both buffers
    if (tid < 16) LS[tid] = seq_len[b0 + tid];
    __syncthreads();
    if (tid == 0) {
        int m = 0;
#pragma unroll
        for (int i = 0; i < 16; ++i) m = max(m, LS[i]);
        LS[16] = m;
    }
    __syncthreads();
    const int Lmax = LS[16];

    const int warp = tid >> 5;
    const int lane = tid & 31;
    const int n_base = warp * 32;
    const int arow = lane & 15;
    const int acol8 = (lane >> 4) * 8;

    // load Wh B-fragments into registers (once)
    unsigned bfr[8][8];
#pragma unroll
    for (int kk = 0; kk < 8; ++kk) {
#pragma unroll
        for (int nt2 = 0; nt2 < 2; ++nt2) {
            unsigned baddr = smem_u32(&WH[(kk * 16 + arow) * WH_STRIDE + n_base + nt2 * 16 + acol8]);
            ldsm_x4_t(bfr[kk][nt2 * 4 + 0], bfr[kk][nt2 * 4 + 1],
                      bfr[kk][nt2 * 4 + 2], bfr[kk][nt2 * 4 + 3], baddr);
        }
    }

    // cell ownership
    const int rr = lane >> 2;
    const int cb = (lane & 3) * 2;
    const int hp = warp * 8 + cb;
    const int xcol = xoff + warp * 32 + (cb >> 1) * 8;
    const int L0 = LS[rr];
    const int L1 = LS[rr + 8];
    const size_t bR0 = (size_t)(b0 + rr);
    const size_t bR1 = (size_t)(b0 + rr + 8);

    float c_reg[4] = {0.f, 0.f, 0.f, 0.f};

    for (int step = 0; step < Lmax; ++step) {
        const bool act0 = (step < L0);
        const bool act1 = (step < L1);
        const int idx0 = act0 ? (dir ? (L0 - 1 - step) : step) : step;
        const int idx1 = act1 ? (dir ? (L1 - 1 - step) : step) : step;

        uint4 xv0 = make_uint4(0u, 0u, 0u, 0u);
        uint4 xv1 = make_uint4(0u, 0u, 0u, 0u);
        if (act0) xv0 = *(const uint4*)(g_xpre16 + (bR0 * TT + idx0) * 1024 + xcol);
        if (act1) xv1 = *(const uint4*)(g_xpre16 + (bR1 * TT + idx1) * 1024 + xcol);

        // ---- phase1: gates in registers via mma ----
        float c[4][4];
#pragma unroll
        for (int i = 0; i < 4; ++i) {
#pragma unroll
            for (int j = 0; j < 4; ++j) c[i][j] = 0.f;
        }
        {
            const __half* hsrc = HS + (step & 1) * HS_BUFSZ;
#pragma unroll
            for (int kk = 0; kk < 8; ++kk) {
                unsigned a0, a1, a2, a3;
                unsigned aaddr = smem_u32(&hsrc[arow * HS_STRIDE + kk * 16 + acol8]);
                ldsm_x4(a0, a1, a2, a3, aaddr);
                mma16816(c[0], a0, a1, a2, a3, bfr[kk][0], bfr[kk][1]);
                mma16816(c[1], a0, a1, a2, a3, bfr[kk][2], bfr[kk][3]);
                mma16816(c[2], a0, a1, a2, a3, bfr[kk][4], bfr[kk][5]);
                mma16816(c[3], a0, a1, a2, a3, bfr[kk][6], bfr[kk][7]);
            }
        }

        // ---- phase2: cell update straight from accumulators ----
        __half* hdst = HS + ((step + 1) & 1) * HS_BUFSZ;

        {   // row rr
            float2 xi = __half22float2(*(__half2*)&xv0.x);
            float2 xj = __half22float2(*(__half2*)&xv0.y);
            float2 xf = __half22float2(*(__half2*)&xv0.z);
            float2 xo = __half22float2(*(__half2*)&xv0.w);
            float hv0 = 0.f, hv1 = 0.f;
            if (act0) {
                float gi0 = c[0][0] + xi.x, gi1 = c[0][1] + xi.y;
                float gj0 = c[1][0] + xj.x, gj1 = c[1][1] + xj.y;
                float gf0 = c[2][0] + xf.x + 1.f, gf1 = c[2][1] + xf.y + 1.f;
                float go0 = c[3][0] + xo.x, go1 = c[3][1] + xo.y;
                float cn0 = fmaf(c_reg[0], sig_apx(gf0), sig_apx(gi0) * tanh_apx(gj0));
                float cn1 = fmaf(c_reg[1], sig_apx(gf1), sig_apx(gi1) * tanh_apx(gj1));
                c_reg[0] = cn0; c_reg[1] = cn1;
                hv0 = tanh_apx(cn0) * sig_apx(go0);
                hv1 = tanh_apx(cn1) * sig_apx(go1);
            }
            __half2 hb = __floats2half2_rn(hv0, hv1);
            *(__half2*)&outh[(bR0 * TT + idx0) * 256 + ooff + hp] = hb;
            if (act0) *(__half2*)&hdst[rr * HS_STRIDE + hp] = hb;
        }
        {   // row rr+8
            float2 xi = __half22float2(*(__half2*)&xv1.x);
            float2 xj = __half22float2(*(__half2*)&xv1.y);
            float2 xf = __half22float2(*(__half2*)&xv1.z);
            float2 xo = __half22float2(*(__half2*)&xv1.w);
            float hv0 = 0.f, hv1 = 0.f;
            if (act1) {
                float gi0 = c[0][2] + xi.x, gi1 = c[0][3] + xi.y;
                float gj0 = c[1][2] + xj.x, gj1 = c[1][3] + xj.y;
                float gf0 = c[2][2] + xf.x + 1.f, gf1 = c[2][3] + xf.y + 1.f;
                float go0 = c[3][2] + xo.x, go1 = c[3][3] + xo.y;
                float cn0 = fmaf(c_reg[2], sig_apx(gf0), sig_apx(gi0) * tanh_apx(gj0));
                float cn1 = fmaf(c_reg[3], sig_apx(gf1), sig_apx(gi1) * tanh_apx(gj1));
                c_reg[2] = cn0; c_reg[3] = cn1;
                hv0 = tanh_apx(cn0) * sig_apx(go0);
                hv1 = tanh_apx(cn1) * sig_apx(go1);
            }
            __half2 hb = __floats2half2_rn(hv0, hv1);
            *(__half2*)&outh[(bR1 * TT + idx1) * 256 + ooff + hp] = hb;
            if (act1) *(__half2*)&hdst[(rr + 8) * HS_STRIDE + hp] = hb;
        }

        __syncthreads();
    }

    // barrier-free zero tail: positions [Lmax, TT) are zero for every row
    for (int step = Lmax; step < TT; ++step) {
        *(unsigned*)&outh[(bR0 * TT + step) * 256 + ooff + hp] = 0u;
        *(unsigned*)&outh[(bR1 * TT + step) * 256 + ooff + hp] = 0u;
    }
}

// ---------------------------------------------------------------------------
// Attention pooling (single pass, smem-resident tile): g_cur1h -> g_attb
// ---------------------------------------------------------------------------
#define ATT_TILE_BYTES (TT * 256 * 2)
#define ATT_WV_OFF  ATT_TILE_BYTES
#define ATT_E_OFF   (ATT_WV_OFF + 256 * 4)
#define ATT_RED_OFF (ATT_E_OFF + 176 * 4)
#define ATT_SMEM    (ATT_RED_OFF + 40 * 4)

__global__ __launch_bounds__(256) void att_kernel(
    const float* __restrict__ w_att, const float* __restrict__ b_att)
{
    extern __shared__ char asm_raw[];
    __half* tile = (__half*)(asm_raw);
    float*  wv   = (float*)(asm_raw + ATT_WV_OFF);
    float*  e_sm = (float*)(asm_raw + ATT_E_OFF);
    float*  red  = (float*)(asm_raw + ATT_RED_OFF);

    const int b = blockIdx.x;
    const int tid = threadIdx.x;
    wv[tid] = w_att[tid];

    const uint4* src = (const uint4*)&g_cur1h[(size_t)b * TT * 256];
    for (int i = tid; i < TT * 256 / 8; i += 256) {
        ((uint4*)tile)[i] = src[i];
    }
    __syncthreads();

    const int warp = tid >> 5;
    const int lane = tid & 31;

    for (int t = warp; t < TT; t += 8) {
        const __half* p = &tile[t * 256 + lane * 8];
        float s = 0.f;
#pragma unroll
        for (int j = 0; j < 4; ++j) {
            __half2 hh = *(const __half2*)(p + j * 2);
            float2 ff = __half22float2(hh);
            s += ff.x * wv[lane * 8 + j * 2] + ff.y * wv[lane * 8 + j * 2 + 1];
        }
#pragma unroll
        for (int off = 16; off > 0; off >>= 1) s += __shfl_down_sync(0xffffffffu, s, off);
        if (lane == 0) e_sm[t] = tanhf(s + b_att[0]);
    }
    __syncthreads();

    float m = -1e30f;
    for (int t = tid; t < TT; t += 256) m = fmaxf(m, e_sm[t]);
#pragma unroll
    for (int off = 16; off > 0; off >>= 1) m = fmaxf(m, __shfl_xor_sync(0xffffffffu, m, off));
    if (lane == 0) red[warp] = m;
    __syncthreads();
    if (tid == 0) {
        float mm = red[0];
        for (int w = 1; w < 8; ++w) mm = fmaxf(mm, red[w]);
        red[32] = mm;
    }
    __syncthreads();
    const float mx = red[32];

    float ssum = 0.f;
    for (int t = tid; t < TT; t += 256) {
        float p = expf(e_sm[t] - mx);
        e_sm[t] = p;
        ssum += p;
    }
#pragma unroll
    for (int off = 16; off > 0; off >>= 1) ssum += __shfl_xor_sync(0xffffffffu, ssum, off);
    if (lane == 0) red[warp] = ssum;
    __syncthreads();
    if (tid == 0) {
        float s2 = 0.f;
        for (int w = 0; w < 8; ++w) s2 += red[w];
        red[33] = s2;
    }
    __syncthreads();
    const float inv = 1.f / red[33];

    float acc = 0.f;
    const __half* base = &tile[tid];
    for (int t = 0; t < TT; ++t) {
        acc += e_sm[t] * __half2float(base[t * 256]);
    }
    g_attb[b * 256 + tid] = acc * inv;
}

// ---------------------------------------------------------------------------
// Classifier head: [g_sbuf, g_attb] -> out
// ---------------------------------------------------------------------------
__global__ __launch_bounds__(64) void head_kernel(
    const float* __restrict__ w1, const float* __restrict__ b1,
    const float* __restrict__ w2, const float* __restrict__ b2,
    float* __restrict__ out)
{
    const int b = blockIdx.x;
    const int tid = threadIdx.x;
    __shared__ float cat[272];
    __shared__ float h1[64];
    if (tid < 16) cat[tid] = g_sbuf[b * 16 + tid];
    for (int j = tid; j < 256; j += 64) cat[16 + j] = g_attb[b * 256 + j];
    __syncthreads();
    float a = b1[tid];
#pragma unroll 4
    for (int k = 0; k < 272; ++k) a += cat[k] * w1[k * 64 + tid];
    h1[tid] = fmaxf(a, 0.f);
    __syncthreads();
    if (tid < 32) {
        float a2 = b2[tid];
#pragma unroll
        for (int k = 0; k < 64; ++k) a2 += h1[k] * w2[k * 32 + tid];
        out[b * 32 + tid] = fmaxf(a2, 0.f);
    }
}

// ---------------------------------------------------------------------------
// Launch
// ---------------------------------------------------------------------------
extern "C" void kernel_launch(void* const* d_in, const int* in_sizes, int n_in,
                              void* d_out, int out_size)
{
    const float* x_static = (const float*)d_in[0];
    const float* x_dyn    = (const float*)d_in[1];
    const int*   seq      = (const int*)  d_in[2];
    const float* w_s0  = (const float*)d_in[3];
    const float* b_s0  = (const float*)d_in[4];
    const float* w_s1  = (const float*)d_in[5];
    const float* b_s1  = (const float*)d_in[6];
    const float* Wx_f0 = (const float*)d_in[7];
    const float* Wh_f0 = (const float*)d_in[8];
    const float* bb_f0 = (const float*)d_in[9];
    const float* Wx_b0 = (const float*)d_in[10];
    const float* Wh_b0 = (const float*)d_in[11];
    const float* bb_b0 = (const float*)d_in[12];
    const float* Wx_f1 = (const float*)d_in[13];
    const float* Wh_f1 = (const float*)d_in[14];
    const float* bb_f1 = (const float*)d_in[15];
    const float* Wx_b1 = (const float*)d_in[16];
    const float* Wh_b1 = (const float*)d_in[17];
    const float* bb_b1 = (const float*)d_in[18];
    const float* w_att = (const float*)d_in[19];
    const float* b_att = (const float*)d_in[20];
    const float* w_c1  = (const float*)d_in[21];
    const float* b_c1  = (const float*)d_in[22];
    const float* w_c2  = (const float*)d_in[23];
    const float* b_c2  = (const float*)d_in[24];
    float* out = (float*)d_out;

    cudaFuncSetAttribute(rec_mma, cudaFuncAttributeMaxDynamicSharedMemorySize, REC_SMEM);
    cudaFuncSetAttribute(att_kernel, cudaFuncAttributeMaxDynamicSharedMemorySize, ATT_SMEM);

    prep_kernel<<<256, 256>>>(Wh_f0, Wh_b0, Wh_f1, Wh_b1,
                              Wx_f0, Wx_b0, Wx_f1, Wx_b1,
                              bb_f0, bb_b0, bb_f1, bb_b1);
    static_kernel<<<(BATCH + 255) / 256, 256>>>(x_static, w_s0, b_s0, w_s1, b_s1);

    dim3 ggrid(8, MTOT / 128);
    xpre_gemm2<<<ggrid, 256>>>(x_dyn, FDYN, 0, seq);
    rec_mma<<<128, 512, REC_SMEM>>>(seq, 0);
    xpre_gemm2<<<ggrid, 256>>>(nullptr, 256, 1, seq);
    rec_mma<<<128, 512, REC_SMEM>>>(seq, 1);
    att_kernel<<<BATCH, 256, ATT_SMEM>>>(w_att, b_att);
    head_kernel<<<BATCH, 64>>>(w_c1, b_c1, w_c2, b_c2, out);
}